// round 1
// baseline (speedup 1.0000x reference)
#include <cuda_runtime.h>
#include <math.h>

#define Bz 8
#define Nn 1024
#define Dm 1024
#define Hh 16
#define HD 64
#define TT (Bz*Nn)       // 8192 tokens
#define MH 2048
#define NE 4

// ---------------- static device scratch (no allocation allowed) ----------------
__device__ float g_Tr[(size_t)TT*Dm];
__device__ float g_S [(size_t)TT*Dm];
__device__ float g_Sn[(size_t)TT*Dm];   // LN output; reused as xf after attention
__device__ float g_Q [(size_t)TT*Dm];
__device__ float g_K [(size_t)TT*Dm];
__device__ float g_V [(size_t)TT*Dm];
__device__ float g_Y [(size_t)TT*Dm];
__device__ float g_XS[(size_t)TT*Dm];
__device__ float g_H [(size_t)TT*MH];
__device__ float g_W [(size_t)TT*NE];   // routing weights (0 for unselected)
__device__ float g_Aux[2*NE];           // [0..3] sum gates, [4..7] sum selected

// ---------------- decomposition: 3 depthwise MAs, softmax-mixed ----------------
__global__ __launch_bounds__(256) void decomp_kernel(
    const float* __restrict__ x, const float* __restrict__ alpha,
    const float* __restrict__ w7, const float* __restrict__ w25,
    const float* __restrict__ w49, float* __restrict__ Tr, float* __restrict__ S)
{
    int n = blockIdx.x, b = blockIdx.y;
    float a0 = alpha[0], a1 = alpha[1], a2 = alpha[2];
    float mx = fmaxf(a0, fmaxf(a1, a2));
    float e0 = __expf(a0-mx), e1 = __expf(a1-mx), e2 = __expf(a2-mx);
    float inv = 1.f/(e0+e1+e2);
    float wt0 = e0*inv, wt1 = e1*inv, wt2 = e2*inv;

    for (int d = threadIdx.x; d < Dm; d += 256) {
        float t7 = 0.f, t25 = 0.f, t49 = 0.f;
        #pragma unroll
        for (int j = 0; j < 7; j++) {
            int p = n + j - 3; p = p < 0 ? -p : (p >= Nn ? 2*Nn-2-p : p);
            t7 += w7[d*7+j] * x[((size_t)(b*Nn+p))*Dm + d];
        }
        #pragma unroll
        for (int j = 0; j < 25; j++) {
            int p = n + j - 12; p = p < 0 ? -p : (p >= Nn ? 2*Nn-2-p : p);
            t25 += w25[d*25+j] * x[((size_t)(b*Nn+p))*Dm + d];
        }
        #pragma unroll
        for (int j = 0; j < 49; j++) {
            int p = n + j - 24; p = p < 0 ? -p : (p >= Nn ? 2*Nn-2-p : p);
            t49 += w49[d*49+j] * x[((size_t)(b*Nn+p))*Dm + d];
        }
        float tr = wt0*t7 + wt1*t25 + wt2*t49;
        size_t idx = ((size_t)(b*Nn+n))*Dm + d;
        Tr[idx] = tr;
        S[idx]  = x[idx] - tr;
    }
}

// ---------------- LayerNorm (one block per token) ----------------
__global__ __launch_bounds__(256) void ln_kernel(
    const float* __restrict__ in, float* __restrict__ out,
    const float* __restrict__ g, const float* __restrict__ b)
{
    __shared__ float red[256];
    int t = blockIdx.x;
    const float* row = in + (size_t)t*Dm;
    int tid = threadIdx.x;
    float s = 0.f;
    for (int d = tid; d < Dm; d += 256) s += row[d];
    red[tid] = s; __syncthreads();
    for (int o = 128; o; o >>= 1) { if (tid < o) red[tid] += red[tid+o]; __syncthreads(); }
    float m = red[0] * (1.f/Dm);
    __syncthreads();
    float v = 0.f;
    for (int d = tid; d < Dm; d += 256) { float dv = row[d]-m; v += dv*dv; }
    red[tid] = v; __syncthreads();
    for (int o = 128; o; o >>= 1) { if (tid < o) red[tid] += red[tid+o]; __syncthreads(); }
    float inv = rsqrtf(red[0]*(1.f/Dm) + 1e-5f);
    for (int d = tid; d < Dm; d += 256)
        out[(size_t)t*Dm + d] = (row[d]-m)*inv*g[d] + b[d];
}

// ---------------- SGEMM NT: C[t,o] = A[t,:]·W[o,:] + bias(+extras) ----------------
// MODE 0: C = dot+bias
// MODE 1: C = dot+bias+res
// MODE 2: C = gelu(dot+bias), block-skip if all 128 row-weights are 0
// MODE 3: C += w[t]*(dot+bias), block-skip; per-row skip if w==0
__device__ __forceinline__ float gelu_f(float v) {
    return 0.5f*v*(1.0f + erff(v*0.70710678118654752f));
}

template<int MODE>
__global__ __launch_bounds__(256) void gemm_nt(
    const float* __restrict__ A, const float* __restrict__ W,
    const float* __restrict__ bias, const float* __restrict__ res,
    const float* __restrict__ wrow,   // stride NE, already offset by expert
    float* __restrict__ C, int K, int O)
{
    __shared__ float As[8][128];
    __shared__ float Bs[8][128];
    int t0 = blockIdx.y*128, o0 = blockIdx.x*128;
    int tid = threadIdx.x;

    if (MODE == 2 || MODE == 3) {
        __shared__ int anyflag;
        if (tid == 0) anyflag = 0;
        __syncthreads();
        if (tid < 128 && wrow[(size_t)(t0+tid)*NE] != 0.f) anyflag = 1;
        __syncthreads();
        if (!anyflag) return;
    }

    float acc[8][8];
    #pragma unroll
    for (int i = 0; i < 8; i++)
        #pragma unroll
        for (int j = 0; j < 8; j++) acc[i][j] = 0.f;

    int lr = tid >> 1, lk4 = (tid & 1)*4;
    int my = (tid >> 4)*8, mxc = (tid & 15)*8;

    for (int kt = 0; kt < K; kt += 8) {
        float4 av = *(const float4*)&A[(size_t)(t0+lr)*K + kt + lk4];
        float4 bv = *(const float4*)&W[(size_t)(o0+lr)*K + kt + lk4];
        As[lk4+0][lr]=av.x; As[lk4+1][lr]=av.y; As[lk4+2][lr]=av.z; As[lk4+3][lr]=av.w;
        Bs[lk4+0][lr]=bv.x; Bs[lk4+1][lr]=bv.y; Bs[lk4+2][lr]=bv.z; Bs[lk4+3][lr]=bv.w;
        __syncthreads();
        #pragma unroll
        for (int k = 0; k < 8; k++) {
            float4 ra0 = *(const float4*)&As[k][my];
            float4 ra1 = *(const float4*)&As[k][my+4];
            float4 rb0 = *(const float4*)&Bs[k][mxc];
            float4 rb1 = *(const float4*)&Bs[k][mxc+4];
            float ra[8] = {ra0.x,ra0.y,ra0.z,ra0.w,ra1.x,ra1.y,ra1.z,ra1.w};
            float rb[8] = {rb0.x,rb0.y,rb0.z,rb0.w,rb1.x,rb1.y,rb1.z,rb1.w};
            #pragma unroll
            for (int i = 0; i < 8; i++)
                #pragma unroll
                for (int j = 0; j < 8; j++) acc[i][j] += ra[i]*rb[j];
        }
        __syncthreads();
    }

    #pragma unroll
    for (int i = 0; i < 8; i++) {
        int row = t0 + my + i;
        float w = 0.f;
        if (MODE == 3) { w = wrow[(size_t)row*NE]; if (w == 0.f) continue; }
        #pragma unroll
        for (int j = 0; j < 8; j++) {
            int col = o0 + mxc + j;
            float val = acc[i][j] + bias[col];
            size_t idx = (size_t)row*O + col;
            if (MODE == 0) C[idx] = val;
            else if (MODE == 1) C[idx] = val + res[idx];
            else if (MODE == 2) C[idx] = gelu_f(val);
            else C[idx] += w*val;
        }
    }
}

// ---------------- ALiBi attention: block = (b,h, 16 queries) ----------------
// dynamic smem: Qs[16*64] | KV[64*68] | P[16*1024]
#define ATT_SH_FLOATS (16*64 + 64*68 + 16*1024)

__global__ __launch_bounds__(256) void attn_kernel(
    const float* __restrict__ Q, const float* __restrict__ K,
    const float* __restrict__ V, float* __restrict__ Y)
{
    extern __shared__ float sh[];
    float* Qs = sh;                 // [r*64 + d]
    float* KV = sh + 16*64;         // K phase: [d*68+j]; V phase: [j*68+d]
    float* Ps = sh + 16*64 + 64*68; // [r*1024 + j]

    int bh = blockIdx.y;
    int b = bh >> 4, h = bh & 15;
    int q0 = blockIdx.x * 16;
    int tid = threadIdx.x;
    float slope = exp2f(-0.5f * (float)(h+1));

    for (int i = tid; i < 16*64; i += 256) {
        int r = i >> 6, d = i & 63;
        Qs[i] = Q[((size_t)(b*Nn + q0 + r))*Dm + h*64 + d];
    }
    __syncthreads();

    for (int kt = 0; kt < Nn; kt += 64) {
        for (int i = tid; i < 64*64; i += 256) {
            int j = i >> 6, d = i & 63;
            KV[d*68 + j] = K[((size_t)(b*Nn + kt + j))*Dm + h*64 + d];
        }
        __syncthreads();
        #pragma unroll
        for (int c = 0; c < 4; c++) {
            int e = tid + c*256;
            int r = e >> 6, j = e & 63;
            float s = 0.f;
            #pragma unroll 16
            for (int d = 0; d < 64; d++) s += Qs[r*64+d] * KV[d*68+j];
            int jg = kt + j, qg = q0 + r;
            float dist = (jg > qg) ? (float)(jg - qg) : 0.f;
            Ps[r*1024 + jg] = s*0.125f - slope*dist;
        }
        __syncthreads();
    }

    // softmax: warp w handles rows w, w+8
    int warp = tid >> 5, lane = tid & 31;
    for (int r = warp; r < 16; r += 8) {
        float mxv = -1e30f;
        for (int j = lane; j < Nn; j += 32) mxv = fmaxf(mxv, Ps[r*1024+j]);
        #pragma unroll
        for (int o = 16; o; o >>= 1) mxv = fmaxf(mxv, __shfl_xor_sync(0xffffffff, mxv, o));
        float sum = 0.f;
        for (int j = lane; j < Nn; j += 32) {
            float p = __expf(Ps[r*1024+j] - mxv);
            Ps[r*1024+j] = p; sum += p;
        }
        #pragma unroll
        for (int o = 16; o; o >>= 1) sum += __shfl_xor_sync(0xffffffff, sum, o);
        float invs = 1.f / sum;
        for (int j = lane; j < Nn; j += 32) Ps[r*1024+j] *= invs;
    }
    __syncthreads();

    // output: thread owns (row r, 4 dims d0..d0+3)
    int r = tid >> 4, d0 = (tid & 15) << 2;
    float4 acc = make_float4(0.f, 0.f, 0.f, 0.f);
    for (int kt = 0; kt < Nn; kt += 64) {
        for (int i = tid; i < 64*64; i += 256) {
            int j = i >> 6, d = i & 63;
            KV[j*68 + d] = V[((size_t)(b*Nn + kt + j))*Dm + h*64 + d];
        }
        __syncthreads();
        #pragma unroll 8
        for (int j = 0; j < 64; j++) {
            float p = Ps[r*1024 + kt + j];
            float4 v = *(const float4*)&KV[j*68 + d0];
            acc.x += p*v.x; acc.y += p*v.y; acc.z += p*v.z; acc.w += p*v.w;
        }
        __syncthreads();
    }
    float* yout = &Y[((size_t)(b*Nn + q0 + r))*Dm + h*64 + d0];
    yout[0]=acc.x; yout[1]=acc.y; yout[2]=acc.z; yout[3]=acc.w;
}

// ---------------- router: softmax over 4 experts + top-2 + aux sums ----------------
__global__ __launch_bounds__(128) void router_kernel(
    const float* __restrict__ xf, const float* __restrict__ rw,
    float* __restrict__ Wout, float* __restrict__ Aux)
{
    int t = blockIdx.x;
    int warp = threadIdx.x >> 5, lane = threadIdx.x & 31;
    __shared__ float sg[NE];
    const float* xrow = xf + (size_t)t*Dm;
    float s = 0.f;
    for (int i = lane; i < Dm; i += 32) s += xrow[i]*rw[(size_t)warp*Dm + i];
    #pragma unroll
    for (int o = 16; o; o >>= 1) s += __shfl_xor_sync(0xffffffff, s, o);
    if (lane == 0) sg[warp] = s;
    __syncthreads();
    if (threadIdx.x == 0) {
        float m = fmaxf(fmaxf(sg[0],sg[1]), fmaxf(sg[2],sg[3]));
        float e[NE], sum = 0.f;
        #pragma unroll
        for (int i = 0; i < NE; i++) { e[i] = __expf(sg[i]-m); sum += e[i]; }
        float gate[NE];
        #pragma unroll
        for (int i = 0; i < NE; i++) gate[i] = e[i]/sum;
        int i0 = 0;
        #pragma unroll
        for (int i = 1; i < NE; i++) if (gate[i] > gate[i0]) i0 = i;
        int i1 = -1;
        #pragma unroll
        for (int i = 0; i < NE; i++) if (i != i0 && (i1 < 0 || gate[i] > gate[i1])) i1 = i;
        float s2 = fmaxf(gate[i0] + gate[i1], 1e-9f);
        #pragma unroll
        for (int i = 0; i < NE; i++) Wout[(size_t)t*NE + i] = 0.f;
        Wout[(size_t)t*NE + i0] = gate[i0]/s2;
        Wout[(size_t)t*NE + i1] = gate[i1]/s2;
        #pragma unroll
        for (int i = 0; i < NE; i++) atomicAdd(&Aux[i], gate[i]);
        atomicAdd(&Aux[NE + i0], 1.f);
        atomicAdd(&Aux[NE + i1], 1.f);
    }
}

// ---------------- final: out = XS + dwconv5(Tr) + tb; aux ----------------
__global__ __launch_bounds__(256) void final_kernel(
    const float* __restrict__ tw, const float* __restrict__ tb,
    const float* __restrict__ Tr, const float* __restrict__ XS,
    float* __restrict__ out)
{
    int n = blockIdx.x, b = blockIdx.y;
    for (int d = threadIdx.x; d < Dm; d += 256) {
        float acc = tb[d];
        #pragma unroll
        for (int j = 0; j < 5; j++) {
            int p = n + j - 2;
            if (p >= 0 && p < Nn) acc += tw[d*5+j] * Tr[((size_t)(b*Nn+p))*Dm + d];
        }
        size_t idx = ((size_t)(b*Nn+n))*Dm + d;
        out[idx] = XS[idx] + acc;
    }
}

__global__ void zero_aux_kernel(float* Aux) {
    if (threadIdx.x < 2*NE) Aux[threadIdx.x] = 0.f;
}

__global__ void aux_write_kernel(const float* Aux, float* out, int out_size) {
    if (out_size > TT*Dm) {
        float a = 0.f;
        #pragma unroll
        for (int e = 0; e < NE; e++)
            a += (Aux[e]/(float)TT) * (Aux[NE+e]/(float)TT);
        out[TT*Dm] = (float)NE * a;
    }
}

// ---------------- launcher ----------------
extern "C" void kernel_launch(void* const* d_in, const int* in_sizes, int n_in,
                              void* d_out, int out_size)
{
    const float* x    = (const float*)d_in[0];
    const float* qw   = (const float*)d_in[1];
    const float* qb   = (const float*)d_in[2];
    const float* kw   = (const float*)d_in[3];
    const float* kb   = (const float*)d_in[4];
    const float* vw   = (const float*)d_in[5];
    const float* vb   = (const float*)d_in[6];
    const float* ow   = (const float*)d_in[7];
    const float* ob   = (const float*)d_in[8];
    const float* n1g  = (const float*)d_in[9];
    const float* n1b  = (const float*)d_in[10];
    const float* n2g  = (const float*)d_in[11];
    const float* n2b  = (const float*)d_in[12];
    const float* alpha= (const float*)d_in[13];
    const float* dw7  = (const float*)d_in[14];
    const float* dw25 = (const float*)d_in[15];
    const float* dw49 = (const float*)d_in[16];
    const float* rw   = (const float*)d_in[17];
    const float* ew1  = (const float*)d_in[18];
    const float* eb1  = (const float*)d_in[19];
    const float* ew2  = (const float*)d_in[20];
    const float* eb2  = (const float*)d_in[21];
    const float* tw   = (const float*)d_in[22];
    const float* tb   = (const float*)d_in[23];
    float* out = (float*)d_out;

    float *Tr,*S,*Sn,*Qb,*Kb,*Vb,*Yb,*XS,*Hb,*Wt,*Aux;
    cudaGetSymbolAddress((void**)&Tr,  g_Tr);
    cudaGetSymbolAddress((void**)&S,   g_S);
    cudaGetSymbolAddress((void**)&Sn,  g_Sn);
    cudaGetSymbolAddress((void**)&Qb,  g_Q);
    cudaGetSymbolAddress((void**)&Kb,  g_K);
    cudaGetSymbolAddress((void**)&Vb,  g_V);
    cudaGetSymbolAddress((void**)&Yb,  g_Y);
    cudaGetSymbolAddress((void**)&XS,  g_XS);
    cudaGetSymbolAddress((void**)&Hb,  g_H);
    cudaGetSymbolAddress((void**)&Wt,  g_W);
    cudaGetSymbolAddress((void**)&Aux, g_Aux);

    const int ATT_SH_BYTES = ATT_SH_FLOATS * 4;
    cudaFuncSetAttribute(attn_kernel, cudaFuncAttributeMaxDynamicSharedMemorySize, ATT_SH_BYTES);

    zero_aux_kernel<<<1, 32>>>(Aux);
    decomp_kernel<<<dim3(Nn, Bz), 256>>>(x, alpha, dw7, dw25, dw49, Tr, S);
    ln_kernel<<<TT, 256>>>(S, Sn, n1g, n1b);

    gemm_nt<0><<<dim3(Dm/128, TT/128), 256>>>(Sn, qw, qb, nullptr, nullptr, Qb, Dm, Dm);
    gemm_nt<0><<<dim3(Dm/128, TT/128), 256>>>(Sn, kw, kb, nullptr, nullptr, Kb, Dm, Dm);
    gemm_nt<0><<<dim3(Dm/128, TT/128), 256>>>(Sn, vw, vb, nullptr, nullptr, Vb, Dm, Dm);

    attn_kernel<<<dim3(Nn/16, Bz*Hh), 256, ATT_SH_BYTES>>>(Qb, Kb, Vb, Yb);

    gemm_nt<1><<<dim3(Dm/128, TT/128), 256>>>(Yb, ow, ob, S, nullptr, XS, Dm, Dm);
    ln_kernel<<<TT, 256>>>(XS, Sn, n2g, n2b);
    router_kernel<<<TT, 128>>>(Sn, rw, Wt, Aux);

    for (int e = 0; e < NE; e++) {
        gemm_nt<2><<<dim3(MH/128, TT/128), 256>>>(
            Sn, ew1 + (size_t)e*MH*Dm, eb1 + (size_t)e*MH, nullptr, Wt + e, Hb, Dm, MH);
        gemm_nt<3><<<dim3(Dm/128, TT/128), 256>>>(
            Hb, ew2 + (size_t)e*Dm*MH, eb2 + (size_t)e*Dm, nullptr, Wt + e, XS, MH, Dm);
    }

    final_kernel<<<dim3(Nn, Bz), 256>>>(tw, tb, Tr, XS, out);
    aux_write_kernel<<<1, 1>>>(Aux, out, out_size);
}

// round 2
// speedup vs baseline: 1.4099x; 1.4099x over previous
#include <cuda_runtime.h>
#include <math.h>

#define Bz 8
#define Nn 1024
#define Dm 1024
#define Hh 16
#define HD 64
#define TT (Bz*Nn)       // 8192 tokens
#define MH 2048
#define NE 4

// ---------------- static device scratch (no allocation allowed) ----------------
__device__ float g_Tr[(size_t)TT*Dm];
__device__ float g_S [(size_t)TT*Dm];
__device__ float g_Sn[(size_t)TT*Dm];   // LN output; reused as xf after attention
__device__ float g_Q [(size_t)TT*Dm];
__device__ float g_K [(size_t)TT*Dm];
__device__ float g_V [(size_t)TT*Dm];
__device__ float g_Y [(size_t)TT*Dm];
__device__ float g_XS[(size_t)TT*Dm];
__device__ float g_H [(size_t)TT*MH];
__device__ float g_W [(size_t)TT*NE];       // dense routing weights (0 for unselected)
__device__ float g_Xe[(size_t)NE*TT*Dm];    // per-expert gathered token rows
__device__ int   g_Eidx[NE*TT];             // per-expert token index list
__device__ float g_Ewt [NE*TT];             // per-expert token weight list
__device__ int   g_Cnt[NE];                 // per-expert token counts
__device__ float g_Aux[2*NE];               // [0..3] sum gates, [4..7] sum selected

// ---------------- decomposition: 3 depthwise MAs, softmax-mixed ----------------
__global__ __launch_bounds__(256) void decomp_kernel(
    const float* __restrict__ x, const float* __restrict__ alpha,
    const float* __restrict__ w7, const float* __restrict__ w25,
    const float* __restrict__ w49, float* __restrict__ Tr, float* __restrict__ S)
{
    int n = blockIdx.x, b = blockIdx.y;
    float a0 = alpha[0], a1 = alpha[1], a2 = alpha[2];
    float mx = fmaxf(a0, fmaxf(a1, a2));
    float e0 = __expf(a0-mx), e1 = __expf(a1-mx), e2 = __expf(a2-mx);
    float inv = 1.f/(e0+e1+e2);
    float wt0 = e0*inv, wt1 = e1*inv, wt2 = e2*inv;

    for (int d = threadIdx.x; d < Dm; d += 256) {
        float t7 = 0.f, t25 = 0.f, t49 = 0.f;
        #pragma unroll
        for (int j = 0; j < 7; j++) {
            int p = n + j - 3; p = p < 0 ? -p : (p >= Nn ? 2*Nn-2-p : p);
            t7 += w7[d*7+j] * x[((size_t)(b*Nn+p))*Dm + d];
        }
        #pragma unroll
        for (int j = 0; j < 25; j++) {
            int p = n + j - 12; p = p < 0 ? -p : (p >= Nn ? 2*Nn-2-p : p);
            t25 += w25[d*25+j] * x[((size_t)(b*Nn+p))*Dm + d];
        }
        #pragma unroll
        for (int j = 0; j < 49; j++) {
            int p = n + j - 24; p = p < 0 ? -p : (p >= Nn ? 2*Nn-2-p : p);
            t49 += w49[d*49+j] * x[((size_t)(b*Nn+p))*Dm + d];
        }
        float tr = wt0*t7 + wt1*t25 + wt2*t49;
        size_t idx = ((size_t)(b*Nn+n))*Dm + d;
        Tr[idx] = tr;
        S[idx]  = x[idx] - tr;
    }
}

// ---------------- LayerNorm (one block per token) ----------------
__global__ __launch_bounds__(256) void ln_kernel(
    const float* __restrict__ in, float* __restrict__ out,
    const float* __restrict__ g, const float* __restrict__ b)
{
    __shared__ float red[256];
    int t = blockIdx.x;
    const float* row = in + (size_t)t*Dm;
    int tid = threadIdx.x;
    float s = 0.f;
    for (int d = tid; d < Dm; d += 256) s += row[d];
    red[tid] = s; __syncthreads();
    for (int o = 128; o; o >>= 1) { if (tid < o) red[tid] += red[tid+o]; __syncthreads(); }
    float m = red[0] * (1.f/Dm);
    __syncthreads();
    float v = 0.f;
    for (int d = tid; d < Dm; d += 256) { float dv = row[d]-m; v += dv*dv; }
    red[tid] = v; __syncthreads();
    for (int o = 128; o; o >>= 1) { if (tid < o) red[tid] += red[tid+o]; __syncthreads(); }
    float inv = rsqrtf(red[0]*(1.f/Dm) + 1e-5f);
    for (int d = tid; d < Dm; d += 256)
        out[(size_t)t*Dm + d] = (row[d]-m)*inv*g[d] + b[d];
}

// ---------------- SGEMM NT: C[t,o] = A[t,:]·W[o,:] + bias(+extras) ----------------
// MODE 0: C = dot+bias
// MODE 1: C = dot+bias+res
// MODE 2: C = gelu(dot+bias), compact rows; skip blocks/rows >= *cnt
// MODE 3: XS[idx[r]] += w[r]*(dot+bias), compact rows; skip >= *cnt
__device__ __forceinline__ float gelu_f(float v) {
    return 0.5f*v*(1.0f + erff(v*0.70710678118654752f));
}

template<int MODE>
__global__ __launch_bounds__(256, 2) void gemm_nt(
    const float* __restrict__ A, const float* __restrict__ W,
    const float* __restrict__ bias, const float* __restrict__ res,
    const int* __restrict__ cnt, const int* __restrict__ ridx,
    const float* __restrict__ wvec,
    float* __restrict__ C, int K, int O)
{
    __shared__ float As[16][128];
    __shared__ float Bs[16][128];
    int t0 = blockIdx.y*128, o0 = blockIdx.x*128;
    int tid = threadIdx.x;

    int cN = 1 << 30;
    if (MODE == 2 || MODE == 3) {
        cN = *cnt;
        if (t0 >= cN) return;
    }

    float acc[8][8];
    #pragma unroll
    for (int i = 0; i < 8; i++)
        #pragma unroll
        for (int j = 0; j < 8; j++) acc[i][j] = 0.f;

    int lr = tid >> 1, lc = (tid & 1)*8;
    int my = (tid >> 4)*8, mxc = (tid & 15)*8;

    const float* Ap = A + (size_t)(t0+lr)*K + lc;
    const float* Bp = W + (size_t)(o0+lr)*K + lc;

    float4 a0 = *(const float4*)(Ap);
    float4 a1 = *(const float4*)(Ap+4);
    float4 b0 = *(const float4*)(Bp);
    float4 b1 = *(const float4*)(Bp+4);

    for (int kt = 0; kt < K; kt += 16) {
        As[lc+0][lr]=a0.x; As[lc+1][lr]=a0.y; As[lc+2][lr]=a0.z; As[lc+3][lr]=a0.w;
        As[lc+4][lr]=a1.x; As[lc+5][lr]=a1.y; As[lc+6][lr]=a1.z; As[lc+7][lr]=a1.w;
        Bs[lc+0][lr]=b0.x; Bs[lc+1][lr]=b0.y; Bs[lc+2][lr]=b0.z; Bs[lc+3][lr]=b0.w;
        Bs[lc+4][lr]=b1.x; Bs[lc+5][lr]=b1.y; Bs[lc+6][lr]=b1.z; Bs[lc+7][lr]=b1.w;
        __syncthreads();
        if (kt + 16 < K) {
            a0 = *(const float4*)(Ap + kt + 16);
            a1 = *(const float4*)(Ap + kt + 20);
            b0 = *(const float4*)(Bp + kt + 16);
            b1 = *(const float4*)(Bp + kt + 20);
        }
        #pragma unroll
        for (int k = 0; k < 16; k++) {
            float4 ra0 = *(const float4*)&As[k][my];
            float4 ra1 = *(const float4*)&As[k][my+4];
            float4 rb0 = *(const float4*)&Bs[k][mxc];
            float4 rb1 = *(const float4*)&Bs[k][mxc+4];
            float ra[8] = {ra0.x,ra0.y,ra0.z,ra0.w,ra1.x,ra1.y,ra1.z,ra1.w};
            float rb[8] = {rb0.x,rb0.y,rb0.z,rb0.w,rb1.x,rb1.y,rb1.z,rb1.w};
            #pragma unroll
            for (int i = 0; i < 8; i++)
                #pragma unroll
                for (int j = 0; j < 8; j++) acc[i][j] += ra[i]*rb[j];
        }
        __syncthreads();
    }

    #pragma unroll
    for (int i = 0; i < 8; i++) {
        int row = t0 + my + i;
        if ((MODE == 2 || MODE == 3) && row >= cN) continue;
        float w = 0.f; int tgt = row;
        if (MODE == 3) { w = wvec[row]; tgt = ridx[row]; }
        #pragma unroll
        for (int j = 0; j < 8; j++) {
            int col = o0 + mxc + j;
            float val = acc[i][j] + bias[col];
            if (MODE == 0) C[(size_t)row*O + col] = val;
            else if (MODE == 1) C[(size_t)row*O + col] = val + res[(size_t)row*O + col];
            else if (MODE == 2) C[(size_t)row*O + col] = gelu_f(val);
            else C[(size_t)tgt*O + col] += w*val;
        }
    }
}

// ---------------- ALiBi attention: block = (b,h, 16 queries) ----------------
#define ATT_SH_FLOATS (16*64 + 64*68 + 16*1024)

__global__ __launch_bounds__(256) void attn_kernel(
    const float* __restrict__ Q, const float* __restrict__ K,
    const float* __restrict__ V, float* __restrict__ Y)
{
    extern __shared__ float sh[];
    float* Qs = sh;                 // [r*64 + d]
    float* KV = sh + 16*64;         // K phase: [d*68+j]; V phase: [j*68+d]
    float* Ps = sh + 16*64 + 64*68; // [r*1024 + j]

    int bh = blockIdx.y;
    int b = bh >> 4, h = bh & 15;
    int q0 = blockIdx.x * 16;
    int tid = threadIdx.x;
    float slope = exp2f(-0.5f * (float)(h+1));

    for (int i = tid; i < 16*64; i += 256) {
        int r = i >> 6, d = i & 63;
        Qs[i] = Q[((size_t)(b*Nn + q0 + r))*Dm + h*64 + d];
    }
    __syncthreads();

    for (int kt = 0; kt < Nn; kt += 64) {
        for (int i = tid; i < 64*64; i += 256) {
            int j = i >> 6, d = i & 63;
            KV[d*68 + j] = K[((size_t)(b*Nn + kt + j))*Dm + h*64 + d];
        }
        __syncthreads();
        #pragma unroll
        for (int c = 0; c < 4; c++) {
            int e = tid + c*256;
            int r = e >> 6, j = e & 63;
            float s = 0.f;
            #pragma unroll 16
            for (int d = 0; d < 64; d++) s += Qs[r*64+d] * KV[d*68+j];
            int jg = kt + j, qg = q0 + r;
            float dist = (jg > qg) ? (float)(jg - qg) : 0.f;
            Ps[r*1024 + jg] = s*0.125f - slope*dist;
        }
        __syncthreads();
    }

    int warp = tid >> 5, lane = tid & 31;
    for (int r = warp; r < 16; r += 8) {
        float mxv = -1e30f;
        for (int j = lane; j < Nn; j += 32) mxv = fmaxf(mxv, Ps[r*1024+j]);
        #pragma unroll
        for (int o = 16; o; o >>= 1) mxv = fmaxf(mxv, __shfl_xor_sync(0xffffffff, mxv, o));
        float sum = 0.f;
        for (int j = lane; j < Nn; j += 32) {
            float p = __expf(Ps[r*1024+j] - mxv);
            Ps[r*1024+j] = p; sum += p;
        }
        #pragma unroll
        for (int o = 16; o; o >>= 1) sum += __shfl_xor_sync(0xffffffff, sum, o);
        float invs = 1.f / sum;
        for (int j = lane; j < Nn; j += 32) Ps[r*1024+j] *= invs;
    }
    __syncthreads();

    int r = tid >> 4, d0 = (tid & 15) << 2;
    float4 acc = make_float4(0.f, 0.f, 0.f, 0.f);
    for (int kt = 0; kt < Nn; kt += 64) {
        for (int i = tid; i < 64*64; i += 256) {
            int j = i >> 6, d = i & 63;
            KV[j*68 + d] = V[((size_t)(b*Nn + kt + j))*Dm + h*64 + d];
        }
        __syncthreads();
        #pragma unroll 8
        for (int j = 0; j < 64; j++) {
            float p = Ps[r*1024 + kt + j];
            float4 v = *(const float4*)&KV[j*68 + d0];
            acc.x += p*v.x; acc.y += p*v.y; acc.z += p*v.z; acc.w += p*v.w;
        }
        __syncthreads();
    }
    float* yout = &Y[((size_t)(b*Nn + q0 + r))*Dm + h*64 + d0];
    yout[0]=acc.x; yout[1]=acc.y; yout[2]=acc.z; yout[3]=acc.w;
}

// ---------------- router: softmax over 4 experts + top-2 + aux sums ----------------
__global__ __launch_bounds__(128) void router_kernel(
    const float* __restrict__ xf, const float* __restrict__ rw,
    float* __restrict__ Wout, float* __restrict__ Aux)
{
    int t = blockIdx.x;
    int warp = threadIdx.x >> 5, lane = threadIdx.x & 31;
    __shared__ float sg[NE];
    const float* xrow = xf + (size_t)t*Dm;
    float s = 0.f;
    for (int i = lane; i < Dm; i += 32) s += xrow[i]*rw[(size_t)warp*Dm + i];
    #pragma unroll
    for (int o = 16; o; o >>= 1) s += __shfl_xor_sync(0xffffffff, s, o);
    if (lane == 0) sg[warp] = s;
    __syncthreads();
    if (threadIdx.x == 0) {
        float m = fmaxf(fmaxf(sg[0],sg[1]), fmaxf(sg[2],sg[3]));
        float e[NE], sum = 0.f;
        #pragma unroll
        for (int i = 0; i < NE; i++) { e[i] = __expf(sg[i]-m); sum += e[i]; }
        float gate[NE];
        #pragma unroll
        for (int i = 0; i < NE; i++) gate[i] = e[i]/sum;
        int i0 = 0;
        #pragma unroll
        for (int i = 1; i < NE; i++) if (gate[i] > gate[i0]) i0 = i;
        int i1 = -1;
        #pragma unroll
        for (int i = 0; i < NE; i++) if (i != i0 && (i1 < 0 || gate[i] > gate[i1])) i1 = i;
        float s2 = fmaxf(gate[i0] + gate[i1], 1e-9f);
        #pragma unroll
        for (int i = 0; i < NE; i++) Wout[(size_t)t*NE + i] = 0.f;
        Wout[(size_t)t*NE + i0] = gate[i0]/s2;
        Wout[(size_t)t*NE + i1] = gate[i1]/s2;
        #pragma unroll
        for (int i = 0; i < NE; i++) atomicAdd(&Aux[i], gate[i]);
        atomicAdd(&Aux[NE + i0], 1.f);
        atomicAdd(&Aux[NE + i1], 1.f);
    }
}

// ---------------- MoE token assignment: compact per-expert lists ----------------
__global__ __launch_bounds__(256) void assign_kernel(
    const float* __restrict__ Wt, int* __restrict__ cnt,
    int* __restrict__ eidx, float* __restrict__ ewt)
{
    int t = blockIdx.x*256 + threadIdx.x;
    if (t >= TT) return;
    #pragma unroll
    for (int e = 0; e < NE; e++) {
        float w = Wt[(size_t)t*NE + e];
        if (w != 0.f) {
            int pos = atomicAdd(&cnt[e], 1);
            eidx[e*TT + pos] = t;
            ewt [e*TT + pos] = w;
        }
    }
}

// gather compact rows (zero-pad up to 128-row boundary)
__global__ __launch_bounds__(256) void gather_kernel(
    const float* __restrict__ xf, const int* __restrict__ cnt,
    const int* __restrict__ eidx, float* __restrict__ Xe)
{
    int e = blockIdx.y, row = blockIdx.x;
    int c = cnt[e];
    float4* dst = (float4*)(Xe + ((size_t)e*TT + row)*Dm);
    if (row < c) {
        const float4* src = (const float4*)(xf + (size_t)eidx[e*TT + row]*Dm);
        dst[threadIdx.x] = src[threadIdx.x];
    } else if (row < ((c + 127) & ~127)) {
        dst[threadIdx.x] = make_float4(0.f,0.f,0.f,0.f);
    }
}

// ---------------- final: out = XS + dwconv5(Tr) + tb; aux ----------------
__global__ __launch_bounds__(256) void final_kernel(
    const float* __restrict__ tw, const float* __restrict__ tb,
    const float* __restrict__ Tr, const float* __restrict__ XS,
    float* __restrict__ out)
{
    int n = blockIdx.x, b = blockIdx.y;
    for (int d = threadIdx.x; d < Dm; d += 256) {
        float acc = tb[d];
        #pragma unroll
        for (int j = 0; j < 5; j++) {
            int p = n + j - 2;
            if (p >= 0 && p < Nn) acc += tw[d*5+j] * Tr[((size_t)(b*Nn+p))*Dm + d];
        }
        size_t idx = ((size_t)(b*Nn+n))*Dm + d;
        out[idx] = XS[idx] + acc;
    }
}

__global__ void zero_aux_kernel(float* Aux, int* cnt) {
    if (threadIdx.x < 2*NE) Aux[threadIdx.x] = 0.f;
    if (threadIdx.x < NE) cnt[threadIdx.x] = 0;
}

__global__ void aux_write_kernel(const float* Aux, float* out, int out_size) {
    if (out_size > TT*Dm) {
        float a = 0.f;
        #pragma unroll
        for (int e = 0; e < NE; e++)
            a += (Aux[e]/(float)TT) * (Aux[NE+e]/(float)TT);
        out[TT*Dm] = (float)NE * a;
    }
}

// ---------------- launcher ----------------
extern "C" void kernel_launch(void* const* d_in, const int* in_sizes, int n_in,
                              void* d_out, int out_size)
{
    const float* x    = (const float*)d_in[0];
    const float* qw   = (const float*)d_in[1];
    const float* qb   = (const float*)d_in[2];
    const float* kw   = (const float*)d_in[3];
    const float* kb   = (const float*)d_in[4];
    const float* vw   = (const float*)d_in[5];
    const float* vb   = (const float*)d_in[6];
    const float* ow   = (const float*)d_in[7];
    const float* ob   = (const float*)d_in[8];
    const float* n1g  = (const float*)d_in[9];
    const float* n1b  = (const float*)d_in[10];
    const float* n2g  = (const float*)d_in[11];
    const float* n2b  = (const float*)d_in[12];
    const float* alpha= (const float*)d_in[13];
    const float* dw7  = (const float*)d_in[14];
    const float* dw25 = (const float*)d_in[15];
    const float* dw49 = (const float*)d_in[16];
    const float* rw   = (const float*)d_in[17];
    const float* ew1  = (const float*)d_in[18];
    const float* eb1  = (const float*)d_in[19];
    const float* ew2  = (const float*)d_in[20];
    const float* eb2  = (const float*)d_in[21];
    const float* tw   = (const float*)d_in[22];
    const float* tb   = (const float*)d_in[23];
    float* out = (float*)d_out;

    float *Tr,*S,*Sn,*Qb,*Kb,*Vb,*Yb,*XS,*Hb,*Wt,*Xe,*Ewt,*Aux;
    int *Eidx,*Cnt;
    cudaGetSymbolAddress((void**)&Tr,  g_Tr);
    cudaGetSymbolAddress((void**)&S,   g_S);
    cudaGetSymbolAddress((void**)&Sn,  g_Sn);
    cudaGetSymbolAddress((void**)&Qb,  g_Q);
    cudaGetSymbolAddress((void**)&Kb,  g_K);
    cudaGetSymbolAddress((void**)&Vb,  g_V);
    cudaGetSymbolAddress((void**)&Yb,  g_Y);
    cudaGetSymbolAddress((void**)&XS,  g_XS);
    cudaGetSymbolAddress((void**)&Hb,  g_H);
    cudaGetSymbolAddress((void**)&Wt,  g_W);
    cudaGetSymbolAddress((void**)&Xe,  g_Xe);
    cudaGetSymbolAddress((void**)&Ewt, g_Ewt);
    cudaGetSymbolAddress((void**)&Aux, g_Aux);
    cudaGetSymbolAddress((void**)&Eidx,g_Eidx);
    cudaGetSymbolAddress((void**)&Cnt, g_Cnt);

    const int ATT_SH_BYTES = ATT_SH_FLOATS * 4;
    cudaFuncSetAttribute(attn_kernel, cudaFuncAttributeMaxDynamicSharedMemorySize, ATT_SH_BYTES);

    zero_aux_kernel<<<1, 32>>>(Aux, Cnt);
    decomp_kernel<<<dim3(Nn, Bz), 256>>>(x, alpha, dw7, dw25, dw49, Tr, S);
    ln_kernel<<<TT, 256>>>(S, Sn, n1g, n1b);

    gemm_nt<0><<<dim3(Dm/128, TT/128), 256>>>(Sn, qw, qb, nullptr, nullptr, nullptr, nullptr, Qb, Dm, Dm);
    gemm_nt<0><<<dim3(Dm/128, TT/128), 256>>>(Sn, kw, kb, nullptr, nullptr, nullptr, nullptr, Kb, Dm, Dm);
    gemm_nt<0><<<dim3(Dm/128, TT/128), 256>>>(Sn, vw, vb, nullptr, nullptr, nullptr, nullptr, Vb, Dm, Dm);

    attn_kernel<<<dim3(Nn/16, Bz*Hh), 256, ATT_SH_BYTES>>>(Qb, Kb, Vb, Yb);

    gemm_nt<1><<<dim3(Dm/128, TT/128), 256>>>(Yb, ow, ob, S, nullptr, nullptr, nullptr, XS, Dm, Dm);
    ln_kernel<<<TT, 256>>>(XS, Sn, n2g, n2b);
    router_kernel<<<TT, 128>>>(Sn, rw, Wt, Aux);
    assign_kernel<<<TT/256, 256>>>(Wt, Cnt, Eidx, Ewt);
    gather_kernel<<<dim3(TT, NE), 256>>>(Sn, Cnt, Eidx, Xe);

    for (int e = 0; e < NE; e++) {
        gemm_nt<2><<<dim3(MH/128, TT/128), 256>>>(
            Xe + (size_t)e*TT*Dm, ew1 + (size_t)e*MH*Dm, eb1 + (size_t)e*MH,
            nullptr, Cnt + e, nullptr, nullptr, Hb, Dm, MH);
        gemm_nt<3><<<dim3(Dm/128, TT/128), 256>>>(
            Hb, ew2 + (size_t)e*Dm*MH, eb2 + (size_t)e*Dm,
            nullptr, Cnt + e, Eidx + e*TT, Ewt + e*TT, XS, MH, Dm);
    }

    final_kernel<<<dim3(Nn, Bz), 256>>>(tw, tb, Tr, XS, out);
    aux_write_kernel<<<1, 1>>>(Aux, out, out_size);
}

// round 3
// speedup vs baseline: 2.0752x; 1.4719x over previous
#include <cuda_runtime.h>
#include <math.h>

#define Bz 8
#define Nn 1024
#define Dm 1024
#define Hh 16
#define HD 64
#define TT (Bz*Nn)       // 8192 tokens
#define MH 2048
#define NE 4

// ---------------- static device scratch (no allocation allowed) ----------------
__device__ float g_Tr[(size_t)TT*Dm];
__device__ float g_S [(size_t)TT*Dm];
__device__ float g_Sn[(size_t)TT*Dm];
__device__ float g_Q [(size_t)TT*Dm];
__device__ float g_K [(size_t)TT*Dm];
__device__ float g_V [(size_t)TT*Dm];
__device__ float g_Y [(size_t)TT*Dm];
__device__ float g_XS[(size_t)TT*Dm];
__device__ float g_H [(size_t)TT*MH];
__device__ float g_W [(size_t)TT*NE];
__device__ float g_Xe[(size_t)NE*TT*Dm];
__device__ int   g_Eidx[NE*TT];
__device__ float g_Ewt [NE*TT];
__device__ int   g_Cnt[NE];
__device__ float g_Aux[2*NE];

// ---------------- tf32 helpers ----------------
__device__ __forceinline__ unsigned f2tf32(float x) {
    unsigned r; asm("cvt.rna.tf32.f32 %0, %1;" : "=r"(r) : "f"(x)); return r;
}
__device__ __forceinline__ void mma_tf32(float* c, const unsigned* a, const unsigned* b) {
    asm volatile(
        "mma.sync.aligned.m16n8k8.row.col.f32.tf32.tf32.f32 "
        "{%0,%1,%2,%3}, {%4,%5,%6,%7}, {%8,%9}, {%0,%1,%2,%3};\n"
        : "+f"(c[0]), "+f"(c[1]), "+f"(c[2]), "+f"(c[3])
        : "r"(a[0]), "r"(a[1]), "r"(a[2]), "r"(a[3]), "r"(b[0]), "r"(b[1]));
}

// ---------------- decomposition ----------------
__global__ __launch_bounds__(256) void decomp_kernel(
    const float* __restrict__ x, const float* __restrict__ alpha,
    const float* __restrict__ w7, const float* __restrict__ w25,
    const float* __restrict__ w49, float* __restrict__ Tr, float* __restrict__ S)
{
    int n = blockIdx.x, b = blockIdx.y;
    float a0 = alpha[0], a1 = alpha[1], a2 = alpha[2];
    float mx = fmaxf(a0, fmaxf(a1, a2));
    float e0 = __expf(a0-mx), e1 = __expf(a1-mx), e2 = __expf(a2-mx);
    float inv = 1.f/(e0+e1+e2);
    float wt0 = e0*inv, wt1 = e1*inv, wt2 = e2*inv;

    for (int d = threadIdx.x; d < Dm; d += 256) {
        float t7 = 0.f, t25 = 0.f, t49 = 0.f;
        #pragma unroll
        for (int j = 0; j < 7; j++) {
            int p = n + j - 3; p = p < 0 ? -p : (p >= Nn ? 2*Nn-2-p : p);
            t7 += w7[d*7+j] * x[((size_t)(b*Nn+p))*Dm + d];
        }
        #pragma unroll
        for (int j = 0; j < 25; j++) {
            int p = n + j - 12; p = p < 0 ? -p : (p >= Nn ? 2*Nn-2-p : p);
            t25 += w25[d*25+j] * x[((size_t)(b*Nn+p))*Dm + d];
        }
        #pragma unroll
        for (int j = 0; j < 49; j++) {
            int p = n + j - 24; p = p < 0 ? -p : (p >= Nn ? 2*Nn-2-p : p);
            t49 += w49[d*49+j] * x[((size_t)(b*Nn+p))*Dm + d];
        }
        float tr = wt0*t7 + wt1*t25 + wt2*t49;
        size_t idx = ((size_t)(b*Nn+n))*Dm + d;
        Tr[idx] = tr;
        S[idx]  = x[idx] - tr;
    }
}

// ---------------- LayerNorm ----------------
__global__ __launch_bounds__(256) void ln_kernel(
    const float* __restrict__ in, float* __restrict__ out,
    const float* __restrict__ g, const float* __restrict__ b)
{
    __shared__ float red[256];
    int t = blockIdx.x;
    const float* row = in + (size_t)t*Dm;
    int tid = threadIdx.x;
    float s = 0.f;
    for (int d = tid; d < Dm; d += 256) s += row[d];
    red[tid] = s; __syncthreads();
    for (int o = 128; o; o >>= 1) { if (tid < o) red[tid] += red[tid+o]; __syncthreads(); }
    float m = red[0] * (1.f/Dm);
    __syncthreads();
    float v = 0.f;
    for (int d = tid; d < Dm; d += 256) { float dv = row[d]-m; v += dv*dv; }
    red[tid] = v; __syncthreads();
    for (int o = 128; o; o >>= 1) { if (tid < o) red[tid] += red[tid+o]; __syncthreads(); }
    float inv = rsqrtf(red[0]*(1.f/Dm) + 1e-5f);
    for (int d = tid; d < Dm; d += 256)
        out[(size_t)t*Dm + d] = (row[d]-m)*inv*g[d] + b[d];
}

// ---------------- tf32 tensor-core GEMM NT: C[t,o] = A·W^T + bias (+extras) ----------------
// MODE 0: C = dot+bias ; MODE 1: += res ; MODE 2: gelu, compact ; MODE 3: scatter +=, compact
__device__ __forceinline__ float gelu_f(float v) {
    return 0.5f*v*(1.0f + erff(v*0.70710678118654752f));
}

#define PITCH 136

template<int MODE>
__global__ __launch_bounds__(256, 2) void gemm_tc(
    const float* __restrict__ A, const float* __restrict__ W,
    const float* __restrict__ bias, const float* __restrict__ res,
    const int* __restrict__ cnt, const int* __restrict__ ridx,
    const float* __restrict__ wvec,
    float* __restrict__ C, int K, int O)
{
    __shared__ unsigned As[16][PITCH];
    __shared__ unsigned Bs[16][PITCH];
    int t0 = blockIdx.y*128, o0 = blockIdx.x*128;
    int tid = threadIdx.x;

    int cN = 1 << 30;
    if (MODE == 2 || MODE == 3) {
        cN = *cnt;
        if (t0 >= cN) return;
    }

    int lane = tid & 31, warp = tid >> 5;
    int warp_m = warp >> 2, warp_n = warp & 3;   // 2 x 4 warps
    int gid = lane >> 2, tig = lane & 3;

    float acc[4][4][4];
    #pragma unroll
    for (int im = 0; im < 4; im++)
        #pragma unroll
        for (int in = 0; in < 4; in++)
            #pragma unroll
            for (int q = 0; q < 4; q++) acc[im][in][q] = 0.f;

    int lr = tid >> 1, lc = (tid & 1)*8;
    const float* Ap = A + (size_t)(t0+lr)*K + lc;
    const float* Bp = W + (size_t)(o0+lr)*K + lc;

    float4 pa0 = *(const float4*)(Ap);
    float4 pa1 = *(const float4*)(Ap+4);
    float4 pb0 = *(const float4*)(Bp);
    float4 pb1 = *(const float4*)(Bp+4);

    for (int kt = 0; kt < K; kt += 16) {
        As[lc+0][lr]=f2tf32(pa0.x); As[lc+1][lr]=f2tf32(pa0.y);
        As[lc+2][lr]=f2tf32(pa0.z); As[lc+3][lr]=f2tf32(pa0.w);
        As[lc+4][lr]=f2tf32(pa1.x); As[lc+5][lr]=f2tf32(pa1.y);
        As[lc+6][lr]=f2tf32(pa1.z); As[lc+7][lr]=f2tf32(pa1.w);
        Bs[lc+0][lr]=f2tf32(pb0.x); Bs[lc+1][lr]=f2tf32(pb0.y);
        Bs[lc+2][lr]=f2tf32(pb0.z); Bs[lc+3][lr]=f2tf32(pb0.w);
        Bs[lc+4][lr]=f2tf32(pb1.x); Bs[lc+5][lr]=f2tf32(pb1.y);
        Bs[lc+6][lr]=f2tf32(pb1.z); Bs[lc+7][lr]=f2tf32(pb1.w);
        __syncthreads();
        if (kt + 16 < K) {
            pa0 = *(const float4*)(Ap + kt + 16);
            pa1 = *(const float4*)(Ap + kt + 20);
            pb0 = *(const float4*)(Bp + kt + 16);
            pb1 = *(const float4*)(Bp + kt + 20);
        }
        #pragma unroll
        for (int ks = 0; ks < 16; ks += 8) {
            unsigned af[4][4], bf[4][2];
            #pragma unroll
            for (int im = 0; im < 4; im++) {
                int m = warp_m*64 + im*16 + gid;
                af[im][0] = As[ks+tig  ][m];
                af[im][1] = As[ks+tig  ][m+8];
                af[im][2] = As[ks+tig+4][m];
                af[im][3] = As[ks+tig+4][m+8];
            }
            #pragma unroll
            for (int in = 0; in < 4; in++) {
                int n = warp_n*32 + in*8 + gid;
                bf[in][0] = Bs[ks+tig  ][n];
                bf[in][1] = Bs[ks+tig+4][n];
            }
            #pragma unroll
            for (int im = 0; im < 4; im++)
                #pragma unroll
                for (int in = 0; in < 4; in++)
                    mma_tf32(acc[im][in], af[im], bf[in]);
        }
        __syncthreads();
    }

    // epilogue: c0,c1 -> (row0, col, col+1); c2,c3 -> (row0+8, ...)
    #pragma unroll
    for (int im = 0; im < 4; im++) {
        #pragma unroll
        for (int half = 0; half < 2; half++) {
            int row = t0 + warp_m*64 + im*16 + gid + half*8;
            if ((MODE == 2 || MODE == 3) && row >= cN) continue;
            float w = 0.f; int tgt = row;
            if (MODE == 3) { w = wvec[row]; tgt = ridx[row]; }
            #pragma unroll
            for (int in = 0; in < 4; in++) {
                int col = o0 + warp_n*32 + in*8 + 2*tig;
                float v0 = acc[im][in][half*2+0] + bias[col];
                float v1 = acc[im][in][half*2+1] + bias[col+1];
                size_t idx = (size_t)row*O + col;
                if (MODE == 0) { C[idx] = v0; C[idx+1] = v1; }
                else if (MODE == 1) { C[idx] = v0 + res[idx]; C[idx+1] = v1 + res[idx+1]; }
                else if (MODE == 2) { C[idx] = gelu_f(v0); C[idx+1] = gelu_f(v1); }
                else {
                    size_t oidx = (size_t)tgt*O + col;
                    C[oidx]   += w*v0;
                    C[oidx+1] += w*v1;
                }
            }
        }
    }
}

// ---------------- ALiBi attention: block = (b,h, 16 queries) ----------------
#define ATT_SH_FLOATS (16*64 + 64*68 + 16*1024)

__global__ __launch_bounds__(256) void attn_kernel(
    const float* __restrict__ Q, const float* __restrict__ K,
    const float* __restrict__ V, float* __restrict__ Y)
{
    extern __shared__ float sh[];
    float* Qs = sh;                 // [r*64 + d]
    float* KV = sh + 16*64;         // K phase: [d*68+j]; V phase: [j*68+d]
    float* Ps = sh + 16*64 + 64*68; // [r*1024 + j]

    int bh = blockIdx.y;
    int b = bh >> 4, h = bh & 15;
    int q0 = blockIdx.x * 16;
    int tid = threadIdx.x;
    float slope = exp2f(-0.5f * (float)(h+1));

    for (int i = tid; i < 16*64; i += 256) {
        int r = i >> 6, d = i & 63;
        Qs[i] = Q[((size_t)(b*Nn + q0 + r))*Dm + h*64 + d];
    }
    __syncthreads();

    int rq = tid >> 4;              // 0..15 query row
    int j0 = (tid & 15) * 4;        // 0..60, 4 keys per thread
    int qg = q0 + rq;

    for (int kt = 0; kt < Nn; kt += 64) {
        for (int i = tid; i < 64*64; i += 256) {
            int j = i >> 6, d = i & 63;
            KV[d*68 + j] = K[((size_t)(b*Nn + kt + j))*Dm + h*64 + d];
        }
        __syncthreads();
        float4 s = make_float4(0.f,0.f,0.f,0.f);
        #pragma unroll 16
        for (int d = 0; d < 64; d++) {
            float q = Qs[rq*64+d];
            float4 kv = *(const float4*)&KV[d*68 + j0];
            s.x += q*kv.x; s.y += q*kv.y; s.z += q*kv.z; s.w += q*kv.w;
        }
        int jg = kt + j0;
        float4 o;
        o.x = s.x*0.125f - slope*((jg+0 > qg) ? (float)(jg+0-qg) : 0.f);
        o.y = s.y*0.125f - slope*((jg+1 > qg) ? (float)(jg+1-qg) : 0.f);
        o.z = s.z*0.125f - slope*((jg+2 > qg) ? (float)(jg+2-qg) : 0.f);
        o.w = s.w*0.125f - slope*((jg+3 > qg) ? (float)(jg+3-qg) : 0.f);
        *(float4*)&Ps[rq*1024 + jg] = o;
        __syncthreads();
    }

    int warp = tid >> 5, lane = tid & 31;
    for (int r = warp; r < 16; r += 8) {
        float mxv = -1e30f;
        for (int j = lane; j < Nn; j += 32) mxv = fmaxf(mxv, Ps[r*1024+j]);
        #pragma unroll
        for (int o = 16; o; o >>= 1) mxv = fmaxf(mxv, __shfl_xor_sync(0xffffffff, mxv, o));
        float sum = 0.f;
        for (int j = lane; j < Nn; j += 32) {
            float p = __expf(Ps[r*1024+j] - mxv);
            Ps[r*1024+j] = p; sum += p;
        }
        #pragma unroll
        for (int o = 16; o; o >>= 1) sum += __shfl_xor_sync(0xffffffff, sum, o);
        float invs = 1.f / sum;
        for (int j = lane; j < Nn; j += 32) Ps[r*1024+j] *= invs;
    }
    __syncthreads();

    int r = tid >> 4, d0 = (tid & 15) << 2;
    float4 acc = make_float4(0.f, 0.f, 0.f, 0.f);
    for (int kt = 0; kt < Nn; kt += 64) {
        for (int i = tid; i < 64*64; i += 256) {
            int j = i >> 6, d = i & 63;
            KV[j*68 + d] = V[((size_t)(b*Nn + kt + j))*Dm + h*64 + d];
        }
        __syncthreads();
        #pragma unroll 8
        for (int j = 0; j < 64; j++) {
            float p = Ps[r*1024 + kt + j];
            float4 v = *(const float4*)&KV[j*68 + d0];
            acc.x += p*v.x; acc.y += p*v.y; acc.z += p*v.z; acc.w += p*v.w;
        }
        __syncthreads();
    }
    float* yout = &Y[((size_t)(b*Nn + q0 + r))*Dm + h*64 + d0];
    yout[0]=acc.x; yout[1]=acc.y; yout[2]=acc.z; yout[3]=acc.w;
}

// ---------------- router ----------------
__global__ __launch_bounds__(128) void router_kernel(
    const float* __restrict__ xf, const float* __restrict__ rw,
    float* __restrict__ Wout, float* __restrict__ Aux)
{
    int t = blockIdx.x;
    int warp = threadIdx.x >> 5, lane = threadIdx.x & 31;
    __shared__ float sg[NE];
    const float* xrow = xf + (size_t)t*Dm;
    float s = 0.f;
    for (int i = lane; i < Dm; i += 32) s += xrow[i]*rw[(size_t)warp*Dm + i];
    #pragma unroll
    for (int o = 16; o; o >>= 1) s += __shfl_xor_sync(0xffffffff, s, o);
    if (lane == 0) sg[warp] = s;
    __syncthreads();
    if (threadIdx.x == 0) {
        float m = fmaxf(fmaxf(sg[0],sg[1]), fmaxf(sg[2],sg[3]));
        float e[NE], sum = 0.f;
        #pragma unroll
        for (int i = 0; i < NE; i++) { e[i] = __expf(sg[i]-m); sum += e[i]; }
        float gate[NE];
        #pragma unroll
        for (int i = 0; i < NE; i++) gate[i] = e[i]/sum;
        int i0 = 0;
        #pragma unroll
        for (int i = 1; i < NE; i++) if (gate[i] > gate[i0]) i0 = i;
        int i1 = -1;
        #pragma unroll
        for (int i = 0; i < NE; i++) if (i != i0 && (i1 < 0 || gate[i] > gate[i1])) i1 = i;
        float s2 = fmaxf(gate[i0] + gate[i1], 1e-9f);
        #pragma unroll
        for (int i = 0; i < NE; i++) Wout[(size_t)t*NE + i] = 0.f;
        Wout[(size_t)t*NE + i0] = gate[i0]/s2;
        Wout[(size_t)t*NE + i1] = gate[i1]/s2;
        #pragma unroll
        for (int i = 0; i < NE; i++) atomicAdd(&Aux[i], gate[i]);
        atomicAdd(&Aux[NE + i0], 1.f);
        atomicAdd(&Aux[NE + i1], 1.f);
    }
}

// ---------------- MoE assignment / gather ----------------
__global__ __launch_bounds__(256) void assign_kernel(
    const float* __restrict__ Wt, int* __restrict__ cnt,
    int* __restrict__ eidx, float* __restrict__ ewt)
{
    int t = blockIdx.x*256 + threadIdx.x;
    if (t >= TT) return;
    #pragma unroll
    for (int e = 0; e < NE; e++) {
        float w = Wt[(size_t)t*NE + e];
        if (w != 0.f) {
            int pos = atomicAdd(&cnt[e], 1);
            eidx[e*TT + pos] = t;
            ewt [e*TT + pos] = w;
        }
    }
}

__global__ __launch_bounds__(256) void gather_kernel(
    const float* __restrict__ xf, const int* __restrict__ cnt,
    const int* __restrict__ eidx, float* __restrict__ Xe)
{
    int e = blockIdx.y, row = blockIdx.x;
    int c = cnt[e];
    float4* dst = (float4*)(Xe + ((size_t)e*TT + row)*Dm);
    if (row < c) {
        const float4* src = (const float4*)(xf + (size_t)eidx[e*TT + row]*Dm);
        dst[threadIdx.x] = src[threadIdx.x];
    } else if (row < ((c + 127) & ~127)) {
        dst[threadIdx.x] = make_float4(0.f,0.f,0.f,0.f);
    }
}

// ---------------- final ----------------
__global__ __launch_bounds__(256) void final_kernel(
    const float* __restrict__ tw, const float* __restrict__ tb,
    const float* __restrict__ Tr, const float* __restrict__ XS,
    float* __restrict__ out)
{
    int n = blockIdx.x, b = blockIdx.y;
    for (int d = threadIdx.x; d < Dm; d += 256) {
        float acc = tb[d];
        #pragma unroll
        for (int j = 0; j < 5; j++) {
            int p = n + j - 2;
            if (p >= 0 && p < Nn) acc += tw[d*5+j] * Tr[((size_t)(b*Nn+p))*Dm + d];
        }
        size_t idx = ((size_t)(b*Nn+n))*Dm + d;
        out[idx] = XS[idx] + acc;
    }
}

__global__ void zero_aux_kernel(float* Aux, int* cnt) {
    if (threadIdx.x < 2*NE) Aux[threadIdx.x] = 0.f;
    if (threadIdx.x < NE) cnt[threadIdx.x] = 0;
}

__global__ void aux_write_kernel(const float* Aux, float* out, int out_size) {
    if (out_size > TT*Dm) {
        float a = 0.f;
        #pragma unroll
        for (int e = 0; e < NE; e++)
            a += (Aux[e]/(float)TT) * (Aux[NE+e]/(float)TT);
        out[TT*Dm] = (float)NE * a;
    }
}

// ---------------- launcher ----------------
extern "C" void kernel_launch(void* const* d_in, const int* in_sizes, int n_in,
                              void* d_out, int out_size)
{
    const float* x    = (const float*)d_in[0];
    const float* qw   = (const float*)d_in[1];
    const float* qb   = (const float*)d_in[2];
    const float* kw   = (const float*)d_in[3];
    const float* kb   = (const float*)d_in[4];
    const float* vw   = (const float*)d_in[5];
    const float* vb   = (const float*)d_in[6];
    const float* ow   = (const float*)d_in[7];
    const float* ob   = (const float*)d_in[8];
    const float* n1g  = (const float*)d_in[9];
    const float* n1b  = (const float*)d_in[10];
    const float* n2g  = (const float*)d_in[11];
    const float* n2b  = (const float*)d_in[12];
    const float* alpha= (const float*)d_in[13];
    const float* dw7  = (const float*)d_in[14];
    const float* dw25 = (const float*)d_in[15];
    const float* dw49 = (const float*)d_in[16];
    const float* rw   = (const float*)d_in[17];
    const float* ew1  = (const float*)d_in[18];
    const float* eb1  = (const float*)d_in[19];
    const float* ew2  = (const float*)d_in[20];
    const float* eb2  = (const float*)d_in[21];
    const float* tw   = (const float*)d_in[22];
    const float* tb   = (const float*)d_in[23];
    float* out = (float*)d_out;

    float *Tr,*S,*Sn,*Qb,*Kb,*Vb,*Yb,*XS,*Hb,*Wt,*Xe,*Ewt,*Aux;
    int *Eidx,*Cnt;
    cudaGetSymbolAddress((void**)&Tr,  g_Tr);
    cudaGetSymbolAddress((void**)&S,   g_S);
    cudaGetSymbolAddress((void**)&Sn,  g_Sn);
    cudaGetSymbolAddress((void**)&Qb,  g_Q);
    cudaGetSymbolAddress((void**)&Kb,  g_K);
    cudaGetSymbolAddress((void**)&Vb,  g_V);
    cudaGetSymbolAddress((void**)&Yb,  g_Y);
    cudaGetSymbolAddress((void**)&XS,  g_XS);
    cudaGetSymbolAddress((void**)&Hb,  g_H);
    cudaGetSymbolAddress((void**)&Wt,  g_W);
    cudaGetSymbolAddress((void**)&Xe,  g_Xe);
    cudaGetSymbolAddress((void**)&Ewt, g_Ewt);
    cudaGetSymbolAddress((void**)&Aux, g_Aux);
    cudaGetSymbolAddress((void**)&Eidx,g_Eidx);
    cudaGetSymbolAddress((void**)&Cnt, g_Cnt);

    const int ATT_SH_BYTES = ATT_SH_FLOATS * 4;
    cudaFuncSetAttribute(attn_kernel, cudaFuncAttributeMaxDynamicSharedMemorySize, ATT_SH_BYTES);

    zero_aux_kernel<<<1, 32>>>(Aux, Cnt);
    decomp_kernel<<<dim3(Nn, Bz), 256>>>(x, alpha, dw7, dw25, dw49, Tr, S);
    ln_kernel<<<TT, 256>>>(S, Sn, n1g, n1b);

    gemm_tc<0><<<dim3(Dm/128, TT/128), 256>>>(Sn, qw, qb, nullptr, nullptr, nullptr, nullptr, Qb, Dm, Dm);
    gemm_tc<0><<<dim3(Dm/128, TT/128), 256>>>(Sn, kw, kb, nullptr, nullptr, nullptr, nullptr, Kb, Dm, Dm);
    gemm_tc<0><<<dim3(Dm/128, TT/128), 256>>>(Sn, vw, vb, nullptr, nullptr, nullptr, nullptr, Vb, Dm, Dm);

    attn_kernel<<<dim3(Nn/16, Bz*Hh), 256, ATT_SH_BYTES>>>(Qb, Kb, Vb, Yb);

    gemm_tc<1><<<dim3(Dm/128, TT/128), 256>>>(Yb, ow, ob, S, nullptr, nullptr, nullptr, XS, Dm, Dm);
    ln_kernel<<<TT, 256>>>(XS, Sn, n2g, n2b);
    router_kernel<<<TT, 128>>>(Sn, rw, Wt, Aux);
    assign_kernel<<<TT/256, 256>>>(Wt, Cnt, Eidx, Ewt);
    gather_kernel<<<dim3(TT, NE), 256>>>(Sn, Cnt, Eidx, Xe);

    for (int e = 0; e < NE; e++) {
        gemm_tc<2><<<dim3(MH/128, TT/128), 256>>>(
            Xe + (size_t)e*TT*Dm, ew1 + (size_t)e*MH*Dm, eb1 + (size_t)e*MH,
            nullptr, Cnt + e, nullptr, nullptr, Hb, Dm, MH);
        gemm_tc<3><<<dim3(Dm/128, TT/128), 256>>>(
            Hb, ew2 + (size_t)e*Dm*MH, eb2 + (size_t)e*Dm,
            nullptr, Cnt + e, Eidx + e*TT, Ewt + e*TT, XS, MH, Dm);
    }

    final_kernel<<<dim3(Nn, Bz), 256>>>(tw, tb, Tr, XS, out);
    aux_write_kernel<<<1, 1>>>(Aux, out, out_size);
}

// round 4
// speedup vs baseline: 3.6413x; 1.7547x over previous
#include <cuda_runtime.h>
#include <math.h>

#define Bz 8
#define Nn 1024
#define Dm 1024
#define Hh 16
#define HD 64
#define TT (Bz*Nn)       // 8192 tokens
#define MH 2048
#define NE 4

// ---------------- static device scratch (no allocation allowed) ----------------
__device__ float g_Tr[(size_t)TT*Dm];
__device__ float g_S [(size_t)TT*Dm];
__device__ float g_Sn[(size_t)TT*Dm];
__device__ float g_Q [(size_t)TT*Dm];
__device__ float g_K [(size_t)TT*Dm];
__device__ float g_V [(size_t)TT*Dm];
__device__ float g_Y [(size_t)TT*Dm];
__device__ float g_XS[(size_t)TT*Dm];
__device__ float g_H [(size_t)TT*MH];
__device__ float g_W [(size_t)TT*NE];
__device__ float g_Xe[(size_t)NE*TT*Dm];
__device__ int   g_Eidx[NE*TT];
__device__ float g_Ewt [NE*TT];
__device__ int   g_Cnt[NE];
__device__ float g_Aux[2*NE];

// ---------------- tf32 helpers ----------------
__device__ __forceinline__ unsigned f2tf32(float x) {
    unsigned r; asm("cvt.rna.tf32.f32 %0, %1;" : "=r"(r) : "f"(x)); return r;
}
__device__ __forceinline__ void mma_tf32(float* c, const unsigned* a, const unsigned* b) {
    asm volatile(
        "mma.sync.aligned.m16n8k8.row.col.f32.tf32.tf32.f32 "
        "{%0,%1,%2,%3}, {%4,%5,%6,%7}, {%8,%9}, {%0,%1,%2,%3};\n"
        : "+f"(c[0]), "+f"(c[1]), "+f"(c[2]), "+f"(c[3])
        : "r"(a[0]), "r"(a[1]), "r"(a[2]), "r"(a[3]), "r"(b[0]), "r"(b[1]));
}

// ---------------- decomposition ----------------
__global__ __launch_bounds__(256) void decomp_kernel(
    const float* __restrict__ x, const float* __restrict__ alpha,
    const float* __restrict__ w7, const float* __restrict__ w25,
    const float* __restrict__ w49, float* __restrict__ Tr, float* __restrict__ S)
{
    int n = blockIdx.x, b = blockIdx.y;
    float a0 = alpha[0], a1 = alpha[1], a2 = alpha[2];
    float mx = fmaxf(a0, fmaxf(a1, a2));
    float e0 = __expf(a0-mx), e1 = __expf(a1-mx), e2 = __expf(a2-mx);
    float inv = 1.f/(e0+e1+e2);
    float wt0 = e0*inv, wt1 = e1*inv, wt2 = e2*inv;

    for (int d = threadIdx.x; d < Dm; d += 256) {
        float t7 = 0.f, t25 = 0.f, t49 = 0.f;
        #pragma unroll
        for (int j = 0; j < 7; j++) {
            int p = n + j - 3; p = p < 0 ? -p : (p >= Nn ? 2*Nn-2-p : p);
            t7 += w7[d*7+j] * x[((size_t)(b*Nn+p))*Dm + d];
        }
        #pragma unroll
        for (int j = 0; j < 25; j++) {
            int p = n + j - 12; p = p < 0 ? -p : (p >= Nn ? 2*Nn-2-p : p);
            t25 += w25[d*25+j] * x[((size_t)(b*Nn+p))*Dm + d];
        }
        #pragma unroll
        for (int j = 0; j < 49; j++) {
            int p = n + j - 24; p = p < 0 ? -p : (p >= Nn ? 2*Nn-2-p : p);
            t49 += w49[d*49+j] * x[((size_t)(b*Nn+p))*Dm + d];
        }
        float tr = wt0*t7 + wt1*t25 + wt2*t49;
        size_t idx = ((size_t)(b*Nn+n))*Dm + d;
        Tr[idx] = tr;
        S[idx]  = x[idx] - tr;
    }
}

// ---------------- LayerNorm ----------------
__global__ __launch_bounds__(256) void ln_kernel(
    const float* __restrict__ in, float* __restrict__ out,
    const float* __restrict__ g, const float* __restrict__ b)
{
    __shared__ float red[256];
    int t = blockIdx.x;
    const float* row = in + (size_t)t*Dm;
    int tid = threadIdx.x;
    float s = 0.f;
    for (int d = tid; d < Dm; d += 256) s += row[d];
    red[tid] = s; __syncthreads();
    for (int o = 128; o; o >>= 1) { if (tid < o) red[tid] += red[tid+o]; __syncthreads(); }
    float m = red[0] * (1.f/Dm);
    __syncthreads();
    float v = 0.f;
    for (int d = tid; d < Dm; d += 256) { float dv = row[d]-m; v += dv*dv; }
    red[tid] = v; __syncthreads();
    for (int o = 128; o; o >>= 1) { if (tid < o) red[tid] += red[tid+o]; __syncthreads(); }
    float inv = rsqrtf(red[0]*(1.f/Dm) + 1e-5f);
    for (int d = tid; d < Dm; d += 256)
        out[(size_t)t*Dm + d] = (row[d]-m)*inv*g[d] + b[d];
}

// ---------------- tf32 tensor-core GEMM NT with packed fragment smem ----------------
// A packed: AsV[(hb*4+t)*66 + grp]*4 + comp ; fragment = one LDS.128
// B packed: BsV[(hb*4+t)*132 + n]*2 + kk    ; fragment = one LDS.64
__device__ __forceinline__ float gelu_f(float v) {
    return 0.5f*v*(1.0f + erff(v*0.70710678118654752f));
}

template<int MODE>
__global__ __launch_bounds__(256, 2) void gemm_tc(
    const float* __restrict__ A, const float* __restrict__ W,
    const float* __restrict__ bias, const float* __restrict__ res,
    const int* __restrict__ cnt, const int* __restrict__ ridx,
    const float* __restrict__ wvec,
    float* __restrict__ C, int K, int O)
{
    __shared__ __align__(16) unsigned AsV[2112];
    __shared__ __align__(16) unsigned BsV[2112];
    int t0 = blockIdx.y*128, o0 = blockIdx.x*128;
    int tid = threadIdx.x;

    int cN = 1 << 30;
    if (MODE == 2 || MODE == 3) {
        cN = *cnt;
        if (t0 >= cN) return;
    }

    int lane = tid & 31, warp = tid >> 5;
    int warp_m = warp >> 2, warp_n = warp & 3;   // 2 x 4 warps
    int gid = lane >> 2, tig = lane & 3;

    float acc[4][4][4];
    #pragma unroll
    for (int im = 0; im < 4; im++)
        #pragma unroll
        for (int in = 0; in < 4; in++)
            #pragma unroll
            for (int q = 0; q < 4; q++) acc[im][in][q] = 0.f;

    int lr = tid >> 1;            // row 0..127
    int hb = tid & 1;             // k-half 0/1
    int lc = hb*8;
    const float* Ap = A + (size_t)(t0+lr)*K + lc;
    const float* Bp = W + (size_t)(o0+lr)*K + lc;

    int grpA = ((lr >> 4) << 3) + (lr & 7);
    int pmA  = (lr >> 3) & 1;

    float4 pa0 = *(const float4*)(Ap);
    float4 pa1 = *(const float4*)(Ap+4);
    float4 pb0 = *(const float4*)(Bp);
    float4 pb1 = *(const float4*)(Bp+4);

    for (int kt = 0; kt < K; kt += 16) {
        {
            float av[8] = {pa0.x,pa0.y,pa0.z,pa0.w,pa1.x,pa1.y,pa1.z,pa1.w};
            float bv[8] = {pb0.x,pb0.y,pb0.z,pb0.w,pb1.x,pb1.y,pb1.z,pb1.w};
            #pragma unroll
            for (int q2 = 0; q2 < 8; q2++) {
                int t = q2 & 3, kk = q2 >> 2;
                AsV[((hb*4 + t)*66 + grpA)*4 + pmA + 2*kk] = f2tf32(av[q2]);
                BsV[((hb*4 + t)*132 + lr)*2 + kk]          = f2tf32(bv[q2]);
            }
        }
        __syncthreads();
        if (kt + 16 < K) {
            pa0 = *(const float4*)(Ap + kt + 16);
            pa1 = *(const float4*)(Ap + kt + 20);
            pb0 = *(const float4*)(Bp + kt + 16);
            pb1 = *(const float4*)(Bp + kt + 20);
        }
        #pragma unroll
        for (int h2 = 0; h2 < 2; h2++) {
            unsigned af[4][4], bf[4][2];
            #pragma unroll
            for (int im = 0; im < 4; im++) {
                uint4 v = *(const uint4*)&AsV[(((h2*4 + tig)*66) + (warp_m*4+im)*8 + gid)*4];
                af[im][0]=v.x; af[im][1]=v.y; af[im][2]=v.z; af[im][3]=v.w;
            }
            #pragma unroll
            for (int in = 0; in < 4; in++) {
                uint2 v = *(const uint2*)&BsV[(((h2*4 + tig)*132) + warp_n*32 + in*8 + gid)*2];
                bf[in][0]=v.x; bf[in][1]=v.y;
            }
            #pragma unroll
            for (int im = 0; im < 4; im++)
                #pragma unroll
                for (int in = 0; in < 4; in++)
                    mma_tf32(acc[im][in], af[im], bf[in]);
        }
        __syncthreads();
    }

    #pragma unroll
    for (int im = 0; im < 4; im++) {
        #pragma unroll
        for (int half = 0; half < 2; half++) {
            int row = t0 + warp_m*64 + im*16 + gid + half*8;
            if ((MODE == 2 || MODE == 3) && row >= cN) continue;
            float w = 0.f; int tgt = row;
            if (MODE == 3) { w = wvec[row]; tgt = ridx[row]; }
            #pragma unroll
            for (int in = 0; in < 4; in++) {
                int col = o0 + warp_n*32 + in*8 + 2*tig;
                float v0 = acc[im][in][half*2+0] + bias[col];
                float v1 = acc[im][in][half*2+1] + bias[col+1];
                size_t idx = (size_t)row*O + col;
                if (MODE == 0) { C[idx] = v0; C[idx+1] = v1; }
                else if (MODE == 1) { C[idx] = v0 + res[idx]; C[idx+1] = v1 + res[idx+1]; }
                else if (MODE == 2) { C[idx] = gelu_f(v0); C[idx+1] = gelu_f(v1); }
                else {
                    size_t oidx = (size_t)tgt*O + col;
                    C[oidx]   += w*v0;
                    C[oidx+1] += w*v1;
                }
            }
        }
    }
}

// ---------------- flash attention with tf32 MMA ----------------
// block: (b,h), 64-query tile, key chunks of 64. 256 threads, warps 4m x 2n.
#define ATN_SH_FLOATS (4*4352 + 320)

__global__ __launch_bounds__(256) void attn_mma_kernel(
    const float* __restrict__ Q, const float* __restrict__ K,
    const float* __restrict__ V, float* __restrict__ Y)
{
    extern __shared__ __align__(16) unsigned ash[];
    unsigned* QsV = ash;             // [8][4][34][4] packed A fragments
    unsigned* KsV = ash + 4352;      // [8][4][68][2] packed B fragments (keys)
    unsigned* PsV = ash + 2*4352;    // [8][4][34][4] packed A fragments (P)
    unsigned* VsV = ash + 3*4352;    // [8][4][68][2] packed B fragments (dims)
    float* mrow = (float*)(ash + 4*4352);  // [64]
    float* lrow = mrow + 64;               // [64]
    float* rrow = lrow + 64;               // [64]
    float* cred = rrow + 64;               // [128]

    int bh = blockIdx.y;
    int b = bh >> 4, h = bh & 15;
    int q0 = blockIdx.x * 64;
    int tid = threadIdx.x;
    int warp = tid >> 5, lane = tid & 31;
    int gid = lane >> 2, tig = lane & 3;
    int warp_m = warp >> 1, warp_n = warp & 1;
    float slope = exp2f(-0.5f * (float)(h+1));

    // load Q tile into packed fragment layout
    for (int i = tid; i < 64*64; i += 256) {
        int d = i & 63, q = i >> 6;
        float v = Q[((size_t)(b*Nn + q0 + q))*Dm + h*64 + d];
        int b8 = d >> 3, t = d & 3, kk = (d >> 2) & 1;
        int grp = ((q >> 4) << 3) + (q & 7), comp = ((q >> 3) & 1) + 2*kk;
        QsV[((b8*4 + t)*34 + grp)*4 + comp] = f2tf32(v);
    }
    if (tid < 64) { mrow[tid] = -1e30f; lrow[tid] = 0.f; }

    float o_acc[4][4];
    #pragma unroll
    for (int in = 0; in < 4; in++)
        #pragma unroll
        for (int q = 0; q < 4; q++) o_acc[in][q] = 0.f;

    int qlo = warp_m*16 + gid, qhi = qlo + 8;
    int qglo = q0 + qlo, qghi = q0 + qhi;
    int grpP = warp_m*8 + gid;

    for (int kt = 0; kt < Nn; kt += 64) {
        __syncthreads();
        for (int i = tid; i < 64*64; i += 256) {
            int d = i & 63, j = i >> 6;
            float v = K[((size_t)(b*Nn + kt + j))*Dm + h*64 + d];
            int b8 = d >> 3, t = d & 3, kk = (d >> 2) & 1;
            KsV[((b8*4 + t)*68 + j)*2 + kk] = f2tf32(v);
        }
        for (int i = tid; i < 64*64; i += 256) {
            int d = i & 63, j = i >> 6;
            float v = V[((size_t)(b*Nn + kt + j))*Dm + h*64 + d];
            int b8 = j >> 3, t = j & 3, kk = (j >> 2) & 1;
            VsV[((b8*4 + t)*68 + d)*2 + kk] = f2tf32(v);
        }
        __syncthreads();

        // S = Q K^T : warp computes 16 q rows x 32 keys (4 n8 tiles)
        float acc_s[4][4];
        #pragma unroll
        for (int in = 0; in < 4; in++)
            #pragma unroll
            for (int q = 0; q < 4; q++) acc_s[in][q] = 0.f;

        #pragma unroll
        for (int b8 = 0; b8 < 8; b8++) {
            uint4 afv = *(const uint4*)&QsV[((b8*4 + tig)*34 + grpP)*4];
            unsigned af[4] = {afv.x, afv.y, afv.z, afv.w};
            #pragma unroll
            for (int in = 0; in < 4; in++) {
                uint2 bfv = *(const uint2*)&KsV[((b8*4 + tig)*68 + warp_n*32 + in*8 + gid)*2];
                unsigned bf[2] = {bfv.x, bfv.y};
                mma_tf32(acc_s[in], af, bf);
            }
        }

        // scale + alibi + chunk row max
        float rmax0 = -1e30f, rmax1 = -1e30f;
        #pragma unroll
        for (int in = 0; in < 4; in++) {
            #pragma unroll
            for (int c2 = 0; c2 < 2; c2++) {
                int kg = kt + warp_n*32 + in*8 + 2*tig + c2;
                float d0 = (kg > qglo) ? (float)(kg - qglo) : 0.f;
                float d1 = (kg > qghi) ? (float)(kg - qghi) : 0.f;
                acc_s[in][c2]   = acc_s[in][c2]  *0.125f - slope*d0;
                acc_s[in][c2+2] = acc_s[in][c2+2]*0.125f - slope*d1;
                rmax0 = fmaxf(rmax0, acc_s[in][c2]);
                rmax1 = fmaxf(rmax1, acc_s[in][c2+2]);
            }
        }
        rmax0 = fmaxf(rmax0, __shfl_xor_sync(0xffffffff, rmax0, 1));
        rmax0 = fmaxf(rmax0, __shfl_xor_sync(0xffffffff, rmax0, 2));
        rmax1 = fmaxf(rmax1, __shfl_xor_sync(0xffffffff, rmax1, 1));
        rmax1 = fmaxf(rmax1, __shfl_xor_sync(0xffffffff, rmax1, 2));
        if (tig == 0) {
            cred[warp_n*64 + qlo] = rmax0;
            cred[warp_n*64 + qhi] = rmax1;
        }
        __syncthreads();
        if (tid < 64) {
            float mo = mrow[tid];
            float mn = fmaxf(mo, fmaxf(cred[tid], cred[64+tid]));
            mrow[tid] = mn;
            rrow[tid] = __expf(mo - mn);
        }
        __syncthreads();

        // P = exp(S - m), row sums, pack P fragments
        float mn0 = mrow[qlo], mn1 = mrow[qhi];
        float r0 = rrow[qlo], r1 = rrow[qhi];
        float rs0 = 0.f, rs1 = 0.f;
        #pragma unroll
        for (int in = 0; in < 4; in++) {
            #pragma unroll
            for (int c2 = 0; c2 < 2; c2++) {
                float p0 = __expf(acc_s[in][c2]   - mn0);
                float p1 = __expf(acc_s[in][c2+2] - mn1);
                rs0 += p0; rs1 += p1;
                int kin = 2*tig + c2;
                int t = kin & 3, kk = kin >> 2;
                int b8k = warp_n*4 + in;
                PsV[((b8k*4 + t)*34 + grpP)*4 + 0 + 2*kk] = f2tf32(p0);
                PsV[((b8k*4 + t)*34 + grpP)*4 + 1 + 2*kk] = f2tf32(p1);
            }
        }
        rs0 += __shfl_xor_sync(0xffffffff, rs0, 1);
        rs0 += __shfl_xor_sync(0xffffffff, rs0, 2);
        rs1 += __shfl_xor_sync(0xffffffff, rs1, 1);
        rs1 += __shfl_xor_sync(0xffffffff, rs1, 2);
        if (tig == 0) {
            cred[warp_n*64 + qlo] = rs0;
            cred[warp_n*64 + qhi] = rs1;
        }
        // rescale output accumulator
        #pragma unroll
        for (int in = 0; in < 4; in++) {
            o_acc[in][0] *= r0; o_acc[in][1] *= r0;
            o_acc[in][2] *= r1; o_acc[in][3] *= r1;
        }
        __syncthreads();
        if (tid < 64) lrow[tid] = lrow[tid]*rrow[tid] + cred[tid] + cred[64+tid];

        // O += P @ V
        #pragma unroll
        for (int b8 = 0; b8 < 8; b8++) {
            uint4 afv = *(const uint4*)&PsV[((b8*4 + tig)*34 + grpP)*4];
            unsigned af[4] = {afv.x, afv.y, afv.z, afv.w};
            #pragma unroll
            for (int in = 0; in < 4; in++) {
                uint2 bfv = *(const uint2*)&VsV[((b8*4 + tig)*68 + warp_n*32 + in*8 + gid)*2];
                unsigned bf[2] = {bfv.x, bfv.y};
                mma_tf32(o_acc[in], af, bf);
            }
        }
    }
    __syncthreads();

    float inv0 = 1.f / lrow[qlo];
    float inv1 = 1.f / lrow[qhi];
    #pragma unroll
    for (int in = 0; in < 4; in++) {
        int col = h*64 + warp_n*32 + in*8 + 2*tig;
        float2 v0 = make_float2(o_acc[in][0]*inv0, o_acc[in][1]*inv0);
        float2 v1 = make_float2(o_acc[in][2]*inv1, o_acc[in][3]*inv1);
        *(float2*)&Y[((size_t)(b*Nn + qglo))*Dm + col] = v0;
        *(float2*)&Y[((size_t)(b*Nn + qghi))*Dm + col] = v1;
    }
}

// ---------------- router ----------------
__global__ __launch_bounds__(128) void router_kernel(
    const float* __restrict__ xf, const float* __restrict__ rw,
    float* __restrict__ Wout, float* __restrict__ Aux)
{
    int t = blockIdx.x;
    int warp = threadIdx.x >> 5, lane = threadIdx.x & 31;
    __shared__ float sg[NE];
    const float* xrow = xf + (size_t)t*Dm;
    float s = 0.f;
    for (int i = lane; i < Dm; i += 32) s += xrow[i]*rw[(size_t)warp*Dm + i];
    #pragma unroll
    for (int o = 16; o; o >>= 1) s += __shfl_xor_sync(0xffffffff, s, o);
    if (lane == 0) sg[warp] = s;
    __syncthreads();
    if (threadIdx.x == 0) {
        float m = fmaxf(fmaxf(sg[0],sg[1]), fmaxf(sg[2],sg[3]));
        float e[NE], sum = 0.f;
        #pragma unroll
        for (int i = 0; i < NE; i++) { e[i] = __expf(sg[i]-m); sum += e[i]; }
        float gate[NE];
        #pragma unroll
        for (int i = 0; i < NE; i++) gate[i] = e[i]/sum;
        int i0 = 0;
        #pragma unroll
        for (int i = 1; i < NE; i++) if (gate[i] > gate[i0]) i0 = i;
        int i1 = -1;
        #pragma unroll
        for (int i = 0; i < NE; i++) if (i != i0 && (i1 < 0 || gate[i] > gate[i1])) i1 = i;
        float s2 = fmaxf(gate[i0] + gate[i1], 1e-9f);
        #pragma unroll
        for (int i = 0; i < NE; i++) Wout[(size_t)t*NE + i] = 0.f;
        Wout[(size_t)t*NE + i0] = gate[i0]/s2;
        Wout[(size_t)t*NE + i1] = gate[i1]/s2;
        #pragma unroll
        for (int i = 0; i < NE; i++) atomicAdd(&Aux[i], gate[i]);
        atomicAdd(&Aux[NE + i0], 1.f);
        atomicAdd(&Aux[NE + i1], 1.f);
    }
}

// ---------------- MoE assignment / gather ----------------
__global__ __launch_bounds__(256) void assign_kernel(
    const float* __restrict__ Wt, int* __restrict__ cnt,
    int* __restrict__ eidx, float* __restrict__ ewt)
{
    int t = blockIdx.x*256 + threadIdx.x;
    if (t >= TT) return;
    #pragma unroll
    for (int e = 0; e < NE; e++) {
        float w = Wt[(size_t)t*NE + e];
        if (w != 0.f) {
            int pos = atomicAdd(&cnt[e], 1);
            eidx[e*TT + pos] = t;
            ewt [e*TT + pos] = w;
        }
    }
}

__global__ __launch_bounds__(256) void gather_kernel(
    const float* __restrict__ xf, const int* __restrict__ cnt,
    const int* __restrict__ eidx, float* __restrict__ Xe)
{
    int e = blockIdx.y, row = blockIdx.x;
    int c = cnt[e];
    float4* dst = (float4*)(Xe + ((size_t)e*TT + row)*Dm);
    if (row < c) {
        const float4* src = (const float4*)(xf + (size_t)eidx[e*TT + row]*Dm);
        dst[threadIdx.x] = src[threadIdx.x];
    } else if (row < ((c + 127) & ~127)) {
        dst[threadIdx.x] = make_float4(0.f,0.f,0.f,0.f);
    }
}

// ---------------- final ----------------
__global__ __launch_bounds__(256) void final_kernel(
    const float* __restrict__ tw, const float* __restrict__ tb,
    const float* __restrict__ Tr, const float* __restrict__ XS,
    float* __restrict__ out)
{
    int n = blockIdx.x, b = blockIdx.y;
    for (int d = threadIdx.x; d < Dm; d += 256) {
        float acc = tb[d];
        #pragma unroll
        for (int j = 0; j < 5; j++) {
            int p = n + j - 2;
            if (p >= 0 && p < Nn) acc += tw[d*5+j] * Tr[((size_t)(b*Nn+p))*Dm + d];
        }
        size_t idx = ((size_t)(b*Nn+n))*Dm + d;
        out[idx] = XS[idx] + acc;
    }
}

__global__ void zero_aux_kernel(float* Aux, int* cnt) {
    if (threadIdx.x < 2*NE) Aux[threadIdx.x] = 0.f;
    if (threadIdx.x < NE) cnt[threadIdx.x] = 0;
}

__global__ void aux_write_kernel(const float* Aux, float* out, int out_size) {
    if (out_size > TT*Dm) {
        float a = 0.f;
        #pragma unroll
        for (int e = 0; e < NE; e++)
            a += (Aux[e]/(float)TT) * (Aux[NE+e]/(float)TT);
        out[TT*Dm] = (float)NE * a;
    }
}

// ---------------- launcher ----------------
extern "C" void kernel_launch(void* const* d_in, const int* in_sizes, int n_in,
                              void* d_out, int out_size)
{
    const float* x    = (const float*)d_in[0];
    const float* qw   = (const float*)d_in[1];
    const float* qb   = (const float*)d_in[2];
    const float* kw   = (const float*)d_in[3];
    const float* kb   = (const float*)d_in[4];
    const float* vw   = (const float*)d_in[5];
    const float* vb   = (const float*)d_in[6];
    const float* ow   = (const float*)d_in[7];
    const float* ob   = (const float*)d_in[8];
    const float* n1g  = (const float*)d_in[9];
    const float* n1b  = (const float*)d_in[10];
    const float* n2g  = (const float*)d_in[11];
    const float* n2b  = (const float*)d_in[12];
    const float* alpha= (const float*)d_in[13];
    const float* dw7  = (const float*)d_in[14];
    const float* dw25 = (const float*)d_in[15];
    const float* dw49 = (const float*)d_in[16];
    const float* rw   = (const float*)d_in[17];
    const float* ew1  = (const float*)d_in[18];
    const float* eb1  = (const float*)d_in[19];
    const float* ew2  = (const float*)d_in[20];
    const float* eb2  = (const float*)d_in[21];
    const float* tw   = (const float*)d_in[22];
    const float* tb   = (const float*)d_in[23];
    float* out = (float*)d_out;

    float *Tr,*S,*Sn,*Qb,*Kb,*Vb,*Yb,*XS,*Hb,*Wt,*Xe,*Ewt,*Aux;
    int *Eidx,*Cnt;
    cudaGetSymbolAddress((void**)&Tr,  g_Tr);
    cudaGetSymbolAddress((void**)&S,   g_S);
    cudaGetSymbolAddress((void**)&Sn,  g_Sn);
    cudaGetSymbolAddress((void**)&Qb,  g_Q);
    cudaGetSymbolAddress((void**)&Kb,  g_K);
    cudaGetSymbolAddress((void**)&Vb,  g_V);
    cudaGetSymbolAddress((void**)&Yb,  g_Y);
    cudaGetSymbolAddress((void**)&XS,  g_XS);
    cudaGetSymbolAddress((void**)&Hb,  g_H);
    cudaGetSymbolAddress((void**)&Wt,  g_W);
    cudaGetSymbolAddress((void**)&Xe,  g_Xe);
    cudaGetSymbolAddress((void**)&Ewt, g_Ewt);
    cudaGetSymbolAddress((void**)&Aux, g_Aux);
    cudaGetSymbolAddress((void**)&Eidx,g_Eidx);
    cudaGetSymbolAddress((void**)&Cnt, g_Cnt);

    const int ATN_SH_BYTES = ATN_SH_FLOATS * 4;
    cudaFuncSetAttribute(attn_mma_kernel, cudaFuncAttributeMaxDynamicSharedMemorySize, ATN_SH_BYTES);

    zero_aux_kernel<<<1, 32>>>(Aux, Cnt);
    decomp_kernel<<<dim3(Nn, Bz), 256>>>(x, alpha, dw7, dw25, dw49, Tr, S);
    ln_kernel<<<TT, 256>>>(S, Sn, n1g, n1b);

    gemm_tc<0><<<dim3(Dm/128, TT/128), 256>>>(Sn, qw, qb, nullptr, nullptr, nullptr, nullptr, Qb, Dm, Dm);
    gemm_tc<0><<<dim3(Dm/128, TT/128), 256>>>(Sn, kw, kb, nullptr, nullptr, nullptr, nullptr, Kb, Dm, Dm);
    gemm_tc<0><<<dim3(Dm/128, TT/128), 256>>>(Sn, vw, vb, nullptr, nullptr, nullptr, nullptr, Vb, Dm, Dm);

    attn_mma_kernel<<<dim3(Nn/64, Bz*Hh), 256, ATN_SH_BYTES>>>(Qb, Kb, Vb, Yb);

    gemm_tc<1><<<dim3(Dm/128, TT/128), 256>>>(Yb, ow, ob, S, nullptr, nullptr, nullptr, XS, Dm, Dm);
    ln_kernel<<<TT, 256>>>(XS, Sn, n2g, n2b);
    router_kernel<<<TT, 128>>>(Sn, rw, Wt, Aux);
    assign_kernel<<<TT/256, 256>>>(Wt, Cnt, Eidx, Ewt);
    gather_kernel<<<dim3(TT, NE), 256>>>(Sn, Cnt, Eidx, Xe);

    for (int e = 0; e < NE; e++) {
        gemm_tc<2><<<dim3(MH/128, TT/128), 256>>>(
            Xe + (size_t)e*TT*Dm, ew1 + (size_t)e*MH*Dm, eb1 + (size_t)e*MH,
            nullptr, Cnt + e, nullptr, nullptr, Hb, Dm, MH);
        gemm_tc<3><<<dim3(Dm/128, TT/128), 256>>>(
            Hb, ew2 + (size_t)e*Dm*MH, eb2 + (size_t)e*Dm,
            nullptr, Cnt + e, Eidx + e*TT, Ewt + e*TT, XS, MH, Dm);
    }

    final_kernel<<<dim3(Nn, Bz), 256>>>(tw, tb, Tr, XS, out);
    aux_write_kernel<<<1, 1>>>(Aux, out, out_size);
}

// round 6
// speedup vs baseline: 4.5503x; 1.2497x over previous
#include <cuda_runtime.h>
#include <math.h>

#define Bz 8
#define Nn 1024
#define Dm 1024
#define Hh 16
#define HD 64
#define TT (Bz*Nn)       // 8192 tokens
#define MH 2048
#define NE 4

// ---------------- static device scratch (no allocation allowed) ----------------
__device__ float g_Tr[(size_t)TT*Dm];
__device__ float g_S [(size_t)TT*Dm];
__device__ float g_Sn[(size_t)TT*Dm];
__device__ float g_Q [(size_t)TT*Dm];
__device__ float g_K [(size_t)TT*Dm];
__device__ float g_V [(size_t)TT*Dm];
__device__ float g_Y [(size_t)TT*Dm];
__device__ float g_XS[(size_t)TT*Dm];
__device__ float g_H [(size_t)TT*MH];
__device__ float g_W [(size_t)TT*NE];
__device__ float g_Xe[(size_t)NE*TT*Dm];
__device__ float g_Ck[(size_t)Dm*49];
__device__ int   g_Eidx[NE*TT];
__device__ float g_Ewt [NE*TT];
__device__ int   g_Cnt[NE];
__device__ float g_Aux[2*NE];

// ---------------- tf32 helpers ----------------
__device__ __forceinline__ unsigned f2tf32(float x) {
    unsigned r; asm("cvt.rna.tf32.f32 %0, %1;" : "=r"(r) : "f"(x)); return r;
}
__device__ __forceinline__ void mma_tf32(float* c, const unsigned* a, const unsigned* b) {
    asm volatile(
        "mma.sync.aligned.m16n8k8.row.col.f32.tf32.tf32.f32 "
        "{%0,%1,%2,%3}, {%4,%5,%6,%7}, {%8,%9}, {%0,%1,%2,%3};\n"
        : "+f"(c[0]), "+f"(c[1]), "+f"(c[2]), "+f"(c[3])
        : "r"(a[0]), "r"(a[1]), "r"(a[2]), "r"(a[3]), "r"(b[0]), "r"(b[1]));
}

// ---------------- combined decomposition kernel build ----------------
__global__ void ckbuild_kernel(
    const float* __restrict__ alpha, const float* __restrict__ w7,
    const float* __restrict__ w25, const float* __restrict__ w49,
    float* __restrict__ ck)
{
    int d = blockIdx.x, j = threadIdx.x;
    if (j >= 49) return;
    float a0 = alpha[0], a1 = alpha[1], a2 = alpha[2];
    float mx = fmaxf(a0, fmaxf(a1, a2));
    float e0 = __expf(a0-mx), e1 = __expf(a1-mx), e2 = __expf(a2-mx);
    float inv = 1.f/(e0+e1+e2);
    float wt0 = e0*inv, wt1 = e1*inv, wt2 = e2*inv;
    float v = wt2 * w49[d*49 + j];
    if (j >= 12 && j < 37) v += wt1 * w25[d*25 + (j-12)];
    if (j >= 21 && j < 28) v += wt0 * w7[d*7 + (j-21)];
    ck[d*49 + j] = v;
}

// ---------------- interior trend: combined 49-tap conv, smem window ----------------
__global__ __launch_bounds__(256) void trend_kernel(
    const float* __restrict__ x, const float* __restrict__ ck,
    float* __restrict__ Tr, float* __restrict__ S)
{
    __shared__ float xs[64][128];
    int b = blockIdx.y;
    int n0 = 24 + blockIdx.x * 16;
    int d0 = blockIdx.z * 128;
    int tid = threadIdx.x;
    int dl = tid & 127, ng = tid >> 7;

    for (int i = tid; i < 64*32; i += 256) {
        int p = i >> 5, c = i & 31;
        *(float4*)&xs[p][c*4] =
            *(const float4*)&x[((size_t)(b*Nn + n0 - 24 + p))*Dm + d0 + c*4];
    }
    __syncthreads();

    float ckr[49];
    #pragma unroll
    for (int j = 0; j < 49; j++) ckr[j] = __ldg(&ck[(size_t)(d0+dl)*49 + j]);

    float acc[8];
    #pragma unroll
    for (int j = 0; j < 8; j++) acc[j] = 0.f;

    #pragma unroll
    for (int pr = 0; pr < 56; pr++) {
        float xv = xs[ng*8 + pr][dl];
        #pragma unroll
        for (int j = 0; j < 8; j++) {
            int t = pr - j;
            if (t >= 0 && t < 49) acc[j] += ckr[t] * xv;
        }
    }

    #pragma unroll
    for (int j = 0; j < 8; j++) {
        int nl = ng*8 + j;
        size_t idx = ((size_t)(b*Nn + n0 + nl))*Dm + d0 + dl;
        float xval = xs[nl + 24][dl];
        Tr[idx] = acc[j];
        S[idx]  = xval - acc[j];
    }
}

// ---------------- boundary decomposition (reflect pad), 48 rows per batch ----------------
__global__ __launch_bounds__(256) void decomp_edge_kernel(
    const float* __restrict__ x, const float* __restrict__ alpha,
    const float* __restrict__ w7, const float* __restrict__ w25,
    const float* __restrict__ w49, float* __restrict__ Tr, float* __restrict__ S)
{
    int bx = blockIdx.x;
    int n = (bx < 24) ? bx : (Nn - 48 + bx);
    int b = blockIdx.y;
    float a0 = alpha[0], a1 = alpha[1], a2 = alpha[2];
    float mx = fmaxf(a0, fmaxf(a1, a2));
    float e0 = __expf(a0-mx), e1 = __expf(a1-mx), e2 = __expf(a2-mx);
    float inv = 1.f/(e0+e1+e2);
    float wt0 = e0*inv, wt1 = e1*inv, wt2 = e2*inv;

    for (int d = threadIdx.x; d < Dm; d += 256) {
        float t7 = 0.f, t25 = 0.f, t49 = 0.f;
        #pragma unroll
        for (int j = 0; j < 7; j++) {
            int p = n + j - 3; p = p < 0 ? -p : (p >= Nn ? 2*Nn-2-p : p);
            t7 += w7[d*7+j] * x[((size_t)(b*Nn+p))*Dm + d];
        }
        #pragma unroll
        for (int j = 0; j < 25; j++) {
            int p = n + j - 12; p = p < 0 ? -p : (p >= Nn ? 2*Nn-2-p : p);
            t25 += w25[d*25+j] * x[((size_t)(b*Nn+p))*Dm + d];
        }
        #pragma unroll
        for (int j = 0; j < 49; j++) {
            int p = n + j - 24; p = p < 0 ? -p : (p >= Nn ? 2*Nn-2-p : p);
            t49 += w49[d*49+j] * x[((size_t)(b*Nn+p))*Dm + d];
        }
        float tr = wt0*t7 + wt1*t25 + wt2*t49;
        size_t idx = ((size_t)(b*Nn+n))*Dm + d;
        Tr[idx] = tr;
        S[idx]  = x[idx] - tr;
    }
}

// ---------------- one-pass LayerNorm (row in registers) ----------------
__global__ __launch_bounds__(256) void ln_kernel(
    const float* __restrict__ in, float* __restrict__ out,
    const float* __restrict__ g, const float* __restrict__ b)
{
    __shared__ float red[8];
    int t = blockIdx.x, tid = threadIdx.x;
    int lane = tid & 31, warp = tid >> 5;
    const float4* row4 = (const float4*)(in + (size_t)t*Dm);
    float4 v = row4[tid];
    float s = v.x + v.y + v.z + v.w;
    #pragma unroll
    for (int o = 16; o; o >>= 1) s += __shfl_xor_sync(0xffffffff, s, o);
    if (lane == 0) red[warp] = s;
    __syncthreads();
    float tot = 0.f;
    #pragma unroll
    for (int i = 0; i < 8; i++) tot += red[i];
    float m = tot * (1.f/Dm);
    float dx = v.x-m, dy = v.y-m, dz = v.z-m, dw = v.w-m;
    float s2 = dx*dx + dy*dy + dz*dz + dw*dw;
    #pragma unroll
    for (int o = 16; o; o >>= 1) s2 += __shfl_xor_sync(0xffffffff, s2, o);
    __syncthreads();
    if (lane == 0) red[warp] = s2;
    __syncthreads();
    float tot2 = 0.f;
    #pragma unroll
    for (int i = 0; i < 8; i++) tot2 += red[i];
    float rinv = rsqrtf(tot2*(1.f/Dm) + 1e-5f);
    float4 gv = ((const float4*)g)[tid];
    float4 bv = ((const float4*)b)[tid];
    float4 o4;
    o4.x = dx*rinv*gv.x + bv.x;
    o4.y = dy*rinv*gv.y + bv.y;
    o4.z = dz*rinv*gv.z + bv.z;
    o4.w = dw*rinv*gv.w + bv.w;
    ((float4*)(out + (size_t)t*Dm))[tid] = o4;
}

// ---------------- tf32 tensor-core GEMM NT, double-buffered packed smem ----------------
__device__ __forceinline__ float gelu_f(float v) {
    return 0.5f*v*(1.0f + erff(v*0.70710678118654752f));
}

template<int MODE>
__global__ __launch_bounds__(256, 2) void gemm_tc(
    const float* __restrict__ A, const float* __restrict__ W,
    const float* __restrict__ bias, const float* __restrict__ res,
    const int* __restrict__ cnt, const int* __restrict__ ridx,
    const float* __restrict__ wvec,
    float* __restrict__ C, int K, int O)
{
    __shared__ __align__(16) unsigned AsV[2*2112];
    __shared__ __align__(16) unsigned BsV[2*2112];
    int t0 = blockIdx.y*128, o0 = blockIdx.x*128;
    int tid = threadIdx.x;

    int cN = 1 << 30;
    if (MODE == 2 || MODE == 3) {
        cN = *cnt;
        if (t0 >= cN) return;
    }

    int lane = tid & 31, warp = tid >> 5;
    int warp_m = warp >> 2, warp_n = warp & 3;   // 2 x 4 warps
    int gid = lane >> 2, tig = lane & 3;

    float acc[4][4][4];
    #pragma unroll
    for (int im = 0; im < 4; im++)
        #pragma unroll
        for (int in = 0; in < 4; in++)
            #pragma unroll
            for (int q = 0; q < 4; q++) acc[im][in][q] = 0.f;

    int lr = tid >> 1;            // row 0..127
    int hb = tid & 1;             // k-half 0/1
    int lc = hb*8;
    const float* Ap = A + (size_t)(t0+lr)*K + lc;
    const float* Bp = W + (size_t)(o0+lr)*K + lc;

    int grpA = ((lr >> 4) << 3) + (lr & 7);
    int pmA  = (lr >> 3) & 1;

    float4 pa0 = *(const float4*)(Ap);
    float4 pa1 = *(const float4*)(Ap+4);
    float4 pb0 = *(const float4*)(Bp);
    float4 pb1 = *(const float4*)(Bp+4);

    // pack tile 0 into buffer 0
    {
        float av[8] = {pa0.x,pa0.y,pa0.z,pa0.w,pa1.x,pa1.y,pa1.z,pa1.w};
        float bv[8] = {pb0.x,pb0.y,pb0.z,pb0.w,pb1.x,pb1.y,pb1.z,pb1.w};
        #pragma unroll
        for (int q2 = 0; q2 < 8; q2++) {
            int tq = q2 & 3, kk = q2 >> 2;
            AsV[((hb*4 + tq)*66 + grpA)*4 + pmA + 2*kk] = f2tf32(av[q2]);
            BsV[((hb*4 + tq)*132 + lr)*2 + kk]          = f2tf32(bv[q2]);
        }
    }
    __syncthreads();

    for (int kt = 0; kt < K; kt += 16) {
        int cur = (kt >> 4) & 1;
        bool more = (kt + 16 < K);
        if (more) {
            pa0 = *(const float4*)(Ap + kt + 16);
            pa1 = *(const float4*)(Ap + kt + 20);
            pb0 = *(const float4*)(Bp + kt + 16);
            pb1 = *(const float4*)(Bp + kt + 20);
        }
        // compute on buffer cur
        #pragma unroll
        for (int h2 = 0; h2 < 2; h2++) {
            unsigned af[4][4], bf[4][2];
            #pragma unroll
            for (int im = 0; im < 4; im++) {
                uint4 v = *(const uint4*)&AsV[cur*2112 + (((h2*4 + tig)*66) + (warp_m*4+im)*8 + gid)*4];
                af[im][0]=v.x; af[im][1]=v.y; af[im][2]=v.z; af[im][3]=v.w;
            }
            #pragma unroll
            for (int in = 0; in < 4; in++) {
                uint2 v = *(const uint2*)&BsV[cur*2112 + (((h2*4 + tig)*132) + warp_n*32 + in*8 + gid)*2];
                bf[in][0]=v.x; bf[in][1]=v.y;
            }
            #pragma unroll
            for (int im = 0; im < 4; im++)
                #pragma unroll
                for (int in = 0; in < 4; in++)
                    mma_tf32(acc[im][in], af[im], bf[in]);
        }
        // pack next tile into the other buffer
        if (more) {
            int nb = cur ^ 1;
            float av[8] = {pa0.x,pa0.y,pa0.z,pa0.w,pa1.x,pa1.y,pa1.z,pa1.w};
            float bv[8] = {pb0.x,pb0.y,pb0.z,pb0.w,pb1.x,pb1.y,pb1.z,pb1.w};
            #pragma unroll
            for (int q2 = 0; q2 < 8; q2++) {
                int tq = q2 & 3, kk = q2 >> 2;
                AsV[nb*2112 + ((hb*4 + tq)*66 + grpA)*4 + pmA + 2*kk] = f2tf32(av[q2]);
                BsV[nb*2112 + ((hb*4 + tq)*132 + lr)*2 + kk]          = f2tf32(bv[q2]);
            }
        }
        __syncthreads();
    }

    #pragma unroll
    for (int im = 0; im < 4; im++) {
        #pragma unroll
        for (int half = 0; half < 2; half++) {
            int row = t0 + warp_m*64 + im*16 + gid + half*8;
            if ((MODE == 2 || MODE == 3) && row >= cN) continue;
            float w = 0.f; int tgt = row;
            if (MODE == 3) { w = wvec[row]; tgt = ridx[row]; }
            #pragma unroll
            for (int in = 0; in < 4; in++) {
                int col = o0 + warp_n*32 + in*8 + 2*tig;
                float v0 = acc[im][in][half*2+0] + bias[col];
                float v1 = acc[im][in][half*2+1] + bias[col+1];
                size_t idx = (size_t)row*O + col;
                if (MODE == 0) { C[idx] = v0; C[idx+1] = v1; }
                else if (MODE == 1) { C[idx] = v0 + res[idx]; C[idx+1] = v1 + res[idx+1]; }
                else if (MODE == 2) { C[idx] = gelu_f(v0); C[idx+1] = gelu_f(v1); }
                else {
                    size_t oidx = (size_t)tgt*O + col;
                    C[oidx]   += w*v0;
                    C[oidx+1] += w*v1;
                }
            }
        }
    }
}

// ---------------- flash attention with tf32 MMA ----------------
#define ATN_SH_FLOATS (4*4352 + 320)

__global__ __launch_bounds__(256) void attn_mma_kernel(
    const float* __restrict__ Q, const float* __restrict__ K,
    const float* __restrict__ V, float* __restrict__ Y)
{
    extern __shared__ __align__(16) unsigned ash[];
    unsigned* QsV = ash;
    unsigned* KsV = ash + 4352;
    unsigned* PsV = ash + 2*4352;
    unsigned* VsV = ash + 3*4352;
    float* mrow = (float*)(ash + 4*4352);
    float* lrow = mrow + 64;
    float* rrow = lrow + 64;
    float* cred = rrow + 64;

    int bh = blockIdx.y;
    int b = bh >> 4, h = bh & 15;
    int q0 = blockIdx.x * 64;
    int tid = threadIdx.x;
    int warp = tid >> 5, lane = tid & 31;
    int gid = lane >> 2, tig = lane & 3;
    int warp_m = warp >> 1, warp_n = warp & 1;
    float slope = exp2f(-0.5f * (float)(h+1));

    for (int i = tid; i < 64*64; i += 256) {
        int d = i & 63, q = i >> 6;
        float v = Q[((size_t)(b*Nn + q0 + q))*Dm + h*64 + d];
        int b8 = d >> 3, t = d & 3, kk = (d >> 2) & 1;
        int grp = ((q >> 4) << 3) + (q & 7), comp = ((q >> 3) & 1) + 2*kk;
        QsV[((b8*4 + t)*34 + grp)*4 + comp] = f2tf32(v);
    }
    if (tid < 64) { mrow[tid] = -1e30f; lrow[tid] = 0.f; }

    float o_acc[4][4];
    #pragma unroll
    for (int in = 0; in < 4; in++)
        #pragma unroll
        for (int q = 0; q < 4; q++) o_acc[in][q] = 0.f;

    int qlo = warp_m*16 + gid, qhi = qlo + 8;
    int qglo = q0 + qlo, qghi = q0 + qhi;
    int grpP = warp_m*8 + gid;

    for (int kt = 0; kt < Nn; kt += 64) {
        __syncthreads();
        for (int i = tid; i < 64*64; i += 256) {
            int d = i & 63, j = i >> 6;
            float v = K[((size_t)(b*Nn + kt + j))*Dm + h*64 + d];
            int b8 = d >> 3, t = d & 3, kk = (d >> 2) & 1;
            KsV[((b8*4 + t)*68 + j)*2 + kk] = f2tf32(v);
        }
        for (int i = tid; i < 64*64; i += 256) {
            int d = i & 63, j = i >> 6;
            float v = V[((size_t)(b*Nn + kt + j))*Dm + h*64 + d];
            int b8 = j >> 3, t = j & 3, kk = (j >> 2) & 1;
            VsV[((b8*4 + t)*68 + d)*2 + kk] = f2tf32(v);
        }
        __syncthreads();

        float acc_s[4][4];
        #pragma unroll
        for (int in = 0; in < 4; in++)
            #pragma unroll
            for (int q = 0; q < 4; q++) acc_s[in][q] = 0.f;

        #pragma unroll
        for (int b8 = 0; b8 < 8; b8++) {
            uint4 afv = *(const uint4*)&QsV[((b8*4 + tig)*34 + grpP)*4];
            unsigned af[4] = {afv.x, afv.y, afv.z, afv.w};
            #pragma unroll
            for (int in = 0; in < 4; in++) {
                uint2 bfv = *(const uint2*)&KsV[((b8*4 + tig)*68 + warp_n*32 + in*8 + gid)*2];
                unsigned bf[2] = {bfv.x, bfv.y};
                mma_tf32(acc_s[in], af, bf);
            }
        }

        float rmax0 = -1e30f, rmax1 = -1e30f;
        #pragma unroll
        for (int in = 0; in < 4; in++) {
            #pragma unroll
            for (int c2 = 0; c2 < 2; c2++) {
                int kg = kt + warp_n*32 + in*8 + 2*tig + c2;
                float d0 = (kg > qglo) ? (float)(kg - qglo) : 0.f;
                float d1 = (kg > qghi) ? (float)(kg - qghi) : 0.f;
                acc_s[in][c2]   = acc_s[in][c2]  *0.125f - slope*d0;
                acc_s[in][c2+2] = acc_s[in][c2+2]*0.125f - slope*d1;
                rmax0 = fmaxf(rmax0, acc_s[in][c2]);
                rmax1 = fmaxf(rmax1, acc_s[in][c2+2]);
            }
        }
        rmax0 = fmaxf(rmax0, __shfl_xor_sync(0xffffffff, rmax0, 1));
        rmax0 = fmaxf(rmax0, __shfl_xor_sync(0xffffffff, rmax0, 2));
        rmax1 = fmaxf(rmax1, __shfl_xor_sync(0xffffffff, rmax1, 1));
        rmax1 = fmaxf(rmax1, __shfl_xor_sync(0xffffffff, rmax1, 2));
        if (tig == 0) {
            cred[warp_n*64 + qlo] = rmax0;
            cred[warp_n*64 + qhi] = rmax1;
        }
        __syncthreads();
        if (tid < 64) {
            float mo = mrow[tid];
            float mn = fmaxf(mo, fmaxf(cred[tid], cred[64+tid]));
            mrow[tid] = mn;
            rrow[tid] = __expf(mo - mn);
        }
        __syncthreads();

        float mn0 = mrow[qlo], mn1 = mrow[qhi];
        float r0 = rrow[qlo], r1 = rrow[qhi];
        float rs0 = 0.f, rs1 = 0.f;
        #pragma unroll
        for (int in = 0; in < 4; in++) {
            #pragma unroll
            for (int c2 = 0; c2 < 2; c2++) {
                float p0 = __expf(acc_s[in][c2]   - mn0);
                float p1 = __expf(acc_s[in][c2+2] - mn1);
                rs0 += p0; rs1 += p1;
                int kin = 2*tig + c2;
                int t = kin & 3, kk = kin >> 2;
                int b8k = warp_n*4 + in;
                PsV[((b8k*4 + t)*34 + grpP)*4 + 0 + 2*kk] = f2tf32(p0);
                PsV[((b8k*4 + t)*34 + grpP)*4 + 1 + 2*kk] = f2tf32(p1);
            }
        }
        rs0 += __shfl_xor_sync(0xffffffff, rs0, 1);
        rs0 += __shfl_xor_sync(0xffffffff, rs0, 2);
        rs1 += __shfl_xor_sync(0xffffffff, rs1, 1);
        rs1 += __shfl_xor_sync(0xffffffff, rs1, 2);
        if (tig == 0) {
            cred[warp_n*64 + qlo] = rs0;
            cred[warp_n*64 + qhi] = rs1;
        }
        #pragma unroll
        for (int in = 0; in < 4; in++) {
            o_acc[in][0] *= r0; o_acc[in][1] *= r0;
            o_acc[in][2] *= r1; o_acc[in][3] *= r1;
        }
        __syncthreads();
        if (tid < 64) lrow[tid] = lrow[tid]*rrow[tid] + cred[tid] + cred[64+tid];

        #pragma unroll
        for (int b8 = 0; b8 < 8; b8++) {
            uint4 afv = *(const uint4*)&PsV[((b8*4 + tig)*34 + grpP)*4];
            unsigned af[4] = {afv.x, afv.y, afv.z, afv.w};
            #pragma unroll
            for (int in = 0; in < 4; in++) {
                uint2 bfv = *(const uint2*)&VsV[((b8*4 + tig)*68 + warp_n*32 + in*8 + gid)*2];
                unsigned bf[2] = {bfv.x, bfv.y};
                mma_tf32(o_acc[in], af, bf);
            }
        }
    }
    __syncthreads();

    float inv0 = 1.f / lrow[qlo];
    float inv1 = 1.f / lrow[qhi];
    #pragma unroll
    for (int in = 0; in < 4; in++) {
        int col = h*64 + warp_n*32 + in*8 + 2*tig;
        float2 v0 = make_float2(o_acc[in][0]*inv0, o_acc[in][1]*inv0);
        float2 v1 = make_float2(o_acc[in][2]*inv1, o_acc[in][3]*inv1);
        *(float2*)&Y[((size_t)(b*Nn + qglo))*Dm + col] = v0;
        *(float2*)&Y[((size_t)(b*Nn + qghi))*Dm + col] = v1;
    }
}

// ---------------- router ----------------
__global__ __launch_bounds__(128) void router_kernel(
    const float* __restrict__ xf, const float* __restrict__ rw,
    float* __restrict__ Wout, float* __restrict__ Aux)
{
    int t = blockIdx.x;
    int warp = threadIdx.x >> 5, lane = threadIdx.x & 31;
    __shared__ float sg[NE];
    const float* xrow = xf + (size_t)t*Dm;
    float s = 0.f;
    for (int i = lane; i < Dm; i += 32) s += xrow[i]*rw[(size_t)warp*Dm + i];
    #pragma unroll
    for (int o = 16; o; o >>= 1) s += __shfl_xor_sync(0xffffffff, s, o);
    if (lane == 0) sg[warp] = s;
    __syncthreads();
    if (threadIdx.x == 0) {
        float m = fmaxf(fmaxf(sg[0],sg[1]), fmaxf(sg[2],sg[3]));
        float e[NE], sum = 0.f;
        #pragma unroll
        for (int i = 0; i < NE; i++) { e[i] = __expf(sg[i]-m); sum += e[i]; }
        float gate[NE];
        #pragma unroll
        for (int i = 0; i < NE; i++) gate[i] = e[i]/sum;
        int i0 = 0;
        #pragma unroll
        for (int i = 1; i < NE; i++) if (gate[i] > gate[i0]) i0 = i;
        int i1 = -1;
        #pragma unroll
        for (int i = 0; i < NE; i++) if (i != i0 && (i1 < 0 || gate[i] > gate[i1])) i1 = i;
        float s2 = fmaxf(gate[i0] + gate[i1], 1e-9f);
        #pragma unroll
        for (int i = 0; i < NE; i++) Wout[(size_t)t*NE + i] = 0.f;
        Wout[(size_t)t*NE + i0] = gate[i0]/s2;
        Wout[(size_t)t*NE + i1] = gate[i1]/s2;
        #pragma unroll
        for (int i = 0; i < NE; i++) atomicAdd(&Aux[i], gate[i]);
        atomicAdd(&Aux[NE + i0], 1.f);
        atomicAdd(&Aux[NE + i1], 1.f);
    }
}

// ---------------- MoE assignment / gather ----------------
__global__ __launch_bounds__(256) void assign_kernel(
    const float* __restrict__ Wt, int* __restrict__ cnt,
    int* __restrict__ eidx, float* __restrict__ ewt)
{
    int t = blockIdx.x*256 + threadIdx.x;
    if (t >= TT) return;
    #pragma unroll
    for (int e = 0; e < NE; e++) {
        float w = Wt[(size_t)t*NE + e];
        if (w != 0.f) {
            int pos = atomicAdd(&cnt[e], 1);
            eidx[e*TT + pos] = t;
            ewt [e*TT + pos] = w;
        }
    }
}

__global__ __launch_bounds__(256) void gather_kernel(
    const float* __restrict__ xf, const int* __restrict__ cnt,
    const int* __restrict__ eidx, float* __restrict__ Xe)
{
    int e = blockIdx.y, row = blockIdx.x;
    int c = cnt[e];
    float4* dst = (float4*)(Xe + ((size_t)e*TT + row)*Dm);
    if (row < c) {
        const float4* src = (const float4*)(xf + (size_t)eidx[e*TT + row]*Dm);
        dst[threadIdx.x] = src[threadIdx.x];
    } else if (row < ((c + 127) & ~127)) {
        dst[threadIdx.x] = make_float4(0.f,0.f,0.f,0.f);
    }
}

// ---------------- final ----------------
__global__ __launch_bounds__(256) void final_kernel(
    const float* __restrict__ tw, const float* __restrict__ tb,
    const float* __restrict__ Tr, const float* __restrict__ XS,
    float* __restrict__ out)
{
    int n = blockIdx.x, b = blockIdx.y;
    for (int d = threadIdx.x; d < Dm; d += 256) {
        float acc = tb[d];
        #pragma unroll
        for (int j = 0; j < 5; j++) {
            int p = n + j - 2;
            if (p >= 0 && p < Nn) acc += tw[d*5+j] * Tr[((size_t)(b*Nn+p))*Dm + d];
        }
        size_t idx = ((size_t)(b*Nn+n))*Dm + d;
        out[idx] = XS[idx] + acc;
    }
}

__global__ void zero_aux_kernel(float* Aux, int* cnt) {
    if (threadIdx.x < 2*NE) Aux[threadIdx.x] = 0.f;
    if (threadIdx.x < NE) cnt[threadIdx.x] = 0;
}

__global__ void aux_write_kernel(const float* Aux, float* out, int out_size) {
    if (out_size > TT*Dm) {
        float a = 0.f;
        #pragma unroll
        for (int e = 0; e < NE; e++)
            a += (Aux[e]/(float)TT) * (Aux[NE+e]/(float)TT);
        out[TT*Dm] = (float)NE * a;
    }
}

// ---------------- launcher ----------------
extern "C" void kernel_launch(void* const* d_in, const int* in_sizes, int n_in,
                              void* d_out, int out_size)
{
    const float* x    = (const float*)d_in[0];
    const float* qw   = (const float*)d_in[1];
    const float* qb   = (const float*)d_in[2];
    const float* kw   = (const float*)d_in[3];
    const float* kb   = (const float*)d_in[4];
    const float* vw   = (const float*)d_in[5];
    const float* vb   = (const float*)d_in[6];
    const float* ow   = (const float*)d_in[7];
    const float* ob   = (const float*)d_in[8];
    const float* n1g  = (const float*)d_in[9];
    const float* n1b  = (const float*)d_in[10];
    const float* n2g  = (const float*)d_in[11];
    const float* n2b  = (const float*)d_in[12];
    const float* alpha= (const float*)d_in[13];
    const float* dw7  = (const float*)d_in[14];
    const float* dw25 = (const float*)d_in[15];
    const float* dw49 = (const float*)d_in[16];
    const float* rw   = (const float*)d_in[17];
    const float* ew1  = (const float*)d_in[18];
    const float* eb1  = (const float*)d_in[19];
    const float* ew2  = (const float*)d_in[20];
    const float* eb2  = (const float*)d_in[21];
    const float* tw   = (const float*)d_in[22];
    const float* tb   = (const float*)d_in[23];
    float* out = (float*)d_out;

    float *Tr,*S,*Sn,*Qb,*Kb,*Vb,*Yb,*XS,*Hb,*Wt,*Xe,*Ewt,*Aux,*Ck;
    int *Eidx,*Cnt;
    cudaGetSymbolAddress((void**)&Tr,  g_Tr);
    cudaGetSymbolAddress((void**)&S,   g_S);
    cudaGetSymbolAddress((void**)&Sn,  g_Sn);
    cudaGetSymbolAddress((void**)&Qb,  g_Q);
    cudaGetSymbolAddress((void**)&Kb,  g_K);
    cudaGetSymbolAddress((void**)&Vb,  g_V);
    cudaGetSymbolAddress((void**)&Yb,  g_Y);
    cudaGetSymbolAddress((void**)&XS,  g_XS);
    cudaGetSymbolAddress((void**)&Hb,  g_H);
    cudaGetSymbolAddress((void**)&Wt,  g_W);
    cudaGetSymbolAddress((void**)&Xe,  g_Xe);
    cudaGetSymbolAddress((void**)&Ewt, g_Ewt);
    cudaGetSymbolAddress((void**)&Aux, g_Aux);
    cudaGetSymbolAddress((void**)&Ck,  g_Ck);
    cudaGetSymbolAddress((void**)&Eidx,g_Eidx);
    cudaGetSymbolAddress((void**)&Cnt, g_Cnt);

    const int ATN_SH_BYTES = ATN_SH_FLOATS * 4;
    cudaFuncSetAttribute(attn_mma_kernel, cudaFuncAttributeMaxDynamicSharedMemorySize, ATN_SH_BYTES);

    zero_aux_kernel<<<1, 32>>>(Aux, Cnt);
    ckbuild_kernel<<<Dm, 64>>>(alpha, dw7, dw25, dw49, Ck);
    trend_kernel<<<dim3(61, Bz, Dm/128), 256>>>(x, Ck, Tr, S);
    decomp_edge_kernel<<<dim3(48, Bz), 256>>>(x, alpha, dw7, dw25, dw49, Tr, S);
    ln_kernel<<<TT, 256>>>(S, Sn, n1g, n1b);

    gemm_tc<0><<<dim3(Dm/128, TT/128), 256>>>(Sn, qw, qb, nullptr, nullptr, nullptr, nullptr, Qb, Dm, Dm);
    gemm_tc<0><<<dim3(Dm/128, TT/128), 256>>>(Sn, kw, kb, nullptr, nullptr, nullptr, nullptr, Kb, Dm, Dm);
    gemm_tc<0><<<dim3(Dm/128, TT/128), 256>>>(Sn, vw, vb, nullptr, nullptr, nullptr, nullptr, Vb, Dm, Dm);

    attn_mma_kernel<<<dim3(Nn/64, Bz*Hh), 256, ATN_SH_BYTES>>>(Qb, Kb, Vb, Yb);

    gemm_tc<1><<<dim3(Dm/128, TT/128), 256>>>(Yb, ow, ob, S, nullptr, nullptr, nullptr, XS, Dm, Dm);
    ln_kernel<<<TT, 256>>>(XS, Sn, n2g, n2b);
    router_kernel<<<TT, 128>>>(Sn, rw, Wt, Aux);
    assign_kernel<<<TT/256, 256>>>(Wt, Cnt, Eidx, Ewt);
    gather_kernel<<<dim3(TT, NE), 256>>>(Sn, Cnt, Eidx, Xe);

    for (int e = 0; e < NE; e++) {
        gemm_tc<2><<<dim3(MH/128, TT/128), 256>>>(
            Xe + (size_t)e*TT*Dm, ew1 + (size_t)e*MH*Dm, eb1 + (size_t)e*MH,
            nullptr, Cnt + e, nullptr, nullptr, Hb, Dm, MH);
        gemm_tc<3><<<dim3(Dm/128, TT/128), 256>>>(
            Hb, ew2 + (size_t)e*Dm*MH, eb2 + (size_t)e*Dm,
            nullptr, Cnt + e, Eidx + e*TT, Ewt + e*TT, XS, MH, Dm);
    }

    final_kernel<<<dim3(Nn, Bz), 256>>>(tw, tb, Tr, XS, out);
    aux_write_kernel<<<1, 1>>>(Aux, out, out_size);
}

// round 8
// speedup vs baseline: 4.9820x; 1.0949x over previous
#include <cuda_runtime.h>
#include <math.h>
#include <stdint.h>

#define Bz 8
#define Nn 1024
#define Dm 1024
#define Hh 16
#define HD 64
#define TT (Bz*Nn)       // 8192 tokens
#define MH 2048
#define NE 4

// ---------------- static device scratch (no allocation allowed) ----------------
__device__ float g_Tr[(size_t)TT*Dm];
__device__ float g_S [(size_t)TT*Dm];
__device__ float g_Sn[(size_t)TT*Dm];
__device__ float g_Q [(size_t)TT*Dm];
__device__ float g_K [(size_t)TT*Dm];
__device__ float g_V [(size_t)TT*Dm];
__device__ float g_Y [(size_t)TT*Dm];
__device__ float g_XS[(size_t)TT*Dm];
__device__ float g_H [(size_t)NE*TT*MH];    // per-expert hidden
__device__ float g_Oe[(size_t)NE*TT*Dm];    // per-expert weighted output (compact rows)
__device__ float g_W [(size_t)TT*NE];
__device__ float g_Xe[(size_t)NE*TT*Dm];
__device__ float g_Ck[(size_t)Dm*49];
__device__ int   g_Eidx[NE*TT];
__device__ float g_Ewt [NE*TT];
__device__ int   g_Tinv[TT*2];              // token -> (e*TT + pos) x2
__device__ int   g_Cnt[NE];
__device__ float g_Aux[2*NE];

// ---------------- tf32 helpers ----------------
__device__ __forceinline__ unsigned f2tf32(float x) {
    unsigned r; asm("cvt.rna.tf32.f32 %0, %1;" : "=r"(r) : "f"(x)); return r;
}
__device__ __forceinline__ void mma_tf32(float* c, const unsigned* a, const unsigned* b) {
    asm volatile(
        "mma.sync.aligned.m16n8k8.row.col.f32.tf32.tf32.f32 "
        "{%0,%1,%2,%3}, {%4,%5,%6,%7}, {%8,%9}, {%0,%1,%2,%3};\n"
        : "+f"(c[0]), "+f"(c[1]), "+f"(c[2]), "+f"(c[3])
        : "r"(a[0]), "r"(a[1]), "r"(a[2]), "r"(a[3]), "r"(b[0]), "r"(b[1]));
}

__device__ __forceinline__ float gelu_f(float v) {
    return 0.5f*v*(1.0f + erff(v*0.70710678118654752f));
}

// ---------------- combined decomposition kernel build ----------------
__global__ void ckbuild_kernel(
    const float* __restrict__ alpha, const float* __restrict__ w7,
    const float* __restrict__ w25, const float* __restrict__ w49,
    float* __restrict__ ck)
{
    int d = blockIdx.x, j = threadIdx.x;
    if (j >= 49) return;
    float a0 = alpha[0], a1 = alpha[1], a2 = alpha[2];
    float mx = fmaxf(a0, fmaxf(a1, a2));
    float e0 = __expf(a0-mx), e1 = __expf(a1-mx), e2 = __expf(a2-mx);
    float inv = 1.f/(e0+e1+e2);
    float wt0 = e0*inv, wt1 = e1*inv, wt2 = e2*inv;
    float v = wt2 * w49[d*49 + j];
    if (j >= 12 && j < 37) v += wt1 * w25[d*25 + (j-12)];
    if (j >= 21 && j < 28) v += wt0 * w7[d*7 + (j-21)];
    ck[d*49 + j] = v;
}

// ---------------- interior trend: combined 49-tap conv, smem window ----------------
__global__ __launch_bounds__(256) void trend_kernel(
    const float* __restrict__ x, const float* __restrict__ ck,
    float* __restrict__ Tr, float* __restrict__ S)
{
    __shared__ float xs[64][128];
    int b = blockIdx.y;
    int n0 = 24 + blockIdx.x * 16;
    int d0 = blockIdx.z * 128;
    int tid = threadIdx.x;
    int dl = tid & 127, ng = tid >> 7;

    for (int i = tid; i < 64*32; i += 256) {
        int p = i >> 5, c = i & 31;
        *(float4*)&xs[p][c*4] =
            *(const float4*)&x[((size_t)(b*Nn + n0 - 24 + p))*Dm + d0 + c*4];
    }
    __syncthreads();

    float ckr[49];
    #pragma unroll
    for (int j = 0; j < 49; j++) ckr[j] = __ldg(&ck[(size_t)(d0+dl)*49 + j]);

    float acc[8];
    #pragma unroll
    for (int j = 0; j < 8; j++) acc[j] = 0.f;

    #pragma unroll
    for (int pr = 0; pr < 56; pr++) {
        float xv = xs[ng*8 + pr][dl];
        #pragma unroll
        for (int j = 0; j < 8; j++) {
            int t = pr - j;
            if (t >= 0 && t < 49) acc[j] += ckr[t] * xv;
        }
    }

    #pragma unroll
    for (int j = 0; j < 8; j++) {
        int nl = ng*8 + j;
        size_t idx = ((size_t)(b*Nn + n0 + nl))*Dm + d0 + dl;
        float xval = xs[nl + 24][dl];
        Tr[idx] = acc[j];
        S[idx]  = xval - acc[j];
    }
}

// ---------------- boundary decomposition (reflect pad) ----------------
__global__ __launch_bounds__(256) void decomp_edge_kernel(
    const float* __restrict__ x, const float* __restrict__ alpha,
    const float* __restrict__ w7, const float* __restrict__ w25,
    const float* __restrict__ w49, float* __restrict__ Tr, float* __restrict__ S)
{
    int bx = blockIdx.x;
    int n = (bx < 24) ? bx : (Nn - 48 + bx);
    int b = blockIdx.y;
    float a0 = alpha[0], a1 = alpha[1], a2 = alpha[2];
    float mx = fmaxf(a0, fmaxf(a1, a2));
    float e0 = __expf(a0-mx), e1 = __expf(a1-mx), e2 = __expf(a2-mx);
    float inv = 1.f/(e0+e1+e2);
    float wt0 = e0*inv, wt1 = e1*inv, wt2 = e2*inv;

    for (int d = threadIdx.x; d < Dm; d += 256) {
        float t7 = 0.f, t25 = 0.f, t49 = 0.f;
        #pragma unroll
        for (int j = 0; j < 7; j++) {
            int p = n + j - 3; p = p < 0 ? -p : (p >= Nn ? 2*Nn-2-p : p);
            t7 += w7[d*7+j] * x[((size_t)(b*Nn+p))*Dm + d];
        }
        #pragma unroll
        for (int j = 0; j < 25; j++) {
            int p = n + j - 12; p = p < 0 ? -p : (p >= Nn ? 2*Nn-2-p : p);
            t25 += w25[d*25+j] * x[((size_t)(b*Nn+p))*Dm + d];
        }
        #pragma unroll
        for (int j = 0; j < 49; j++) {
            int p = n + j - 24; p = p < 0 ? -p : (p >= Nn ? 2*Nn-2-p : p);
            t49 += w49[d*49+j] * x[((size_t)(b*Nn+p))*Dm + d];
        }
        float tr = wt0*t7 + wt1*t25 + wt2*t49;
        size_t idx = ((size_t)(b*Nn+n))*Dm + d;
        Tr[idx] = tr;
        S[idx]  = x[idx] - tr;
    }
}

// ---------------- one-pass LayerNorm ----------------
__global__ __launch_bounds__(256) void ln_kernel(
    const float* __restrict__ in, float* __restrict__ out,
    const float* __restrict__ g, const float* __restrict__ b)
{
    __shared__ float red[8];
    int t = blockIdx.x, tid = threadIdx.x;
    int lane = tid & 31, warp = tid >> 5;
    const float4* row4 = (const float4*)(in + (size_t)t*Dm);
    float4 v = row4[tid];
    float s = v.x + v.y + v.z + v.w;
    #pragma unroll
    for (int o = 16; o; o >>= 1) s += __shfl_xor_sync(0xffffffff, s, o);
    if (lane == 0) red[warp] = s;
    __syncthreads();
    float tot = 0.f;
    #pragma unroll
    for (int i = 0; i < 8; i++) tot += red[i];
    float m = tot * (1.f/Dm);
    float dx = v.x-m, dy = v.y-m, dz = v.z-m, dw = v.w-m;
    float s2 = dx*dx + dy*dy + dz*dz + dw*dw;
    #pragma unroll
    for (int o = 16; o; o >>= 1) s2 += __shfl_xor_sync(0xffffffff, s2, o);
    __syncthreads();
    if (lane == 0) red[warp] = s2;
    __syncthreads();
    float tot2 = 0.f;
    #pragma unroll
    for (int i = 0; i < 8; i++) tot2 += red[i];
    float rinv = rsqrtf(tot2*(1.f/Dm) + 1e-5f);
    float4 gv = ((const float4*)g)[tid];
    float4 bv = ((const float4*)b)[tid];
    float4 o4;
    o4.x = dx*rinv*gv.x + bv.x;
    o4.y = dy*rinv*gv.y + bv.y;
    o4.z = dz*rinv*gv.z + bv.z;
    o4.w = dw*rinv*gv.w + bv.w;
    ((float4*)(out + (size_t)t*Dm))[tid] = o4;
}

// ---------------- tf32 tensor-core GEMM core (double-buffered packed smem) ----------------
// MODE 0: C = dot+bias ; MODE 1: += res ; MODE 2: gelu (rows<cN) ; MODE 3: C = w*(dot+bias) (rows<cN)
template<int MODE>
__device__ __forceinline__ void gemm_core(
    const float* __restrict__ A, const float* __restrict__ W,
    const float* __restrict__ bias, const float* __restrict__ res,
    const float* __restrict__ wvec,
    float* __restrict__ C, int K, int O, int t0, int o0, int cN)
{
    __shared__ __align__(16) unsigned AsV[2*2112];
    __shared__ __align__(16) unsigned BsV[2*2112];
    int tid = threadIdx.x;
    int lane = tid & 31, warp = tid >> 5;
    int warp_m = warp >> 2, warp_n = warp & 3;   // 2 x 4 warps
    int gid = lane >> 2, tig = lane & 3;

    float acc[4][4][4];
    #pragma unroll
    for (int im = 0; im < 4; im++)
        #pragma unroll
        for (int in = 0; in < 4; in++)
            #pragma unroll
            for (int q = 0; q < 4; q++) acc[im][in][q] = 0.f;

    int lr = tid >> 1;            // row 0..127
    int hb = tid & 1;             // k-half 0/1
    int lc = hb*8;
    const float* Ap = A + (size_t)(t0+lr)*K + lc;
    const float* Bp = W + (size_t)(o0+lr)*K + lc;

    int grpA = ((lr >> 4) << 3) + (lr & 7);
    int pmA  = (lr >> 3) & 1;

    float4 pa0 = *(const float4*)(Ap);
    float4 pa1 = *(const float4*)(Ap+4);
    float4 pb0 = *(const float4*)(Bp);
    float4 pb1 = *(const float4*)(Bp+4);

    // pack tile 0 into buffer 0
    {
        float av[8] = {pa0.x,pa0.y,pa0.z,pa0.w,pa1.x,pa1.y,pa1.z,pa1.w};
        float bv[8] = {pb0.x,pb0.y,pb0.z,pb0.w,pb1.x,pb1.y,pb1.z,pb1.w};
        #pragma unroll
        for (int q2 = 0; q2 < 8; q2++) {
            int tq = q2 & 3, kk = q2 >> 2;
            AsV[((hb*4 + tq)*66 + grpA)*4 + pmA + 2*kk] = f2tf32(av[q2]);
            BsV[((hb*4 + tq)*132 + lr)*2 + kk]          = f2tf32(bv[q2]);
        }
    }
    __syncthreads();

    for (int kt = 0; kt < K; kt += 16) {
        int cur = (kt >> 4) & 1;
        bool more = (kt + 16 < K);
        if (more) {
            pa0 = *(const float4*)(Ap + kt + 16);
            pa1 = *(const float4*)(Ap + kt + 20);
            pb0 = *(const float4*)(Bp + kt + 16);
            pb1 = *(const float4*)(Bp + kt + 20);
        }
        #pragma unroll
        for (int h2 = 0; h2 < 2; h2++) {
            unsigned af[4][4], bf[4][2];
            #pragma unroll
            for (int im = 0; im < 4; im++) {
                uint4 v = *(const uint4*)&AsV[cur*2112 + (((h2*4 + tig)*66) + (warp_m*4+im)*8 + gid)*4];
                af[im][0]=v.x; af[im][1]=v.y; af[im][2]=v.z; af[im][3]=v.w;
            }
            #pragma unroll
            for (int in = 0; in < 4; in++) {
                uint2 v = *(const uint2*)&BsV[cur*2112 + (((h2*4 + tig)*132) + warp_n*32 + in*8 + gid)*2];
                bf[in][0]=v.x; bf[in][1]=v.y;
            }
            #pragma unroll
            for (int im = 0; im < 4; im++)
                #pragma unroll
                for (int in = 0; in < 4; in++)
                    mma_tf32(acc[im][in], af[im], bf[in]);
        }
        if (more) {
            int nb = cur ^ 1;
            float av[8] = {pa0.x,pa0.y,pa0.z,pa0.w,pa1.x,pa1.y,pa1.z,pa1.w};
            float bv[8] = {pb0.x,pb0.y,pb0.z,pb0.w,pb1.x,pb1.y,pb1.z,pb1.w};
            #pragma unroll
            for (int q2 = 0; q2 < 8; q2++) {
                int tq = q2 & 3, kk = q2 >> 2;
                AsV[nb*2112 + ((hb*4 + tq)*66 + grpA)*4 + pmA + 2*kk] = f2tf32(av[q2]);
                BsV[nb*2112 + ((hb*4 + tq)*132 + lr)*2 + kk]          = f2tf32(bv[q2]);
            }
        }
        __syncthreads();
    }

    #pragma unroll
    for (int im = 0; im < 4; im++) {
        #pragma unroll
        for (int half = 0; half < 2; half++) {
            int row = t0 + warp_m*64 + im*16 + gid + half*8;
            if ((MODE == 2 || MODE == 3) && row >= cN) continue;
            float w = 0.f;
            if (MODE == 3) w = wvec[row];
            #pragma unroll
            for (int in = 0; in < 4; in++) {
                int col = o0 + warp_n*32 + in*8 + 2*tig;
                float v0 = acc[im][in][half*2+0] + bias[col];
                float v1 = acc[im][in][half*2+1] + bias[col+1];
                size_t idx = (size_t)row*O + col;
                if (MODE == 0) { C[idx] = v0; C[idx+1] = v1; }
                else if (MODE == 1) { C[idx] = v0 + res[idx]; C[idx+1] = v1 + res[idx+1]; }
                else if (MODE == 2) { C[idx] = gelu_f(v0); C[idx+1] = gelu_f(v1); }
                else { C[idx] = w*v0; C[idx+1] = w*v1; }
            }
        }
    }
}

// ---- wrappers ----
__global__ __launch_bounds__(256, 2) void gemm_qkv(
    const float* __restrict__ A,
    const float* __restrict__ w0, const float* __restrict__ w1, const float* __restrict__ w2,
    const float* __restrict__ b0, const float* __restrict__ b1, const float* __restrict__ b2,
    float* __restrict__ c0, float* __restrict__ c1, float* __restrict__ c2)
{
    int z = blockIdx.z;
    const float* W = (z == 0) ? w0 : (z == 1) ? w1 : w2;
    const float* B = (z == 0) ? b0 : (z == 1) ? b1 : b2;
    float* C = (z == 0) ? c0 : (z == 1) ? c1 : c2;
    gemm_core<0>(A, W, B, nullptr, nullptr, C, Dm, Dm,
                 blockIdx.y*128, blockIdx.x*128, 1 << 30);
}

__global__ __launch_bounds__(256, 2) void gemm_res(
    const float* __restrict__ A, const float* __restrict__ W,
    const float* __restrict__ bias, const float* __restrict__ res,
    float* __restrict__ C)
{
    gemm_core<1>(A, W, bias, res, nullptr, C, Dm, Dm,
                 blockIdx.y*128, blockIdx.x*128, 1 << 30);
}

__global__ __launch_bounds__(256, 2) void gemm_moe_up(
    const float* __restrict__ Xe, const float* __restrict__ ew1,
    const float* __restrict__ eb1, const int* __restrict__ cnt,
    float* __restrict__ Hb)
{
    int e = blockIdx.z;
    int cN = cnt[e];
    int t0 = blockIdx.y*128;
    if (t0 >= cN) return;
    gemm_core<2>(Xe + (size_t)e*TT*Dm, ew1 + (size_t)e*MH*Dm, eb1 + (size_t)e*MH,
                 nullptr, nullptr, Hb + (size_t)e*TT*MH, Dm, MH,
                 t0, blockIdx.x*128, cN);
}

__global__ __launch_bounds__(256, 2) void gemm_moe_dn(
    const float* __restrict__ Hb, const float* __restrict__ ew2,
    const float* __restrict__ eb2, const int* __restrict__ cnt,
    const float* __restrict__ ewt, float* __restrict__ Oe)
{
    int e = blockIdx.z;
    int cN = cnt[e];
    int t0 = blockIdx.y*128;
    if (t0 >= cN) return;
    gemm_core<3>(Hb + (size_t)e*TT*MH, ew2 + (size_t)e*Dm*MH, eb2 + (size_t)e*Dm,
                 nullptr, ewt + (size_t)e*TT, Oe + (size_t)e*TT*Dm, MH, Dm,
                 t0, blockIdx.x*128, cN);
}

// ---------------- flash attention with tf32 MMA ----------------
#define ATN_SH_FLOATS (4*4352 + 320)

__global__ __launch_bounds__(256) void attn_mma_kernel(
    const float* __restrict__ Q, const float* __restrict__ K,
    const float* __restrict__ V, float* __restrict__ Y)
{
    extern __shared__ __align__(16) unsigned ash[];
    unsigned* QsV = ash;
    unsigned* KsV = ash + 4352;
    unsigned* PsV = ash + 2*4352;
    unsigned* VsV = ash + 3*4352;
    float* mrow = (float*)(ash + 4*4352);
    float* lrow = mrow + 64;
    float* rrow = lrow + 64;
    float* cred = rrow + 64;

    int bh = blockIdx.y;
    int b = bh >> 4, h = bh & 15;
    int q0 = blockIdx.x * 64;
    int tid = threadIdx.x;
    int warp = tid >> 5, lane = tid & 31;
    int gid = lane >> 2, tig = lane & 3;
    int warp_m = warp >> 1, warp_n = warp & 1;
    float slope = exp2f(-0.5f * (float)(h+1));

    for (int i = tid; i < 64*64; i += 256) {
        int d = i & 63, q = i >> 6;
        float v = Q[((size_t)(b*Nn + q0 + q))*Dm + h*64 + d];
        int b8 = d >> 3, t = d & 3, kk = (d >> 2) & 1;
        int grp = ((q >> 4) << 3) + (q & 7), comp = ((q >> 3) & 1) + 2*kk;
        QsV[((b8*4 + t)*34 + grp)*4 + comp] = f2tf32(v);
    }
    if (tid < 64) { mrow[tid] = -1e30f; lrow[tid] = 0.f; }

    float o_acc[4][4];
    #pragma unroll
    for (int in = 0; in < 4; in++)
        #pragma unroll
        for (int q = 0; q < 4; q++) o_acc[in][q] = 0.f;

    int qlo = warp_m*16 + gid, qhi = qlo + 8;
    int qglo = q0 + qlo, qghi = q0 + qhi;
    int grpP = warp_m*8 + gid;

    for (int kt = 0; kt < Nn; kt += 64) {
        __syncthreads();
        for (int i = tid; i < 64*64; i += 256) {
            int d = i & 63, j = i >> 6;
            float v = K[((size_t)(b*Nn + kt + j))*Dm + h*64 + d];
            int b8 = d >> 3, t = d & 3, kk = (d >> 2) & 1;
            KsV[((b8*4 + t)*68 + j)*2 + kk] = f2tf32(v);
        }
        for (int i = tid; i < 64*64; i += 256) {
            int d = i & 63, j = i >> 6;
            float v = V[((size_t)(b*Nn + kt + j))*Dm + h*64 + d];
            int b8 = j >> 3, t = j & 3, kk = (j >> 2) & 1;
            VsV[((b8*4 + t)*68 + d)*2 + kk] = f2tf32(v);
        }
        __syncthreads();

        float acc_s[4][4];
        #pragma unroll
        for (int in = 0; in < 4; in++)
            #pragma unroll
            for (int q = 0; q < 4; q++) acc_s[in][q] = 0.f;

        #pragma unroll
        for (int b8 = 0; b8 < 8; b8++) {
            uint4 afv = *(const uint4*)&QsV[((b8*4 + tig)*34 + grpP)*4];
            unsigned af[4] = {afv.x, afv.y, afv.z, afv.w};
            #pragma unroll
            for (int in = 0; in < 4; in++) {
                uint2 bfv = *(const uint2*)&KsV[((b8*4 + tig)*68 + warp_n*32 + in*8 + gid)*2];
                unsigned bf[2] = {bfv.x, bfv.y};
                mma_tf32(acc_s[in], af, bf);
            }
        }

        float rmax0 = -1e30f, rmax1 = -1e30f;
        #pragma unroll
        for (int in = 0; in < 4; in++) {
            #pragma unroll
            for (int c2 = 0; c2 < 2; c2++) {
                int kg = kt + warp_n*32 + in*8 + 2*tig + c2;
                float d0 = (kg > qglo) ? (float)(kg - qglo) : 0.f;
                float d1 = (kg > qghi) ? (float)(kg - qghi) : 0.f;
                acc_s[in][c2]   = acc_s[in][c2]  *0.125f - slope*d0;
                acc_s[in][c2+2] = acc_s[in][c2+2]*0.125f - slope*d1;
                rmax0 = fmaxf(rmax0, acc_s[in][c2]);
                rmax1 = fmaxf(rmax1, acc_s[in][c2+2]);
            }
        }
        rmax0 = fmaxf(rmax0, __shfl_xor_sync(0xffffffff, rmax0, 1));
        rmax0 = fmaxf(rmax0, __shfl_xor_sync(0xffffffff, rmax0, 2));
        rmax1 = fmaxf(rmax1, __shfl_xor_sync(0xffffffff, rmax1, 1));
        rmax1 = fmaxf(rmax1, __shfl_xor_sync(0xffffffff, rmax1, 2));
        if (tig == 0) {
            cred[warp_n*64 + qlo] = rmax0;
            cred[warp_n*64 + qhi] = rmax1;
        }
        __syncthreads();
        if (tid < 64) {
            float mo = mrow[tid];
            float mn = fmaxf(mo, fmaxf(cred[tid], cred[64+tid]));
            mrow[tid] = mn;
            rrow[tid] = __expf(mo - mn);
        }
        __syncthreads();

        float mn0 = mrow[qlo], mn1 = mrow[qhi];
        float r0 = rrow[qlo], r1 = rrow[qhi];
        float rs0 = 0.f, rs1 = 0.f;
        #pragma unroll
        for (int in = 0; in < 4; in++) {
            #pragma unroll
            for (int c2 = 0; c2 < 2; c2++) {
                float p0 = __expf(acc_s[in][c2]   - mn0);
                float p1 = __expf(acc_s[in][c2+2] - mn1);
                rs0 += p0; rs1 += p1;
                int kin = 2*tig + c2;
                int t = kin & 3, kk = kin >> 2;
                int b8k = warp_n*4 + in;
                PsV[((b8k*4 + t)*34 + grpP)*4 + 0 + 2*kk] = f2tf32(p0);
                PsV[((b8k*4 + t)*34 + grpP)*4 + 1 + 2*kk] = f2tf32(p1);
            }
        }
        rs0 += __shfl_xor_sync(0xffffffff, rs0, 1);
        rs0 += __shfl_xor_sync(0xffffffff, rs0, 2);
        rs1 += __shfl_xor_sync(0xffffffff, rs1, 1);
        rs1 += __shfl_xor_sync(0xffffffff, rs1, 2);
        if (tig == 0) {
            cred[warp_n*64 + qlo] = rs0;
            cred[warp_n*64 + qhi] = rs1;
        }
        #pragma unroll
        for (int in = 0; in < 4; in++) {
            o_acc[in][0] *= r0; o_acc[in][1] *= r0;
            o_acc[in][2] *= r1; o_acc[in][3] *= r1;
        }
        __syncthreads();
        if (tid < 64) lrow[tid] = lrow[tid]*rrow[tid] + cred[tid] + cred[64+tid];

        #pragma unroll
        for (int b8 = 0; b8 < 8; b8++) {
            uint4 afv = *(const uint4*)&PsV[((b8*4 + tig)*34 + grpP)*4];
            unsigned af[4] = {afv.x, afv.y, afv.z, afv.w};
            #pragma unroll
            for (int in = 0; in < 4; in++) {
                uint2 bfv = *(const uint2*)&VsV[((b8*4 + tig)*68 + warp_n*32 + in*8 + gid)*2];
                unsigned bf[2] = {bfv.x, bfv.y};
                mma_tf32(o_acc[in], af, bf);
            }
        }
    }
    __syncthreads();

    float inv0 = 1.f / lrow[qlo];
    float inv1 = 1.f / lrow[qhi];
    #pragma unroll
    for (int in = 0; in < 4; in++) {
        int col = h*64 + warp_n*32 + in*8 + 2*tig;
        float2 v0 = make_float2(o_acc[in][0]*inv0, o_acc[in][1]*inv0);
        float2 v1 = make_float2(o_acc[in][2]*inv1, o_acc[in][3]*inv1);
        *(float2*)&Y[((size_t)(b*Nn + qglo))*Dm + col] = v0;
        *(float2*)&Y[((size_t)(b*Nn + qghi))*Dm + col] = v1;
    }
}

// ---------------- router ----------------
__global__ __launch_bounds__(128) void router_kernel(
    const float* __restrict__ xf, const float* __restrict__ rw,
    float* __restrict__ Wout, float* __restrict__ Aux)
{
    int t = blockIdx.x;
    int warp = threadIdx.x >> 5, lane = threadIdx.x & 31;
    __shared__ float sg[NE];
    const float* xrow = xf + (size_t)t*Dm;
    float s = 0.f;
    for (int i = lane; i < Dm; i += 32) s += xrow[i]*rw[(size_t)warp*Dm + i];
    #pragma unroll
    for (int o = 16; o; o >>= 1) s += __shfl_xor_sync(0xffffffff, s, o);
    if (lane == 0) sg[warp] = s;
    __syncthreads();
    if (threadIdx.x == 0) {
        float m = fmaxf(fmaxf(sg[0],sg[1]), fmaxf(sg[2],sg[3]));
        float e[NE], sum = 0.f;
        #pragma unroll
        for (int i = 0; i < NE; i++) { e[i] = __expf(sg[i]-m); sum += e[i]; }
        float gate[NE];
        #pragma unroll
        for (int i = 0; i < NE; i++) gate[i] = e[i]/sum;
        int i0 = 0;
        #pragma unroll
        for (int i = 1; i < NE; i++) if (gate[i] > gate[i0]) i0 = i;
        int i1 = -1;
        #pragma unroll
        for (int i = 0; i < NE; i++) if (i != i0 && (i1 < 0 || gate[i] > gate[i1])) i1 = i;
        float s2 = fmaxf(gate[i0] + gate[i1], 1e-9f);
        #pragma unroll
        for (int i = 0; i < NE; i++) Wout[(size_t)t*NE + i] = 0.f;
        Wout[(size_t)t*NE + i0] = gate[i0]/s2;
        Wout[(size_t)t*NE + i1] = gate[i1]/s2;
        #pragma unroll
        for (int i = 0; i < NE; i++) atomicAdd(&Aux[i], gate[i]);
        atomicAdd(&Aux[NE + i0], 1.f);
        atomicAdd(&Aux[NE + i1], 1.f);
    }
}

// ---------------- MoE assignment / gather / combine ----------------
__global__ __launch_bounds__(256) void assign_kernel(
    const float* __restrict__ Wt, int* __restrict__ cnt,
    int* __restrict__ eidx, float* __restrict__ ewt, int* __restrict__ tinv)
{
    int t = blockIdx.x*256 + threadIdx.x;
    if (t >= TT) return;
    int s = 0;
    #pragma unroll
    for (int e = 0; e < NE; e++) {
        float w = Wt[(size_t)t*NE + e];
        if (w != 0.f) {
            int pos = atomicAdd(&cnt[e], 1);
            eidx[e*TT + pos] = t;
            ewt [e*TT + pos] = w;
            tinv[t*2 + s] = e*TT + pos;
            s++;
        }
    }
}

__global__ __launch_bounds__(256) void gather_kernel(
    const float* __restrict__ xf, const int* __restrict__ cnt,
    const int* __restrict__ eidx, float* __restrict__ Xe)
{
    int e = blockIdx.y, row = blockIdx.x;
    int c = cnt[e];
    if (row >= c) return;
    float4* dst = (float4*)(Xe + ((size_t)e*TT + row)*Dm);
    const float4* src = (const float4*)(xf + (size_t)eidx[e*TT + row]*Dm);
    dst[threadIdx.x] = src[threadIdx.x];
}

__global__ __launch_bounds__(256) void combine_kernel(
    const int* __restrict__ tinv, const float* __restrict__ Oe,
    float* __restrict__ XS)
{
    int t = blockIdx.x;
    int i0 = tinv[t*2], i1 = tinv[t*2+1];
    float4* xs = (float4*)(XS + (size_t)t*Dm);
    const float4* a = (const float4*)(Oe + (size_t)i0*Dm);
    const float4* b = (const float4*)(Oe + (size_t)i1*Dm);
    int i = threadIdx.x;
    float4 xv = xs[i], av = a[i], bv = b[i];
    xv.x += av.x + bv.x; xv.y += av.y + bv.y;
    xv.z += av.z + bv.z; xv.w += av.w + bv.w;
    xs[i] = xv;
}

// ---------------- final ----------------
__global__ __launch_bounds__(256) void final_kernel(
    const float* __restrict__ tw, const float* __restrict__ tb,
    const float* __restrict__ Tr, const float* __restrict__ XS,
    float* __restrict__ out)
{
    int n = blockIdx.x, b = blockIdx.y;
    for (int d = threadIdx.x; d < Dm; d += 256) {
        float acc = tb[d];
        #pragma unroll
        for (int j = 0; j < 5; j++) {
            int p = n + j - 2;
            if (p >= 0 && p < Nn) acc += tw[d*5+j] * Tr[((size_t)(b*Nn+p))*Dm + d];
        }
        size_t idx = ((size_t)(b*Nn+n))*Dm + d;
        out[idx] = XS[idx] + acc;
    }
}

__global__ void zero_aux_kernel(float* Aux, int* cnt) {
    if (threadIdx.x < 2*NE) Aux[threadIdx.x] = 0.f;
    if (threadIdx.x < NE) cnt[threadIdx.x] = 0;
}

__global__ void aux_write_kernel(const float* Aux, float* out, int out_size) {
    if (out_size > TT*Dm) {
        float a = 0.f;
        #pragma unroll
        for (int e = 0; e < NE; e++)
            a += (Aux[e]/(float)TT) * (Aux[NE+e]/(float)TT);
        out[TT*Dm] = (float)NE * a;
    }
}

// ---------------- launcher ----------------
extern "C" void kernel_launch(void* const* d_in, const int* in_sizes, int n_in,
                              void* d_out, int out_size)
{
    const float* x    = (const float*)d_in[0];
    const float* qw   = (const float*)d_in[1];
    const float* qb   = (const float*)d_in[2];
    const float* kw   = (const float*)d_in[3];
    const float* kb   = (const float*)d_in[4];
    const float* vw   = (const float*)d_in[5];
    const float* vb   = (const float*)d_in[6];
    const float* ow   = (const float*)d_in[7];
    const float* ob   = (const float*)d_in[8];
    const float* n1g  = (const float*)d_in[9];
    const float* n1b  = (const float*)d_in[10];
    const float* n2g  = (const float*)d_in[11];
    const float* n2b  = (const float*)d_in[12];
    const float* alpha= (const float*)d_in[13];
    const float* dw7  = (const float*)d_in[14];
    const float* dw25 = (const float*)d_in[15];
    const float* dw49 = (const float*)d_in[16];
    const float* rw   = (const float*)d_in[17];
    const float* ew1  = (const float*)d_in[18];
    const float* eb1  = (const float*)d_in[19];
    const float* ew2  = (const float*)d_in[20];
    const float* eb2  = (const float*)d_in[21];
    const float* tw   = (const float*)d_in[22];
    const float* tb   = (const float*)d_in[23];
    float* out = (float*)d_out;

    float *Tr,*S,*Sn,*Qb_,*Kb_,*Vb_,*Yb,*XS,*Hb,*Oe,*Wt,*Xe,*Ewt,*Aux,*Ck;
    int *Eidx,*Cnt,*Tinv;
    cudaGetSymbolAddress((void**)&Tr,  g_Tr);
    cudaGetSymbolAddress((void**)&S,   g_S);
    cudaGetSymbolAddress((void**)&Sn,  g_Sn);
    cudaGetSymbolAddress((void**)&Qb_, g_Q);
    cudaGetSymbolAddress((void**)&Kb_, g_K);
    cudaGetSymbolAddress((void**)&Vb_, g_V);
    cudaGetSymbolAddress((void**)&Yb,  g_Y);
    cudaGetSymbolAddress((void**)&XS,  g_XS);
    cudaGetSymbolAddress((void**)&Hb,  g_H);
    cudaGetSymbolAddress((void**)&Oe,  g_Oe);
    cudaGetSymbolAddress((void**)&Wt,  g_W);
    cudaGetSymbolAddress((void**)&Xe,  g_Xe);
    cudaGetSymbolAddress((void**)&Ewt, g_Ewt);
    cudaGetSymbolAddress((void**)&Aux, g_Aux);
    cudaGetSymbolAddress((void**)&Ck,  g_Ck);
    cudaGetSymbolAddress((void**)&Eidx,g_Eidx);
    cudaGetSymbolAddress((void**)&Cnt, g_Cnt);
    cudaGetSymbolAddress((void**)&Tinv,g_Tinv);

    const int ATN_SH_BYTES = ATN_SH_FLOATS * 4;
    cudaFuncSetAttribute(attn_mma_kernel, cudaFuncAttributeMaxDynamicSharedMemorySize, ATN_SH_BYTES);

    zero_aux_kernel<<<1, 32>>>(Aux, Cnt);
    ckbuild_kernel<<<Dm, 64>>>(alpha, dw7, dw25, dw49, Ck);
    trend_kernel<<<dim3(61, Bz, Dm/128), 256>>>(x, Ck, Tr, S);
    decomp_edge_kernel<<<dim3(48, Bz), 256>>>(x, alpha, dw7, dw25, dw49, Tr, S);
    ln_kernel<<<TT, 256>>>(S, Sn, n1g, n1b);

    gemm_qkv<<<dim3(Dm/128, TT/128, 3), 256>>>(Sn, qw, kw, vw, qb, kb, vb, Qb_, Kb_, Vb_);

    attn_mma_kernel<<<dim3(Nn/64, Bz*Hh), 256, ATN_SH_BYTES>>>(Qb_, Kb_, Vb_, Yb);

    gemm_res<<<dim3(Dm/128, TT/128), 256>>>(Yb, ow, ob, S, XS);
    ln_kernel<<<TT, 256>>>(XS, Sn, n2g, n2b);
    router_kernel<<<TT, 128>>>(Sn, rw, Wt, Aux);
    assign_kernel<<<TT/256, 256>>>(Wt, Cnt, Eidx, Ewt, Tinv);
    gather_kernel<<<dim3(TT, NE), 256>>>(Sn, Cnt, Eidx, Xe);

    gemm_moe_up<<<dim3(MH/128, TT/128, NE), 256>>>(Xe, ew1, eb1, Cnt, Hb);
    gemm_moe_dn<<<dim3(Dm/128, TT/128, NE), 256>>>(Hb, ew2, eb2, Cnt, Ewt, Oe);
    combine_kernel<<<TT, 256>>>(Tinv, Oe, XS);

    final_kernel<<<dim3(Nn, Bz), 256>>>(tw, tb, Tr, XS, out);
    aux_write_kernel<<<1, 1>>>(Aux, out, out_size);
}

// round 9
// speedup vs baseline: 6.9777x; 1.4006x over previous
#include <cuda_runtime.h>
#include <cuda_fp16.h>
#include <math.h>
#include <stdint.h>

#define Bz 8
#define Nn 1024
#define Dm 1024
#define Hh 16
#define HD 64
#define TT (Bz*Nn)       // 8192 tokens
#define MH 2048
#define NE 4

// ---------------- static device scratch (no allocation allowed) ----------------
__device__ float g_Tr[(size_t)TT*Dm];
__device__ float g_S [(size_t)TT*Dm];
__device__ float g_Sn[(size_t)TT*Dm];
__device__ float g_Q [(size_t)TT*Dm];
__device__ float g_K [(size_t)TT*Dm];
__device__ float g_V [(size_t)TT*Dm];
__device__ float g_Y [(size_t)TT*Dm];
__device__ float g_XS[(size_t)TT*Dm];
__device__ float g_H [(size_t)NE*TT*MH];    // per-expert hidden
__device__ float g_Oe[(size_t)NE*TT*Dm];    // per-expert weighted output (compact rows)
__device__ float g_W [(size_t)TT*NE];
__device__ float g_Xe[(size_t)NE*TT*Dm];
__device__ float g_Ck[(size_t)Dm*49];
__device__ int   g_Eidx[NE*TT];
__device__ float g_Ewt [NE*TT];
__device__ int   g_Tinv[TT*2];              // token -> (e*TT + pos) x2
__device__ int   g_Cnt[NE];
__device__ float g_Aux[2*NE];

// ---------------- fp16 mma helpers ----------------
__device__ __forceinline__ unsigned pack_h2(float lo, float hi) {
    __half2 h = __floats2half2_rn(lo, hi);
    return *reinterpret_cast<unsigned*>(&h);
}
__device__ __forceinline__ void mma_f16(float* c, const unsigned* a, const unsigned* b) {
    asm volatile(
        "mma.sync.aligned.m16n8k16.row.col.f32.f16.f16.f32 "
        "{%0,%1,%2,%3}, {%4,%5,%6,%7}, {%8,%9}, {%0,%1,%2,%3};\n"
        : "+f"(c[0]), "+f"(c[1]), "+f"(c[2]), "+f"(c[3])
        : "r"(a[0]), "r"(a[1]), "r"(a[2]), "r"(a[3]), "r"(b[0]), "r"(b[1]));
}

__device__ __forceinline__ float gelu_f(float v) {
    return 0.5f*v*(1.0f + erff(v*0.70710678118654752f));
}

// ---------------- combined decomposition kernel build ----------------
__global__ void ckbuild_kernel(
    const float* __restrict__ alpha, const float* __restrict__ w7,
    const float* __restrict__ w25, const float* __restrict__ w49,
    float* __restrict__ ck)
{
    int d = blockIdx.x, j = threadIdx.x;
    if (j >= 49) return;
    float a0 = alpha[0], a1 = alpha[1], a2 = alpha[2];
    float mx = fmaxf(a0, fmaxf(a1, a2));
    float e0 = __expf(a0-mx), e1 = __expf(a1-mx), e2 = __expf(a2-mx);
    float inv = 1.f/(e0+e1+e2);
    float wt0 = e0*inv, wt1 = e1*inv, wt2 = e2*inv;
    float v = wt2 * w49[d*49 + j];
    if (j >= 12 && j < 37) v += wt1 * w25[d*25 + (j-12)];
    if (j >= 21 && j < 28) v += wt0 * w7[d*7 + (j-21)];
    ck[d*49 + j] = v;
}

// ---------------- interior trend: combined 49-tap conv, smem window ----------------
__global__ __launch_bounds__(256) void trend_kernel(
    const float* __restrict__ x, const float* __restrict__ ck,
    float* __restrict__ Tr, float* __restrict__ S)
{
    __shared__ float xs[64][128];
    int b = blockIdx.y;
    int n0 = 24 + blockIdx.x * 16;
    int d0 = blockIdx.z * 128;
    int tid = threadIdx.x;
    int dl = tid & 127, ng = tid >> 7;

    for (int i = tid; i < 64*32; i += 256) {
        int p = i >> 5, c = i & 31;
        *(float4*)&xs[p][c*4] =
            *(const float4*)&x[((size_t)(b*Nn + n0 - 24 + p))*Dm + d0 + c*4];
    }
    __syncthreads();

    float ckr[49];
    #pragma unroll
    for (int j = 0; j < 49; j++) ckr[j] = __ldg(&ck[(size_t)(d0+dl)*49 + j]);

    float acc[8];
    #pragma unroll
    for (int j = 0; j < 8; j++) acc[j] = 0.f;

    #pragma unroll
    for (int pr = 0; pr < 56; pr++) {
        float xv = xs[ng*8 + pr][dl];
        #pragma unroll
        for (int j = 0; j < 8; j++) {
            int t = pr - j;
            if (t >= 0 && t < 49) acc[j] += ckr[t] * xv;
        }
    }

    #pragma unroll
    for (int j = 0; j < 8; j++) {
        int nl = ng*8 + j;
        size_t idx = ((size_t)(b*Nn + n0 + nl))*Dm + d0 + dl;
        float xval = xs[nl + 24][dl];
        Tr[idx] = acc[j];
        S[idx]  = xval - acc[j];
    }
}

// ---------------- boundary decomposition (reflect pad) ----------------
__global__ __launch_bounds__(256) void decomp_edge_kernel(
    const float* __restrict__ x, const float* __restrict__ alpha,
    const float* __restrict__ w7, const float* __restrict__ w25,
    const float* __restrict__ w49, float* __restrict__ Tr, float* __restrict__ S)
{
    int bx = blockIdx.x;
    int n = (bx < 24) ? bx : (Nn - 48 + bx);
    int b = blockIdx.y;
    float a0 = alpha[0], a1 = alpha[1], a2 = alpha[2];
    float mx = fmaxf(a0, fmaxf(a1, a2));
    float e0 = __expf(a0-mx), e1 = __expf(a1-mx), e2 = __expf(a2-mx);
    float inv = 1.f/(e0+e1+e2);
    float wt0 = e0*inv, wt1 = e1*inv, wt2 = e2*inv;

    for (int d = threadIdx.x; d < Dm; d += 256) {
        float t7 = 0.f, t25 = 0.f, t49 = 0.f;
        #pragma unroll
        for (int j = 0; j < 7; j++) {
            int p = n + j - 3; p = p < 0 ? -p : (p >= Nn ? 2*Nn-2-p : p);
            t7 += w7[d*7+j] * x[((size_t)(b*Nn+p))*Dm + d];
        }
        #pragma unroll
        for (int j = 0; j < 25; j++) {
            int p = n + j - 12; p = p < 0 ? -p : (p >= Nn ? 2*Nn-2-p : p);
            t25 += w25[d*25+j] * x[((size_t)(b*Nn+p))*Dm + d];
        }
        #pragma unroll
        for (int j = 0; j < 49; j++) {
            int p = n + j - 24; p = p < 0 ? -p : (p >= Nn ? 2*Nn-2-p : p);
            t49 += w49[d*49+j] * x[((size_t)(b*Nn+p))*Dm + d];
        }
        float tr = wt0*t7 + wt1*t25 + wt2*t49;
        size_t idx = ((size_t)(b*Nn+n))*Dm + d;
        Tr[idx] = tr;
        S[idx]  = x[idx] - tr;
    }
}

// ---------------- one-pass LayerNorm ----------------
__global__ __launch_bounds__(256) void ln_kernel(
    const float* __restrict__ in, float* __restrict__ out,
    const float* __restrict__ g, const float* __restrict__ b)
{
    __shared__ float red[8];
    int t = blockIdx.x, tid = threadIdx.x;
    int lane = tid & 31, warp = tid >> 5;
    const float4* row4 = (const float4*)(in + (size_t)t*Dm);
    float4 v = row4[tid];
    float s = v.x + v.y + v.z + v.w;
    #pragma unroll
    for (int o = 16; o; o >>= 1) s += __shfl_xor_sync(0xffffffff, s, o);
    if (lane == 0) red[warp] = s;
    __syncthreads();
    float tot = 0.f;
    #pragma unroll
    for (int i = 0; i < 8; i++) tot += red[i];
    float m = tot * (1.f/Dm);
    float dx = v.x-m, dy = v.y-m, dz = v.z-m, dw = v.w-m;
    float s2 = dx*dx + dy*dy + dz*dz + dw*dw;
    #pragma unroll
    for (int o = 16; o; o >>= 1) s2 += __shfl_xor_sync(0xffffffff, s2, o);
    __syncthreads();
    if (lane == 0) red[warp] = s2;
    __syncthreads();
    float tot2 = 0.f;
    #pragma unroll
    for (int i = 0; i < 8; i++) tot2 += red[i];
    float rinv = rsqrtf(tot2*(1.f/Dm) + 1e-5f);
    float4 gv = ((const float4*)g)[tid];
    float4 bv = ((const float4*)b)[tid];
    float4 o4;
    o4.x = dx*rinv*gv.x + bv.x;
    o4.y = dy*rinv*gv.y + bv.y;
    o4.z = dz*rinv*gv.z + bv.z;
    o4.w = dw*rinv*gv.w + bv.w;
    ((float4*)(out + (size_t)t*Dm))[tid] = o4;
}

// ---------------- fp16 tensor-core GEMM core (m16n8k16, double-buffered packed smem) ----------------
// MODE 0: C = dot+bias ; MODE 1: += res ; MODE 2: gelu (rows<cN) ; MODE 3: C = w*(dot+bias) (rows<cN)
template<int MODE>
__device__ __forceinline__ void gemm_core(
    const float* __restrict__ A, const float* __restrict__ W,
    const float* __restrict__ bias, const float* __restrict__ res,
    const float* __restrict__ wvec,
    float* __restrict__ C, int K, int O, int t0, int o0, int cN)
{
    __shared__ __align__(16) unsigned AsV[2*1056];
    __shared__ __align__(16) unsigned BsV[2*1056];
    int tid = threadIdx.x;
    int lane = tid & 31, warp = tid >> 5;
    int warp_m = warp >> 2, warp_n = warp & 3;   // 2 x 4 warps
    int gid = lane >> 2, tig = lane & 3;

    float acc[4][4][4];
    #pragma unroll
    for (int im = 0; im < 4; im++)
        #pragma unroll
        for (int in = 0; in < 4; in++)
            #pragma unroll
            for (int q = 0; q < 4; q++) acc[im][in][q] = 0.f;

    int lr = tid >> 1;            // row 0..127
    int hb = tid & 1;             // k-half 0/1 (of 16)
    int lc = hb*8;
    const float* Ap = A + (size_t)(t0+lr)*K + lc;
    const float* Bp = W + (size_t)(o0+lr)*K + lc;

    int grpA = ((lr >> 4) << 3) + (lr & 7);
    int pmA  = (lr >> 3) & 1;

    float4 pa0 = *(const float4*)(Ap);
    float4 pa1 = *(const float4*)(Ap+4);
    float4 pb0 = *(const float4*)(Bp);
    float4 pb1 = *(const float4*)(Bp+4);

    // pack tile 0 into buffer 0
    {
        float av[8] = {pa0.x,pa0.y,pa0.z,pa0.w,pa1.x,pa1.y,pa1.z,pa1.w};
        float bv[8] = {pb0.x,pb0.y,pb0.z,pb0.w,pb1.x,pb1.y,pb1.z,pb1.w};
        #pragma unroll
        for (int j = 0; j < 4; j++) {
            AsV[(j*66 + grpA)*4 + pmA + 2*hb] = pack_h2(av[2*j], av[2*j+1]);
            BsV[(j*132 + lr)*2 + hb]          = pack_h2(bv[2*j], bv[2*j+1]);
        }
    }
    __syncthreads();

    for (int kt = 0; kt < K; kt += 16) {
        int cur = (kt >> 4) & 1;
        bool more = (kt + 16 < K);
        if (more) {
            pa0 = *(const float4*)(Ap + kt + 16);
            pa1 = *(const float4*)(Ap + kt + 20);
            pb0 = *(const float4*)(Bp + kt + 16);
            pb1 = *(const float4*)(Bp + kt + 20);
        }
        // compute on buffer cur: one k16 step, 16 MMAs
        {
            unsigned af[4][4], bf[4][2];
            #pragma unroll
            for (int im = 0; im < 4; im++) {
                uint4 v = *(const uint4*)&AsV[cur*1056 + (tig*66 + (warp_m*4+im)*8 + gid)*4];
                af[im][0]=v.x; af[im][1]=v.y; af[im][2]=v.z; af[im][3]=v.w;
            }
            #pragma unroll
            for (int in = 0; in < 4; in++) {
                uint2 v = *(const uint2*)&BsV[cur*1056 + (tig*132 + warp_n*32 + in*8 + gid)*2];
                bf[in][0]=v.x; bf[in][1]=v.y;
            }
            #pragma unroll
            for (int im = 0; im < 4; im++)
                #pragma unroll
                for (int in = 0; in < 4; in++)
                    mma_f16(acc[im][in], af[im], bf[in]);
        }
        if (more) {
            int nb = cur ^ 1;
            float av[8] = {pa0.x,pa0.y,pa0.z,pa0.w,pa1.x,pa1.y,pa1.z,pa1.w};
            float bv[8] = {pb0.x,pb0.y,pb0.z,pb0.w,pb1.x,pb1.y,pb1.z,pb1.w};
            #pragma unroll
            for (int j = 0; j < 4; j++) {
                AsV[nb*1056 + (j*66 + grpA)*4 + pmA + 2*hb] = pack_h2(av[2*j], av[2*j+1]);
                BsV[nb*1056 + (j*132 + lr)*2 + hb]          = pack_h2(bv[2*j], bv[2*j+1]);
            }
        }
        __syncthreads();
    }

    #pragma unroll
    for (int im = 0; im < 4; im++) {
        #pragma unroll
        for (int half = 0; half < 2; half++) {
            int row = t0 + warp_m*64 + im*16 + gid + half*8;
            if ((MODE == 2 || MODE == 3) && row >= cN) continue;
            float w = 0.f;
            if (MODE == 3) w = wvec[row];
            #pragma unroll
            for (int in = 0; in < 4; in++) {
                int col = o0 + warp_n*32 + in*8 + 2*tig;
                float v0 = acc[im][in][half*2+0] + bias[col];
                float v1 = acc[im][in][half*2+1] + bias[col+1];
                size_t idx = (size_t)row*O + col;
                if (MODE == 0) { C[idx] = v0; C[idx+1] = v1; }
                else if (MODE == 1) { C[idx] = v0 + res[idx]; C[idx+1] = v1 + res[idx+1]; }
                else if (MODE == 2) { C[idx] = gelu_f(v0); C[idx+1] = gelu_f(v1); }
                else { C[idx] = w*v0; C[idx+1] = w*v1; }
            }
        }
    }
}

// ---- wrappers ----
__global__ __launch_bounds__(256, 2) void gemm_qkv(
    const float* __restrict__ A,
    const float* __restrict__ w0, const float* __restrict__ w1, const float* __restrict__ w2,
    const float* __restrict__ b0, const float* __restrict__ b1, const float* __restrict__ b2,
    float* __restrict__ c0, float* __restrict__ c1, float* __restrict__ c2)
{
    int z = blockIdx.z;
    const float* W = (z == 0) ? w0 : (z == 1) ? w1 : w2;
    const float* B = (z == 0) ? b0 : (z == 1) ? b1 : b2;
    float* C = (z == 0) ? c0 : (z == 1) ? c1 : c2;
    gemm_core<0>(A, W, B, nullptr, nullptr, C, Dm, Dm,
                 blockIdx.y*128, blockIdx.x*128, 1 << 30);
}

__global__ __launch_bounds__(256, 2) void gemm_res(
    const float* __restrict__ A, const float* __restrict__ W,
    const float* __restrict__ bias, const float* __restrict__ res,
    float* __restrict__ C)
{
    gemm_core<1>(A, W, bias, res, nullptr, C, Dm, Dm,
                 blockIdx.y*128, blockIdx.x*128, 1 << 30);
}

__global__ __launch_bounds__(256, 2) void gemm_moe_up(
    const float* __restrict__ Xe, const float* __restrict__ ew1,
    const float* __restrict__ eb1, const int* __restrict__ cnt,
    float* __restrict__ Hb)
{
    int e = blockIdx.z;
    int cN = cnt[e];
    int t0 = blockIdx.y*128;
    if (t0 >= cN) return;
    gemm_core<2>(Xe + (size_t)e*TT*Dm, ew1 + (size_t)e*MH*Dm, eb1 + (size_t)e*MH,
                 nullptr, nullptr, Hb + (size_t)e*TT*MH, Dm, MH,
                 t0, blockIdx.x*128, cN);
}

__global__ __launch_bounds__(256, 2) void gemm_moe_dn(
    const float* __restrict__ Hb, const float* __restrict__ ew2,
    const float* __restrict__ eb2, const int* __restrict__ cnt,
    const float* __restrict__ ewt, float* __restrict__ Oe)
{
    int e = blockIdx.z;
    int cN = cnt[e];
    int t0 = blockIdx.y*128;
    if (t0 >= cN) return;
    gemm_core<3>(Hb + (size_t)e*TT*MH, ew2 + (size_t)e*Dm*MH, eb2 + (size_t)e*Dm,
                 nullptr, ewt + (size_t)e*TT, Oe + (size_t)e*TT*Dm, MH, Dm,
                 t0, blockIdx.x*128, cN);
}

// ---------------- flash attention with fp16 MMA (m16n8k16) ----------------
// packed fragments: Qs/Ps [4 b16][4 tig][34 grp][4 comp], Ks/Vs [4 b16][4 tig][68 col][2 khalf]
#define ATN_SH_FLOATS (4*2176 + 320)

__global__ __launch_bounds__(256) void attn_mma_kernel(
    const float* __restrict__ Q, const float* __restrict__ K,
    const float* __restrict__ V, float* __restrict__ Y)
{
    extern __shared__ __align__(16) unsigned ash[];
    unsigned* QsV = ash;
    unsigned* KsV = ash + 2176;
    unsigned* PsV = ash + 2*2176;
    unsigned* VsV = ash + 3*2176;
    float* mrow = (float*)(ash + 4*2176);
    float* lrow = mrow + 64;
    float* rrow = lrow + 64;
    float* cred = rrow + 64;

    int bh = blockIdx.y;
    int b = bh >> 4, h = bh & 15;
    int q0 = blockIdx.x * 64;
    int tid = threadIdx.x;
    int warp = tid >> 5, lane = tid & 31;
    int gid = lane >> 2, tig = lane & 3;
    int warp_m = warp >> 1, warp_n = warp & 1;
    float slope = exp2f(-0.5f * (float)(h+1));

    // load Q tile (pairs of d)
    for (int i = tid; i < 64*32; i += 256) {
        int q = i >> 5, d = (i & 31)*2;
        float2 v2 = *(const float2*)&Q[((size_t)(b*Nn + q0 + q))*Dm + h*64 + d];
        int b16 = d >> 4, khalf = (d >> 3) & 1, tg = (d >> 1) & 3;
        int grp = ((q >> 4) << 3) + (q & 7), rh = (q >> 3) & 1;
        QsV[((b16*4 + tg)*34 + grp)*4 + rh + 2*khalf] = pack_h2(v2.x, v2.y);
    }
    if (tid < 64) { mrow[tid] = -1e30f; lrow[tid] = 0.f; }

    float o_acc[4][4];
    #pragma unroll
    for (int in = 0; in < 4; in++)
        #pragma unroll
        for (int q = 0; q < 4; q++) o_acc[in][q] = 0.f;

    int qlo = warp_m*16 + gid, qhi = qlo + 8;
    int qglo = q0 + qlo, qghi = q0 + qhi;
    int grpP = warp_m*8 + gid;

    for (int kt = 0; kt < Nn; kt += 64) {
        __syncthreads();
        // K: pairs of d per key row j
        for (int i = tid; i < 64*32; i += 256) {
            int j = i >> 5, d = (i & 31)*2;
            float2 v2 = *(const float2*)&K[((size_t)(b*Nn + kt + j))*Dm + h*64 + d];
            int b16 = d >> 4, khalf = (d >> 3) & 1, tg = (d >> 1) & 3;
            KsV[((b16*4 + tg)*68 + j)*2 + khalf] = pack_h2(v2.x, v2.y);
        }
        // V: pairs of j per dim d (d fast for coalescing)
        for (int i = tid; i < 64*32; i += 256) {
            int d = i & 63, j = (i >> 6)*2;
            float v0 = V[((size_t)(b*Nn + kt + j  ))*Dm + h*64 + d];
            float v1 = V[((size_t)(b*Nn + kt + j+1))*Dm + h*64 + d];
            int b16 = j >> 4, khalf = (j >> 3) & 1, tg = (j >> 1) & 3;
            VsV[((b16*4 + tg)*68 + d)*2 + khalf] = pack_h2(v0, v1);
        }
        __syncthreads();

        float acc_s[4][4];
        #pragma unroll
        for (int in = 0; in < 4; in++)
            #pragma unroll
            for (int q = 0; q < 4; q++) acc_s[in][q] = 0.f;

        #pragma unroll
        for (int b16 = 0; b16 < 4; b16++) {
            uint4 afv = *(const uint4*)&QsV[((b16*4 + tig)*34 + grpP)*4];
            unsigned af[4] = {afv.x, afv.y, afv.z, afv.w};
            #pragma unroll
            for (int in = 0; in < 4; in++) {
                uint2 bfv = *(const uint2*)&KsV[((b16*4 + tig)*68 + warp_n*32 + in*8 + gid)*2];
                unsigned bf[2] = {bfv.x, bfv.y};
                mma_f16(acc_s[in], af, bf);
            }
        }

        float rmax0 = -1e30f, rmax1 = -1e30f;
        #pragma unroll
        for (int in = 0; in < 4; in++) {
            #pragma unroll
            for (int c2 = 0; c2 < 2; c2++) {
                int kg = kt + warp_n*32 + in*8 + 2*tig + c2;
                float d0 = (kg > qglo) ? (float)(kg - qglo) : 0.f;
                float d1 = (kg > qghi) ? (float)(kg - qghi) : 0.f;
                acc_s[in][c2]   = acc_s[in][c2]  *0.125f - slope*d0;
                acc_s[in][c2+2] = acc_s[in][c2+2]*0.125f - slope*d1;
                rmax0 = fmaxf(rmax0, acc_s[in][c2]);
                rmax1 = fmaxf(rmax1, acc_s[in][c2+2]);
            }
        }
        rmax0 = fmaxf(rmax0, __shfl_xor_sync(0xffffffff, rmax0, 1));
        rmax0 = fmaxf(rmax0, __shfl_xor_sync(0xffffffff, rmax0, 2));
        rmax1 = fmaxf(rmax1, __shfl_xor_sync(0xffffffff, rmax1, 1));
        rmax1 = fmaxf(rmax1, __shfl_xor_sync(0xffffffff, rmax1, 2));
        if (tig == 0) {
            cred[warp_n*64 + qlo] = rmax0;
            cred[warp_n*64 + qhi] = rmax1;
        }
        __syncthreads();
        if (tid < 64) {
            float mo = mrow[tid];
            float mn = fmaxf(mo, fmaxf(cred[tid], cred[64+tid]));
            mrow[tid] = mn;
            rrow[tid] = __expf(mo - mn);
        }
        __syncthreads();

        float mn0 = mrow[qlo], mn1 = mrow[qhi];
        float r0 = rrow[qlo], r1 = rrow[qhi];
        float rs0 = 0.f, rs1 = 0.f;
        #pragma unroll
        for (int in = 0; in < 4; in++) {
            float p00 = __expf(acc_s[in][0] - mn0);
            float p01 = __expf(acc_s[in][1] - mn0);
            float p10 = __expf(acc_s[in][2] - mn1);
            float p11 = __expf(acc_s[in][3] - mn1);
            rs0 += p00 + p01; rs1 += p10 + p11;
            int b16k = warp_n*2 + (in >> 1);
            int khalf = in & 1;
            PsV[((b16k*4 + tig)*34 + grpP)*4 + 0 + 2*khalf] = pack_h2(p00, p01);
            PsV[((b16k*4 + tig)*34 + grpP)*4 + 1 + 2*khalf] = pack_h2(p10, p11);
        }
        rs0 += __shfl_xor_sync(0xffffffff, rs0, 1);
        rs0 += __shfl_xor_sync(0xffffffff, rs0, 2);
        rs1 += __shfl_xor_sync(0xffffffff, rs1, 1);
        rs1 += __shfl_xor_sync(0xffffffff, rs1, 2);
        if (tig == 0) {
            cred[warp_n*64 + qlo] = rs0;
            cred[warp_n*64 + qhi] = rs1;
        }
        #pragma unroll
        for (int in = 0; in < 4; in++) {
            o_acc[in][0] *= r0; o_acc[in][1] *= r0;
            o_acc[in][2] *= r1; o_acc[in][3] *= r1;
        }
        __syncthreads();
        if (tid < 64) lrow[tid] = lrow[tid]*rrow[tid] + cred[tid] + cred[64+tid];

        #pragma unroll
        for (int b16 = 0; b16 < 4; b16++) {
            uint4 afv = *(const uint4*)&PsV[((b16*4 + tig)*34 + grpP)*4];
            unsigned af[4] = {afv.x, afv.y, afv.z, afv.w};
            #pragma unroll
            for (int in = 0; in < 4; in++) {
                uint2 bfv = *(const uint2*)&VsV[((b16*4 + tig)*68 + warp_n*32 + in*8 + gid)*2];
                unsigned bf[2] = {bfv.x, bfv.y};
                mma_f16(o_acc[in], af, bf);
            }
        }
    }
    __syncthreads();

    float inv0 = 1.f / lrow[qlo];
    float inv1 = 1.f / lrow[qhi];
    #pragma unroll
    for (int in = 0; in < 4; in++) {
        int col = h*64 + warp_n*32 + in*8 + 2*tig;
        float2 v0 = make_float2(o_acc[in][0]*inv0, o_acc[in][1]*inv0);
        float2 v1 = make_float2(o_acc[in][2]*inv1, o_acc[in][3]*inv1);
        *(float2*)&Y[((size_t)(b*Nn + qglo))*Dm + col] = v0;
        *(float2*)&Y[((size_t)(b*Nn + qghi))*Dm + col] = v1;
    }
}

// ---------------- router ----------------
__global__ __launch_bounds__(128) void router_kernel(
    const float* __restrict__ xf, const float* __restrict__ rw,
    float* __restrict__ Wout, float* __restrict__ Aux)
{
    int t = blockIdx.x;
    int warp = threadIdx.x >> 5, lane = threadIdx.x & 31;
    __shared__ float sg[NE];
    const float* xrow = xf + (size_t)t*Dm;
    float s = 0.f;
    for (int i = lane; i < Dm; i += 32) s += xrow[i]*rw[(size_t)warp*Dm + i];
    #pragma unroll
    for (int o = 16; o; o >>= 1) s += __shfl_xor_sync(0xffffffff, s, o);
    if (lane == 0) sg[warp] = s;
    __syncthreads();
    if (threadIdx.x == 0) {
        float m = fmaxf(fmaxf(sg[0],sg[1]), fmaxf(sg[2],sg[3]));
        float e[NE], sum = 0.f;
        #pragma unroll
        for (int i = 0; i < NE; i++) { e[i] = __expf(sg[i]-m); sum += e[i]; }
        float gate[NE];
        #pragma unroll
        for (int i = 0; i < NE; i++) gate[i] = e[i]/sum;
        int i0 = 0;
        #pragma unroll
        for (int i = 1; i < NE; i++) if (gate[i] > gate[i0]) i0 = i;
        int i1 = -1;
        #pragma unroll
        for (int i = 0; i < NE; i++) if (i != i0 && (i1 < 0 || gate[i] > gate[i1])) i1 = i;
        float s2 = fmaxf(gate[i0] + gate[i1], 1e-9f);
        #pragma unroll
        for (int i = 0; i < NE; i++) Wout[(size_t)t*NE + i] = 0.f;
        Wout[(size_t)t*NE + i0] = gate[i0]/s2;
        Wout[(size_t)t*NE + i1] = gate[i1]/s2;
        #pragma unroll
        for (int i = 0; i < NE; i++) atomicAdd(&Aux[i], gate[i]);
        atomicAdd(&Aux[NE + i0], 1.f);
        atomicAdd(&Aux[NE + i1], 1.f);
    }
}

// ---------------- MoE assignment / gather / combine ----------------
__global__ __launch_bounds__(256) void assign_kernel(
    const float* __restrict__ Wt, int* __restrict__ cnt,
    int* __restrict__ eidx, float* __restrict__ ewt, int* __restrict__ tinv)
{
    int t = blockIdx.x*256 + threadIdx.x;
    if (t >= TT) return;
    int s = 0;
    #pragma unroll
    for (int e = 0; e < NE; e++) {
        float w = Wt[(size_t)t*NE + e];
        if (w != 0.f) {
            int pos = atomicAdd(&cnt[e], 1);
            eidx[e*TT + pos] = t;
            ewt [e*TT + pos] = w;
            tinv[t*2 + s] = e*TT + pos;
            s++;
        }
    }
}

__global__ __launch_bounds__(256) void gather_kernel(
    const float* __restrict__ xf, const int* __restrict__ cnt,
    const int* __restrict__ eidx, float* __restrict__ Xe)
{
    int e = blockIdx.y, row = blockIdx.x;
    int c = cnt[e];
    if (row >= c) return;
    float4* dst = (float4*)(Xe + ((size_t)e*TT + row)*Dm);
    const float4* src = (const float4*)(xf + (size_t)eidx[e*TT + row]*Dm);
    dst[threadIdx.x] = src[threadIdx.x];
}

__global__ __launch_bounds__(256) void combine_kernel(
    const int* __restrict__ tinv, const float* __restrict__ Oe,
    float* __restrict__ XS)
{
    int t = blockIdx.x;
    int i0 = tinv[t*2], i1 = tinv[t*2+1];
    float4* xs = (float4*)(XS + (size_t)t*Dm);
    const float4* a = (const float4*)(Oe + (size_t)i0*Dm);
    const float4* b = (const float4*)(Oe + (size_t)i1*Dm);
    int i = threadIdx.x;
    float4 xv = xs[i], av = a[i], bv = b[i];
    xv.x += av.x + bv.x; xv.y += av.y + bv.y;
    xv.z += av.z + bv.z; xv.w += av.w + bv.w;
    xs[i] = xv;
}

// ---------------- final ----------------
__global__ __launch_bounds__(256) void final_kernel(
    const float* __restrict__ tw, const float* __restrict__ tb,
    const float* __restrict__ Tr, const float* __restrict__ XS,
    float* __restrict__ out)
{
    int n = blockIdx.x, b = blockIdx.y;
    for (int d = threadIdx.x; d < Dm; d += 256) {
        float acc = tb[d];
        #pragma unroll
        for (int j = 0; j < 5; j++) {
            int p = n + j - 2;
            if (p >= 0 && p < Nn) acc += tw[d*5+j] * Tr[((size_t)(b*Nn+p))*Dm + d];
        }
        size_t idx = ((size_t)(b*Nn+n))*Dm + d;
        out[idx] = XS[idx] + acc;
    }
}

__global__ void zero_aux_kernel(float* Aux, int* cnt) {
    if (threadIdx.x < 2*NE) Aux[threadIdx.x] = 0.f;
    if (threadIdx.x < NE) cnt[threadIdx.x] = 0;
}

__global__ void aux_write_kernel(const float* Aux, float* out, int out_size) {
    if (out_size > TT*Dm) {
        float a = 0.f;
        #pragma unroll
        for (int e = 0; e < NE; e++)
            a += (Aux[e]/(float)TT) * (Aux[NE+e]/(float)TT);
        out[TT*Dm] = (float)NE * a;
    }
}

// ---------------- launcher ----------------
extern "C" void kernel_launch(void* const* d_in, const int* in_sizes, int n_in,
                              void* d_out, int out_size)
{
    const float* x    = (const float*)d_in[0];
    const float* qw   = (const float*)d_in[1];
    const float* qb   = (const float*)d_in[2];
    const float* kw   = (const float*)d_in[3];
    const float* kb   = (const float*)d_in[4];
    const float* vw   = (const float*)d_in[5];
    const float* vb   = (const float*)d_in[6];
    const float* ow   = (const float*)d_in[7];
    const float* ob   = (const float*)d_in[8];
    const float* n1g  = (const float*)d_in[9];
    const float* n1b  = (const float*)d_in[10];
    const float* n2g  = (const float*)d_in[11];
    const float* n2b  = (const float*)d_in[12];
    const float* alpha= (const float*)d_in[13];
    const float* dw7  = (const float*)d_in[14];
    const float* dw25 = (const float*)d_in[15];
    const float* dw49 = (const float*)d_in[16];
    const float* rw   = (const float*)d_in[17];
    const float* ew1  = (const float*)d_in[18];
    const float* eb1  = (const float*)d_in[19];
    const float* ew2  = (const float*)d_in[20];
    const float* eb2  = (const float*)d_in[21];
    const float* tw   = (const float*)d_in[22];
    const float* tb   = (const float*)d_in[23];
    float* out = (float*)d_out;

    float *Tr,*S,*Sn,*Qb_,*Kb_,*Vb_,*Yb,*XS,*Hb,*Oe,*Wt,*Xe,*Ewt,*Aux,*Ck;
    int *Eidx,*Cnt,*Tinv;
    cudaGetSymbolAddress((void**)&Tr,  g_Tr);
    cudaGetSymbolAddress((void**)&S,   g_S);
    cudaGetSymbolAddress((void**)&Sn,  g_Sn);
    cudaGetSymbolAddress((void**)&Qb_, g_Q);
    cudaGetSymbolAddress((void**)&Kb_, g_K);
    cudaGetSymbolAddress((void**)&Vb_, g_V);
    cudaGetSymbolAddress((void**)&Yb,  g_Y);
    cudaGetSymbolAddress((void**)&XS,  g_XS);
    cudaGetSymbolAddress((void**)&Hb,  g_H);
    cudaGetSymbolAddress((void**)&Oe,  g_Oe);
    cudaGetSymbolAddress((void**)&Wt,  g_W);
    cudaGetSymbolAddress((void**)&Xe,  g_Xe);
    cudaGetSymbolAddress((void**)&Ewt, g_Ewt);
    cudaGetSymbolAddress((void**)&Aux, g_Aux);
    cudaGetSymbolAddress((void**)&Ck,  g_Ck);
    cudaGetSymbolAddress((void**)&Eidx,g_Eidx);
    cudaGetSymbolAddress((void**)&Cnt, g_Cnt);
    cudaGetSymbolAddress((void**)&Tinv,g_Tinv);

    const int ATN_SH_BYTES = ATN_SH_FLOATS * 4;
    cudaFuncSetAttribute(attn_mma_kernel, cudaFuncAttributeMaxDynamicSharedMemorySize, ATN_SH_BYTES);

    zero_aux_kernel<<<1, 32>>>(Aux, Cnt);
    ckbuild_kernel<<<Dm, 64>>>(alpha, dw7, dw25, dw49, Ck);
    trend_kernel<<<dim3(61, Bz, Dm/128), 256>>>(x, Ck, Tr, S);
    decomp_edge_kernel<<<dim3(48, Bz), 256>>>(x, alpha, dw7, dw25, dw49, Tr, S);
    ln_kernel<<<TT, 256>>>(S, Sn, n1g, n1b);

    gemm_qkv<<<dim3(Dm/128, TT/128, 3), 256>>>(Sn, qw, kw, vw, qb, kb, vb, Qb_, Kb_, Vb_);

    attn_mma_kernel<<<dim3(Nn/64, Bz*Hh), 256, ATN_SH_BYTES>>>(Qb_, Kb_, Vb_, Yb);

    gemm_res<<<dim3(Dm/128, TT/128), 256>>>(Yb, ow, ob, S, XS);
    ln_kernel<<<TT, 256>>>(XS, Sn, n2g, n2b);
    router_kernel<<<TT, 128>>>(Sn, rw, Wt, Aux);
    assign_kernel<<<TT/256, 256>>>(Wt, Cnt, Eidx, Ewt, Tinv);
    gather_kernel<<<dim3(TT, NE), 256>>>(Sn, Cnt, Eidx, Xe);

    gemm_moe_up<<<dim3(MH/128, TT/128, NE), 256>>>(Xe, ew1, eb1, Cnt, Hb);
    gemm_moe_dn<<<dim3(Dm/128, TT/128, NE), 256>>>(Hb, ew2, eb2, Cnt, Ewt, Oe);
    combine_kernel<<<TT, 256>>>(Tinv, Oe, XS);

    final_kernel<<<dim3(Nn, Bz), 256>>>(tw, tb, Tr, XS, out);
    aux_write_kernel<<<1, 1>>>(Aux, out, out_size);
}

// round 10
// speedup vs baseline: 8.9060x; 1.2764x over previous
#include <cuda_runtime.h>
#include <cuda_fp16.h>
#include <math.h>
#include <stdint.h>

#define Bz 8
#define Nn 1024
#define Dm 1024
#define Hh 16
#define HD 64
#define TT (Bz*Nn)       // 8192 tokens
#define MH 2048
#define NE 4

// ---------------- static device scratch (no allocation allowed) ----------------
__device__ float  g_Tr[(size_t)TT*Dm];
__device__ float  g_S [(size_t)TT*Dm];
__device__ float  g_XS[(size_t)TT*Dm];
__device__ float  g_Oe[(size_t)NE*TT*Dm];    // per-expert weighted output (compact rows, fp32)
__device__ float  g_W [(size_t)TT*NE];
__device__ float  g_Ck[(size_t)Dm*49];
__device__ __half g_hSn[(size_t)TT*Dm];
__device__ __half g_hQ [(size_t)TT*Dm];
__device__ __half g_hK [(size_t)TT*Dm];
__device__ __half g_hV [(size_t)TT*Dm];
__device__ __half g_hY [(size_t)TT*Dm];
__device__ __half g_hH [(size_t)NE*TT*MH];   // per-expert hidden (half)
__device__ __half g_hXe[(size_t)NE*TT*Dm];   // per-expert gathered rows (half)
__device__ __half g_hQw[(size_t)Dm*Dm];
__device__ __half g_hKw[(size_t)Dm*Dm];
__device__ __half g_hVw[(size_t)Dm*Dm];
__device__ __half g_hOw[(size_t)Dm*Dm];
__device__ __half g_hE1[(size_t)NE*MH*Dm];
__device__ __half g_hE2[(size_t)NE*Dm*MH];
__device__ int    g_Eidx[NE*TT];
__device__ float  g_Ewt [NE*TT];
__device__ int    g_Tinv[TT*2];              // token -> (e*TT + pos) x2
__device__ int    g_Cnt[NE];
__device__ float  g_Aux[2*NE];

// ---------------- fp16 mma helpers ----------------
__device__ __forceinline__ unsigned pack_h2(float lo, float hi) {
    __half2 h = __floats2half2_rn(lo, hi);
    return *reinterpret_cast<unsigned*>(&h);
}
__device__ __forceinline__ void mma_f16(float* c, const unsigned* a, const unsigned* b) {
    asm volatile(
        "mma.sync.aligned.m16n8k16.row.col.f32.f16.f16.f32 "
        "{%0,%1,%2,%3}, {%4,%5,%6,%7}, {%8,%9}, {%0,%1,%2,%3};\n"
        : "+f"(c[0]), "+f"(c[1]), "+f"(c[2]), "+f"(c[3])
        : "r"(a[0]), "r"(a[1]), "r"(a[2]), "r"(a[3]), "r"(b[0]), "r"(b[1]));
}

__device__ __forceinline__ float gelu_f(float v) {
    return 0.5f*v*(1.0f + erff(v*0.70710678118654752f));
}

// ---------------- fp32 -> fp16 weight conversion ----------------
__global__ __launch_bounds__(256) void cvt_kernel(
    const float* __restrict__ src, __half* __restrict__ dst, int n4)
{
    int i = blockIdx.x*256 + threadIdx.x;
    if (i >= n4) return;
    float4 v = ((const float4*)src)[i];
    __half2 h0 = __floats2half2_rn(v.x, v.y);
    __half2 h1 = __floats2half2_rn(v.z, v.w);
    ((__half2*)dst)[2*i]   = h0;
    ((__half2*)dst)[2*i+1] = h1;
}

// ---------------- combined decomposition kernel build ----------------
__global__ void ckbuild_kernel(
    const float* __restrict__ alpha, const float* __restrict__ w7,
    const float* __restrict__ w25, const float* __restrict__ w49,
    float* __restrict__ ck)
{
    int d = blockIdx.x, j = threadIdx.x;
    if (j >= 49) return;
    float a0 = alpha[0], a1 = alpha[1], a2 = alpha[2];
    float mx = fmaxf(a0, fmaxf(a1, a2));
    float e0 = __expf(a0-mx), e1 = __expf(a1-mx), e2 = __expf(a2-mx);
    float inv = 1.f/(e0+e1+e2);
    float wt0 = e0*inv, wt1 = e1*inv, wt2 = e2*inv;
    float v = wt2 * w49[d*49 + j];
    if (j >= 12 && j < 37) v += wt1 * w25[d*25 + (j-12)];
    if (j >= 21 && j < 28) v += wt0 * w7[d*7 + (j-21)];
    ck[d*49 + j] = v;
}

// ---------------- interior trend: combined 49-tap conv, smem window ----------------
__global__ __launch_bounds__(256) void trend_kernel(
    const float* __restrict__ x, const float* __restrict__ ck,
    float* __restrict__ Tr, float* __restrict__ S)
{
    __shared__ float xs[64][128];
    int b = blockIdx.y;
    int n0 = 24 + blockIdx.x * 16;
    int d0 = blockIdx.z * 128;
    int tid = threadIdx.x;
    int dl = tid & 127, ng = tid >> 7;

    for (int i = tid; i < 64*32; i += 256) {
        int p = i >> 5, c = i & 31;
        *(float4*)&xs[p][c*4] =
            *(const float4*)&x[((size_t)(b*Nn + n0 - 24 + p))*Dm + d0 + c*4];
    }
    __syncthreads();

    float ckr[49];
    #pragma unroll
    for (int j = 0; j < 49; j++) ckr[j] = __ldg(&ck[(size_t)(d0+dl)*49 + j]);

    float acc[8];
    #pragma unroll
    for (int j = 0; j < 8; j++) acc[j] = 0.f;

    #pragma unroll
    for (int pr = 0; pr < 56; pr++) {
        float xv = xs[ng*8 + pr][dl];
        #pragma unroll
        for (int j = 0; j < 8; j++) {
            int t = pr - j;
            if (t >= 0 && t < 49) acc[j] += ckr[t] * xv;
        }
    }

    #pragma unroll
    for (int j = 0; j < 8; j++) {
        int nl = ng*8 + j;
        size_t idx = ((size_t)(b*Nn + n0 + nl))*Dm + d0 + dl;
        float xval = xs[nl + 24][dl];
        Tr[idx] = acc[j];
        S[idx]  = xval - acc[j];
    }
}

// ---------------- boundary decomposition (reflect pad) ----------------
__global__ __launch_bounds__(256) void decomp_edge_kernel(
    const float* __restrict__ x, const float* __restrict__ alpha,
    const float* __restrict__ w7, const float* __restrict__ w25,
    const float* __restrict__ w49, float* __restrict__ Tr, float* __restrict__ S)
{
    int bx = blockIdx.x;
    int n = (bx < 24) ? bx : (Nn - 48 + bx);
    int b = blockIdx.y;
    float a0 = alpha[0], a1 = alpha[1], a2 = alpha[2];
    float mx = fmaxf(a0, fmaxf(a1, a2));
    float e0 = __expf(a0-mx), e1 = __expf(a1-mx), e2 = __expf(a2-mx);
    float inv = 1.f/(e0+e1+e2);
    float wt0 = e0*inv, wt1 = e1*inv, wt2 = e2*inv;

    for (int d = threadIdx.x; d < Dm; d += 256) {
        float t7 = 0.f, t25 = 0.f, t49 = 0.f;
        #pragma unroll
        for (int j = 0; j < 7; j++) {
            int p = n + j - 3; p = p < 0 ? -p : (p >= Nn ? 2*Nn-2-p : p);
            t7 += w7[d*7+j] * x[((size_t)(b*Nn+p))*Dm + d];
        }
        #pragma unroll
        for (int j = 0; j < 25; j++) {
            int p = n + j - 12; p = p < 0 ? -p : (p >= Nn ? 2*Nn-2-p : p);
            t25 += w25[d*25+j] * x[((size_t)(b*Nn+p))*Dm + d];
        }
        #pragma unroll
        for (int j = 0; j < 49; j++) {
            int p = n + j - 24; p = p < 0 ? -p : (p >= Nn ? 2*Nn-2-p : p);
            t49 += w49[d*49+j] * x[((size_t)(b*Nn+p))*Dm + d];
        }
        float tr = wt0*t7 + wt1*t25 + wt2*t49;
        size_t idx = ((size_t)(b*Nn+n))*Dm + d;
        Tr[idx] = tr;
        S[idx]  = x[idx] - tr;
    }
}

// ---------------- one-pass LayerNorm (fp32 in, half out) ----------------
__global__ __launch_bounds__(256) void ln_kernel(
    const float* __restrict__ in, __half* __restrict__ out,
    const float* __restrict__ g, const float* __restrict__ b)
{
    __shared__ float red[8];
    int t = blockIdx.x, tid = threadIdx.x;
    int lane = tid & 31, warp = tid >> 5;
    const float4* row4 = (const float4*)(in + (size_t)t*Dm);
    float4 v = row4[tid];
    float s = v.x + v.y + v.z + v.w;
    #pragma unroll
    for (int o = 16; o; o >>= 1) s += __shfl_xor_sync(0xffffffff, s, o);
    if (lane == 0) red[warp] = s;
    __syncthreads();
    float tot = 0.f;
    #pragma unroll
    for (int i = 0; i < 8; i++) tot += red[i];
    float m = tot * (1.f/Dm);
    float dx = v.x-m, dy = v.y-m, dz = v.z-m, dw = v.w-m;
    float s2 = dx*dx + dy*dy + dz*dz + dw*dw;
    #pragma unroll
    for (int o = 16; o; o >>= 1) s2 += __shfl_xor_sync(0xffffffff, s2, o);
    __syncthreads();
    if (lane == 0) red[warp] = s2;
    __syncthreads();
    float tot2 = 0.f;
    #pragma unroll
    for (int i = 0; i < 8; i++) tot2 += red[i];
    float rinv = rsqrtf(tot2*(1.f/Dm) + 1e-5f);
    float4 gv = ((const float4*)g)[tid];
    float4 bv = ((const float4*)b)[tid];
    __half2* out2 = (__half2*)(out + (size_t)t*Dm);
    out2[2*tid]   = __floats2half2_rn(dx*rinv*gv.x + bv.x, dy*rinv*gv.y + bv.y);
    out2[2*tid+1] = __floats2half2_rn(dz*rinv*gv.z + bv.z, dw*rinv*gv.w + bv.w);
}

// ---------------- fp16 tensor-core GEMM core (half in, m16n8k16, double-buffered) ----------------
// MODE 0: half C = dot+bias ; MODE 1: float C = +res ; MODE 2: half C = gelu (rows<cN) ;
// MODE 3: float C = w*(dot+bias) (rows<cN)
template<int MODE>
__device__ __forceinline__ void gemm_core(
    const __half* __restrict__ A, const __half* __restrict__ W,
    const float* __restrict__ bias, const float* __restrict__ res,
    const float* __restrict__ wvec,
    void* __restrict__ Cv, int K, int O, int t0, int o0, int cN)
{
    __shared__ __align__(16) unsigned AsV[2*1056];
    __shared__ __align__(16) unsigned BsV[2*1056];
    int tid = threadIdx.x;
    int lane = tid & 31, warp = tid >> 5;
    int warp_m = warp >> 2, warp_n = warp & 3;   // 2 x 4 warps
    int gid = lane >> 2, tig = lane & 3;

    float acc[4][4][4];
    #pragma unroll
    for (int im = 0; im < 4; im++)
        #pragma unroll
        for (int in = 0; in < 4; in++)
            #pragma unroll
            for (int q = 0; q < 4; q++) acc[im][in][q] = 0.f;

    int lr = tid >> 1;            // row 0..127
    int hb = tid & 1;             // k-half 0/1 (of 16)
    int lc = hb*8;                // 8 halves = 16 bytes
    const __half* Ap = A + (size_t)(t0+lr)*K + lc;
    const __half* Bp = W + (size_t)(o0+lr)*K + lc;

    int grpA = ((lr >> 4) << 3) + (lr & 7);
    int pmA  = (lr >> 3) & 1;

    uint4 pa = *(const uint4*)Ap;
    uint4 pb = *(const uint4*)Bp;

    // pack tile 0 into buffer 0 (data is already half2-packed)
    {
        unsigned av[4] = {pa.x, pa.y, pa.z, pa.w};
        unsigned bv[4] = {pb.x, pb.y, pb.z, pb.w};
        #pragma unroll
        for (int j = 0; j < 4; j++) {
            AsV[(j*66 + grpA)*4 + pmA + 2*hb] = av[j];
            BsV[(j*132 + lr)*2 + hb]          = bv[j];
        }
    }
    __syncthreads();

    for (int kt = 0; kt < K; kt += 16) {
        int cur = (kt >> 4) & 1;
        bool more = (kt + 16 < K);
        if (more) {
            pa = *(const uint4*)(Ap + kt + 16);
            pb = *(const uint4*)(Bp + kt + 16);
        }
        // compute on buffer cur: one k16 step, 16 MMAs
        {
            unsigned af[4][4], bf[4][2];
            #pragma unroll
            for (int im = 0; im < 4; im++) {
                uint4 v = *(const uint4*)&AsV[cur*1056 + (tig*66 + (warp_m*4+im)*8 + gid)*4];
                af[im][0]=v.x; af[im][1]=v.y; af[im][2]=v.z; af[im][3]=v.w;
            }
            #pragma unroll
            for (int in = 0; in < 4; in++) {
                uint2 v = *(const uint2*)&BsV[cur*1056 + (tig*132 + warp_n*32 + in*8 + gid)*2];
                bf[in][0]=v.x; bf[in][1]=v.y;
            }
            #pragma unroll
            for (int im = 0; im < 4; im++)
                #pragma unroll
                for (int in = 0; in < 4; in++)
                    mma_f16(acc[im][in], af[im], bf[in]);
        }
        if (more) {
            int nb = cur ^ 1;
            unsigned av[4] = {pa.x, pa.y, pa.z, pa.w};
            unsigned bv[4] = {pb.x, pb.y, pb.z, pb.w};
            #pragma unroll
            for (int j = 0; j < 4; j++) {
                AsV[nb*1056 + (j*66 + grpA)*4 + pmA + 2*hb] = av[j];
                BsV[nb*1056 + (j*132 + lr)*2 + hb]          = bv[j];
            }
        }
        __syncthreads();
    }

    #pragma unroll
    for (int im = 0; im < 4; im++) {
        #pragma unroll
        for (int half = 0; half < 2; half++) {
            int row = t0 + warp_m*64 + im*16 + gid + half*8;
            if ((MODE == 2 || MODE == 3) && row >= cN) continue;
            float w = 0.f;
            if (MODE == 3) w = wvec[row];
            #pragma unroll
            for (int in = 0; in < 4; in++) {
                int col = o0 + warp_n*32 + in*8 + 2*tig;
                float v0 = acc[im][in][half*2+0] + bias[col];
                float v1 = acc[im][in][half*2+1] + bias[col+1];
                size_t idx = (size_t)row*O + col;
                if (MODE == 0) {
                    *(__half2*)&((__half*)Cv)[idx] = __floats2half2_rn(v0, v1);
                } else if (MODE == 1) {
                    float* C = (float*)Cv;
                    C[idx] = v0 + res[idx]; C[idx+1] = v1 + res[idx+1];
                } else if (MODE == 2) {
                    *(__half2*)&((__half*)Cv)[idx] = __floats2half2_rn(gelu_f(v0), gelu_f(v1));
                } else {
                    float* C = (float*)Cv;
                    C[idx] = w*v0; C[idx+1] = w*v1;
                }
            }
        }
    }
}

// ---- wrappers ----
__global__ __launch_bounds__(256, 2) void gemm_qkv(
    const __half* __restrict__ A,
    const __half* __restrict__ w0, const __half* __restrict__ w1, const __half* __restrict__ w2,
    const float* __restrict__ b0, const float* __restrict__ b1, const float* __restrict__ b2,
    __half* __restrict__ c0, __half* __restrict__ c1, __half* __restrict__ c2)
{
    int z = blockIdx.z;
    const __half* W = (z == 0) ? w0 : (z == 1) ? w1 : w2;
    const float* B = (z == 0) ? b0 : (z == 1) ? b1 : b2;
    __half* C = (z == 0) ? c0 : (z == 1) ? c1 : c2;
    gemm_core<0>(A, W, B, nullptr, nullptr, C, Dm, Dm,
                 blockIdx.y*128, blockIdx.x*128, 1 << 30);
}

__global__ __launch_bounds__(256, 2) void gemm_res(
    const __half* __restrict__ A, const __half* __restrict__ W,
    const float* __restrict__ bias, const float* __restrict__ res,
    float* __restrict__ C)
{
    gemm_core<1>(A, W, bias, res, nullptr, C, Dm, Dm,
                 blockIdx.y*128, blockIdx.x*128, 1 << 30);
}

__global__ __launch_bounds__(256, 2) void gemm_moe_up(
    const __half* __restrict__ Xe, const __half* __restrict__ ew1,
    const float* __restrict__ eb1, const int* __restrict__ cnt,
    __half* __restrict__ Hb)
{
    int e = blockIdx.z;
    int cN = cnt[e];
    int t0 = blockIdx.y*128;
    if (t0 >= cN) return;
    gemm_core<2>(Xe + (size_t)e*TT*Dm, ew1 + (size_t)e*MH*Dm, eb1 + (size_t)e*MH,
                 nullptr, nullptr, Hb + (size_t)e*TT*MH, Dm, MH,
                 t0, blockIdx.x*128, cN);
}

__global__ __launch_bounds__(256, 2) void gemm_moe_dn(
    const __half* __restrict__ Hb, const __half* __restrict__ ew2,
    const float* __restrict__ eb2, const int* __restrict__ cnt,
    const float* __restrict__ ewt, float* __restrict__ Oe)
{
    int e = blockIdx.z;
    int cN = cnt[e];
    int t0 = blockIdx.y*128;
    if (t0 >= cN) return;
    gemm_core<3>(Hb + (size_t)e*TT*MH, ew2 + (size_t)e*Dm*MH, eb2 + (size_t)e*Dm,
                 nullptr, ewt + (size_t)e*TT, Oe + (size_t)e*TT*Dm, MH, Dm,
                 t0, blockIdx.x*128, cN);
}

// ---------------- flash attention with fp16 MMA (m16n8k16, half I/O) ----------------
#define ATN_SH_FLOATS (4*2176 + 320)

__global__ __launch_bounds__(256) void attn_mma_kernel(
    const __half* __restrict__ Q, const __half* __restrict__ K,
    const __half* __restrict__ V, __half* __restrict__ Y)
{
    extern __shared__ __align__(16) unsigned ash[];
    unsigned* QsV = ash;
    unsigned* KsV = ash + 2176;
    unsigned* PsV = ash + 2*2176;
    unsigned* VsV = ash + 3*2176;
    float* mrow = (float*)(ash + 4*2176);
    float* lrow = mrow + 64;
    float* rrow = lrow + 64;
    float* cred = rrow + 64;

    int bh = blockIdx.y;
    int b = bh >> 4, h = bh & 15;
    int q0 = blockIdx.x * 64;
    int tid = threadIdx.x;
    int warp = tid >> 5, lane = tid & 31;
    int gid = lane >> 2, tig = lane & 3;
    int warp_m = warp >> 1, warp_n = warp & 1;
    float slope = exp2f(-0.5f * (float)(h+1));

    // load Q tile (half2 pairs of d, already packed)
    for (int i = tid; i < 64*32; i += 256) {
        int q = i >> 5, d = (i & 31)*2;
        unsigned u = *(const unsigned*)&Q[((size_t)(b*Nn + q0 + q))*Dm + h*64 + d];
        int b16 = d >> 4, khalf = (d >> 3) & 1, tg = (d >> 1) & 3;
        int grp = ((q >> 4) << 3) + (q & 7), rh = (q >> 3) & 1;
        QsV[((b16*4 + tg)*34 + grp)*4 + rh + 2*khalf] = u;
    }
    if (tid < 64) { mrow[tid] = -1e30f; lrow[tid] = 0.f; }

    float o_acc[4][4];
    #pragma unroll
    for (int in = 0; in < 4; in++)
        #pragma unroll
        for (int q = 0; q < 4; q++) o_acc[in][q] = 0.f;

    int qlo = warp_m*16 + gid, qhi = qlo + 8;
    int qglo = q0 + qlo, qghi = q0 + qhi;
    int grpP = warp_m*8 + gid;

    for (int kt = 0; kt < Nn; kt += 64) {
        __syncthreads();
        // K: half2 pairs of d per key row j
        for (int i = tid; i < 64*32; i += 256) {
            int j = i >> 5, d = (i & 31)*2;
            unsigned u = *(const unsigned*)&K[((size_t)(b*Nn + kt + j))*Dm + h*64 + d];
            int b16 = d >> 4, khalf = (d >> 3) & 1, tg = (d >> 1) & 3;
            KsV[((b16*4 + tg)*68 + j)*2 + khalf] = u;
        }
        // V: pairs of j per dim d
        for (int i = tid; i < 64*32; i += 256) {
            int d = i & 63, j = (i >> 6)*2;
            __half v0 = V[((size_t)(b*Nn + kt + j  ))*Dm + h*64 + d];
            __half v1 = V[((size_t)(b*Nn + kt + j+1))*Dm + h*64 + d];
            __half2 h2 = __halves2half2(v0, v1);
            int b16 = j >> 4, khalf = (j >> 3) & 1, tg = (j >> 1) & 3;
            VsV[((b16*4 + tg)*68 + d)*2 + khalf] = *reinterpret_cast<unsigned*>(&h2);
        }
        __syncthreads();

        float acc_s[4][4];
        #pragma unroll
        for (int in = 0; in < 4; in++)
            #pragma unroll
            for (int q = 0; q < 4; q++) acc_s[in][q] = 0.f;

        #pragma unroll
        for (int b16 = 0; b16 < 4; b16++) {
            uint4 afv = *(const uint4*)&QsV[((b16*4 + tig)*34 + grpP)*4];
            unsigned af[4] = {afv.x, afv.y, afv.z, afv.w};
            #pragma unroll
            for (int in = 0; in < 4; in++) {
                uint2 bfv = *(const uint2*)&KsV[((b16*4 + tig)*68 + warp_n*32 + in*8 + gid)*2];
                unsigned bf[2] = {bfv.x, bfv.y};
                mma_f16(acc_s[in], af, bf);
            }
        }

        float rmax0 = -1e30f, rmax1 = -1e30f;
        #pragma unroll
        for (int in = 0; in < 4; in++) {
            #pragma unroll
            for (int c2 = 0; c2 < 2; c2++) {
                int kg = kt + warp_n*32 + in*8 + 2*tig + c2;
                float d0 = (kg > qglo) ? (float)(kg - qglo) : 0.f;
                float d1 = (kg > qghi) ? (float)(kg - qghi) : 0.f;
                acc_s[in][c2]   = acc_s[in][c2]  *0.125f - slope*d0;
                acc_s[in][c2+2] = acc_s[in][c2+2]*0.125f - slope*d1;
                rmax0 = fmaxf(rmax0, acc_s[in][c2]);
                rmax1 = fmaxf(rmax1, acc_s[in][c2+2]);
            }
        }
        rmax0 = fmaxf(rmax0, __shfl_xor_sync(0xffffffff, rmax0, 1));
        rmax0 = fmaxf(rmax0, __shfl_xor_sync(0xffffffff, rmax0, 2));
        rmax1 = fmaxf(rmax1, __shfl_xor_sync(0xffffffff, rmax1, 1));
        rmax1 = fmaxf(rmax1, __shfl_xor_sync(0xffffffff, rmax1, 2));
        if (tig == 0) {
            cred[warp_n*64 + qlo] = rmax0;
            cred[warp_n*64 + qhi] = rmax1;
        }
        __syncthreads();
        if (tid < 64) {
            float mo = mrow[tid];
            float mn = fmaxf(mo, fmaxf(cred[tid], cred[64+tid]));
            mrow[tid] = mn;
            rrow[tid] = __expf(mo - mn);
        }
        __syncthreads();

        float mn0 = mrow[qlo], mn1 = mrow[qhi];
        float r0 = rrow[qlo], r1 = rrow[qhi];
        float rs0 = 0.f, rs1 = 0.f;
        #pragma unroll
        for (int in = 0; in < 4; in++) {
            float p00 = __expf(acc_s[in][0] - mn0);
            float p01 = __expf(acc_s[in][1] - mn0);
            float p10 = __expf(acc_s[in][2] - mn1);
            float p11 = __expf(acc_s[in][3] - mn1);
            rs0 += p00 + p01; rs1 += p10 + p11;
            int b16k = warp_n*2 + (in >> 1);
            int khalf = in & 1;
            PsV[((b16k*4 + tig)*34 + grpP)*4 + 0 + 2*khalf] = pack_h2(p00, p01);
            PsV[((b16k*4 + tig)*34 + grpP)*4 + 1 + 2*khalf] = pack_h2(p10, p11);
        }
        rs0 += __shfl_xor_sync(0xffffffff, rs0, 1);
        rs0 += __shfl_xor_sync(0xffffffff, rs0, 2);
        rs1 += __shfl_xor_sync(0xffffffff, rs1, 1);
        rs1 += __shfl_xor_sync(0xffffffff, rs1, 2);
        if (tig == 0) {
            cred[warp_n*64 + qlo] = rs0;
            cred[warp_n*64 + qhi] = rs1;
        }
        #pragma unroll
        for (int in = 0; in < 4; in++) {
            o_acc[in][0] *= r0; o_acc[in][1] *= r0;
            o_acc[in][2] *= r1; o_acc[in][3] *= r1;
        }
        __syncthreads();
        if (tid < 64) lrow[tid] = lrow[tid]*rrow[tid] + cred[tid] + cred[64+tid];

        #pragma unroll
        for (int b16 = 0; b16 < 4; b16++) {
            uint4 afv = *(const uint4*)&PsV[((b16*4 + tig)*34 + grpP)*4];
            unsigned af[4] = {afv.x, afv.y, afv.z, afv.w};
            #pragma unroll
            for (int in = 0; in < 4; in++) {
                uint2 bfv = *(const uint2*)&VsV[((b16*4 + tig)*68 + warp_n*32 + in*8 + gid)*2];
                unsigned bf[2] = {bfv.x, bfv.y};
                mma_f16(o_acc[in], af, bf);
            }
        }
    }
    __syncthreads();

    float inv0 = 1.f / lrow[qlo];
    float inv1 = 1.f / lrow[qhi];
    #pragma unroll
    for (int in = 0; in < 4; in++) {
        int col = h*64 + warp_n*32 + in*8 + 2*tig;
        *(__half2*)&Y[((size_t)(b*Nn + qglo))*Dm + col] =
            __floats2half2_rn(o_acc[in][0]*inv0, o_acc[in][1]*inv0);
        *(__half2*)&Y[((size_t)(b*Nn + qghi))*Dm + col] =
            __floats2half2_rn(o_acc[in][2]*inv1, o_acc[in][3]*inv1);
    }
}

// ---------------- router (half activations) ----------------
__global__ __launch_bounds__(128) void router_kernel(
    const __half* __restrict__ xf, const float* __restrict__ rw,
    float* __restrict__ Wout, float* __restrict__ Aux)
{
    int t = blockIdx.x;
    int warp = threadIdx.x >> 5, lane = threadIdx.x & 31;
    __shared__ float sg[NE];
    const __half* xrow = xf + (size_t)t*Dm;
    float s = 0.f;
    for (int i = lane; i < Dm; i += 32) s += __half2float(xrow[i])*rw[(size_t)warp*Dm + i];
    #pragma unroll
    for (int o = 16; o; o >>= 1) s += __shfl_xor_sync(0xffffffff, s, o);
    if (lane == 0) sg[warp] = s;
    __syncthreads();
    if (threadIdx.x == 0) {
        float m = fmaxf(fmaxf(sg[0],sg[1]), fmaxf(sg[2],sg[3]));
        float e[NE], sum = 0.f;
        #pragma unroll
        for (int i = 0; i < NE; i++) { e[i] = __expf(sg[i]-m); sum += e[i]; }
        float gate[NE];
        #pragma unroll
        for (int i = 0; i < NE; i++) gate[i] = e[i]/sum;
        int i0 = 0;
        #pragma unroll
        for (int i = 1; i < NE; i++) if (gate[i] > gate[i0]) i0 = i;
        int i1 = -1;
        #pragma unroll
        for (int i = 0; i < NE; i++) if (i != i0 && (i1 < 0 || gate[i] > gate[i1])) i1 = i;
        float s2 = fmaxf(gate[i0] + gate[i1], 1e-9f);
        #pragma unroll
        for (int i = 0; i < NE; i++) Wout[(size_t)t*NE + i] = 0.f;
        Wout[(size_t)t*NE + i0] = gate[i0]/s2;
        Wout[(size_t)t*NE + i1] = gate[i1]/s2;
        #pragma unroll
        for (int i = 0; i < NE; i++) atomicAdd(&Aux[i], gate[i]);
        atomicAdd(&Aux[NE + i0], 1.f);
        atomicAdd(&Aux[NE + i1], 1.f);
    }
}

// ---------------- MoE assignment / gather ----------------
__global__ __launch_bounds__(256) void assign_kernel(
    const float* __restrict__ Wt, int* __restrict__ cnt,
    int* __restrict__ eidx, float* __restrict__ ewt, int* __restrict__ tinv)
{
    int t = blockIdx.x*256 + threadIdx.x;
    if (t >= TT) return;
    int s = 0;
    #pragma unroll
    for (int e = 0; e < NE; e++) {
        float w = Wt[(size_t)t*NE + e];
        if (w != 0.f) {
            int pos = atomicAdd(&cnt[e], 1);
            eidx[e*TT + pos] = t;
            ewt [e*TT + pos] = w;
            tinv[t*2 + s] = e*TT + pos;
            s++;
        }
    }
}

__global__ __launch_bounds__(256) void gather_kernel(
    const __half* __restrict__ xf, const int* __restrict__ cnt,
    const int* __restrict__ eidx, __half* __restrict__ Xe)
{
    int e = blockIdx.y, row = blockIdx.x;
    int c = cnt[e];
    if (row >= c) return;
    uint2* dst = (uint2*)(Xe + ((size_t)e*TT + row)*Dm);
    const uint2* src = (const uint2*)(xf + (size_t)eidx[e*TT + row]*Dm);
    dst[threadIdx.x] = src[threadIdx.x];
}

// ---------------- final (fused MoE combine + trend conv + residual) ----------------
__global__ __launch_bounds__(256) void final_kernel(
    const float* __restrict__ tw, const float* __restrict__ tb,
    const float* __restrict__ Tr, const float* __restrict__ XS,
    const int* __restrict__ tinv, const float* __restrict__ Oe,
    float* __restrict__ out)
{
    int n = blockIdx.x, b = blockIdx.y;
    int t = b*Nn + n;
    int i0 = tinv[t*2], i1 = tinv[t*2+1];
    const float* oe0 = Oe + (size_t)i0*Dm;
    const float* oe1 = Oe + (size_t)i1*Dm;
    for (int d = threadIdx.x; d < Dm; d += 256) {
        float acc = tb[d];
        #pragma unroll
        for (int j = 0; j < 5; j++) {
            int p = n + j - 2;
            if (p >= 0 && p < Nn) acc += tw[d*5+j] * Tr[((size_t)(b*Nn+p))*Dm + d];
        }
        size_t idx = (size_t)t*Dm + d;
        out[idx] = XS[idx] + oe0[d] + oe1[d] + acc;
    }
}

__global__ void zero_aux_kernel(float* Aux, int* cnt) {
    if (threadIdx.x < 2*NE) Aux[threadIdx.x] = 0.f;
    if (threadIdx.x < NE) cnt[threadIdx.x] = 0;
}

__global__ void aux_write_kernel(const float* Aux, float* out, int out_size) {
    if (out_size > TT*Dm) {
        float a = 0.f;
        #pragma unroll
        for (int e = 0; e < NE; e++)
            a += (Aux[e]/(float)TT) * (Aux[NE+e]/(float)TT);
        out[TT*Dm] = (float)NE * a;
    }
}

// ---------------- launcher ----------------
extern "C" void kernel_launch(void* const* d_in, const int* in_sizes, int n_in,
                              void* d_out, int out_size)
{
    const float* x    = (const float*)d_in[0];
    const float* qw   = (const float*)d_in[1];
    const float* qb   = (const float*)d_in[2];
    const float* kw   = (const float*)d_in[3];
    const float* kb   = (const float*)d_in[4];
    const float* vw   = (const float*)d_in[5];
    const float* vb   = (const float*)d_in[6];
    const float* ow   = (const float*)d_in[7];
    const float* ob   = (const float*)d_in[8];
    const float* n1g  = (const float*)d_in[9];
    const float* n1b  = (const float*)d_in[10];
    const float* n2g  = (const float*)d_in[11];
    const float* n2b  = (const float*)d_in[12];
    const float* alpha= (const float*)d_in[13];
    const float* dw7  = (const float*)d_in[14];
    const float* dw25 = (const float*)d_in[15];
    const float* dw49 = (const float*)d_in[16];
    const float* rw   = (const float*)d_in[17];
    const float* ew1  = (const float*)d_in[18];
    const float* eb1  = (const float*)d_in[19];
    const float* ew2  = (const float*)d_in[20];
    const float* eb2  = (const float*)d_in[21];
    const float* tw   = (const float*)d_in[22];
    const float* tb   = (const float*)d_in[23];
    float* out = (float*)d_out;

    float *Tr,*S,*XS,*Oe,*Wt,*Ewt,*Aux,*Ck;
    __half *hSn,*hQ,*hK,*hV,*hY,*hH,*hXe,*hQw,*hKw,*hVw,*hOw,*hE1,*hE2;
    int *Eidx,*Cnt,*Tinv;
    cudaGetSymbolAddress((void**)&Tr,  g_Tr);
    cudaGetSymbolAddress((void**)&S,   g_S);
    cudaGetSymbolAddress((void**)&XS,  g_XS);
    cudaGetSymbolAddress((void**)&Oe,  g_Oe);
    cudaGetSymbolAddress((void**)&Wt,  g_W);
    cudaGetSymbolAddress((void**)&Ewt, g_Ewt);
    cudaGetSymbolAddress((void**)&Aux, g_Aux);
    cudaGetSymbolAddress((void**)&Ck,  g_Ck);
    cudaGetSymbolAddress((void**)&hSn, g_hSn);
    cudaGetSymbolAddress((void**)&hQ,  g_hQ);
    cudaGetSymbolAddress((void**)&hK,  g_hK);
    cudaGetSymbolAddress((void**)&hV,  g_hV);
    cudaGetSymbolAddress((void**)&hY,  g_hY);
    cudaGetSymbolAddress((void**)&hH,  g_hH);
    cudaGetSymbolAddress((void**)&hXe, g_hXe);
    cudaGetSymbolAddress((void**)&hQw, g_hQw);
    cudaGetSymbolAddress((void**)&hKw, g_hKw);
    cudaGetSymbolAddress((void**)&hVw, g_hVw);
    cudaGetSymbolAddress((void**)&hOw, g_hOw);
    cudaGetSymbolAddress((void**)&hE1, g_hE1);
    cudaGetSymbolAddress((void**)&hE2, g_hE2);
    cudaGetSymbolAddress((void**)&Eidx,g_Eidx);
    cudaGetSymbolAddress((void**)&Cnt, g_Cnt);
    cudaGetSymbolAddress((void**)&Tinv,g_Tinv);

    const int ATN_SH_BYTES = ATN_SH_FLOATS * 4;
    cudaFuncSetAttribute(attn_mma_kernel, cudaFuncAttributeMaxDynamicSharedMemorySize, ATN_SH_BYTES);

    zero_aux_kernel<<<1, 32>>>(Aux, Cnt);
    // weight conversion (once per call; overlaps decomposition)
    const int NW4 = (Dm*Dm)/4, NE14 = (NE*MH*Dm)/4;
    cvt_kernel<<<(NW4+255)/256, 256>>>(qw, hQw, NW4);
    cvt_kernel<<<(NW4+255)/256, 256>>>(kw, hKw, NW4);
    cvt_kernel<<<(NW4+255)/256, 256>>>(vw, hVw, NW4);
    cvt_kernel<<<(NW4+255)/256, 256>>>(ow, hOw, NW4);
    cvt_kernel<<<(NE14+255)/256, 256>>>(ew1, hE1, NE14);
    cvt_kernel<<<(NE14+255)/256, 256>>>(ew2, hE2, NE14);

    ckbuild_kernel<<<Dm, 64>>>(alpha, dw7, dw25, dw49, Ck);
    trend_kernel<<<dim3(61, Bz, Dm/128), 256>>>(x, Ck, Tr, S);
    decomp_edge_kernel<<<dim3(48, Bz), 256>>>(x, alpha, dw7, dw25, dw49, Tr, S);
    ln_kernel<<<TT, 256>>>(S, hSn, n1g, n1b);

    gemm_qkv<<<dim3(Dm/128, TT/128, 3), 256>>>(hSn, hQw, hKw, hVw, qb, kb, vb, hQ, hK, hV);

    attn_mma_kernel<<<dim3(Nn/64, Bz*Hh), 256, ATN_SH_BYTES>>>(hQ, hK, hV, hY);

    gemm_res<<<dim3(Dm/128, TT/128), 256>>>(hY, hOw, ob, S, XS);
    ln_kernel<<<TT, 256>>>(XS, hSn, n2g, n2b);
    router_kernel<<<TT, 128>>>(hSn, rw, Wt, Aux);
    assign_kernel<<<TT/256, 256>>>(Wt, Cnt, Eidx, Ewt, Tinv);
    gather_kernel<<<dim3(TT, NE), 256>>>(hSn, Cnt, Eidx, hXe);

    gemm_moe_up<<<dim3(MH/128, TT/128, NE), 256>>>(hXe, hE1, eb1, Cnt, hH);
    gemm_moe_dn<<<dim3(Dm/128, TT/128, NE), 256>>>(hH, hE2, eb2, Cnt, Ewt, Oe);

    final_kernel<<<dim3(Nn, Bz), 256>>>(tw, tb, Tr, XS, Tinv, Oe, out);
    aux_write_kernel<<<1, 1>>>(Aux, out, out_size);
}

// round 11
// speedup vs baseline: 11.4081x; 1.2809x over previous
#include <cuda_runtime.h>
#include <cuda_fp16.h>
#include <math.h>
#include <stdint.h>

#define Bz 8
#define Nn 1024
#define Dm 1024
#define Hh 16
#define HD 64
#define TT (Bz*Nn)       // 8192 tokens
#define MH 2048
#define NE 4

// ---------------- static device scratch (no allocation allowed) ----------------
__device__ float  g_Tr[(size_t)TT*Dm];
__device__ float  g_S [(size_t)TT*Dm];
__device__ float  g_XS[(size_t)TT*Dm];
__device__ float  g_Oe[(size_t)NE*TT*Dm];
__device__ float  g_W [(size_t)TT*NE];
__device__ float  g_Ck[(size_t)Dm*49];
__device__ __align__(16) __half g_hSn[(size_t)TT*Dm];
__device__ __align__(16) __half g_hQ [(size_t)TT*Dm];
__device__ __align__(16) __half g_hK [(size_t)TT*Dm];
__device__ __align__(16) __half g_hV [(size_t)TT*Dm];
__device__ __align__(16) __half g_hY [(size_t)TT*Dm];
__device__ __align__(16) __half g_hH [(size_t)NE*TT*MH];
__device__ __align__(16) __half g_hXe[(size_t)NE*TT*Dm];
__device__ __align__(16) __half g_hQw[(size_t)Dm*Dm];
__device__ __align__(16) __half g_hKw[(size_t)Dm*Dm];
__device__ __align__(16) __half g_hVw[(size_t)Dm*Dm];
__device__ __align__(16) __half g_hOw[(size_t)Dm*Dm];
__device__ __align__(16) __half g_hE1[(size_t)NE*MH*Dm];
__device__ __align__(16) __half g_hE2[(size_t)NE*Dm*MH];
__device__ int    g_Eidx[NE*TT];
__device__ float  g_Ewt [NE*TT];
__device__ int    g_Tinv[TT*2];
__device__ int    g_Cnt[NE];
__device__ float  g_Aux[2*NE];

// ---------------- ptx helpers ----------------
__device__ __forceinline__ uint32_t smem_u32(const void* p) {
    uint32_t a;
    asm("{ .reg .u64 t; cvta.to.shared.u64 t, %1; cvt.u32.u64 %0, t; }" : "=r"(a) : "l"(p));
    return a;
}
__device__ __forceinline__ unsigned pack_h2(float lo, float hi) {
    __half2 h = __floats2half2_rn(lo, hi);
    return *reinterpret_cast<unsigned*>(&h);
}
__device__ __forceinline__ void mma_f16(float* c, const unsigned* a, const unsigned* b) {
    asm volatile(
        "mma.sync.aligned.m16n8k16.row.col.f32.f16.f16.f32 "
        "{%0,%1,%2,%3}, {%4,%5,%6,%7}, {%8,%9}, {%0,%1,%2,%3};\n"
        : "+f"(c[0]), "+f"(c[1]), "+f"(c[2]), "+f"(c[3])
        : "r"(a[0]), "r"(a[1]), "r"(a[2]), "r"(a[3]), "r"(b[0]), "r"(b[1]));
}
__device__ __forceinline__ void cp16(uint32_t dst, const void* src) {
    asm volatile("cp.async.cg.shared.global [%0], [%1], 16;\n" :: "r"(dst), "l"(src));
}
#define CP_COMMIT() asm volatile("cp.async.commit_group;\n" ::: "memory")
#define CP_WAIT2()  asm volatile("cp.async.wait_group 2;\n" ::: "memory")
__device__ __forceinline__ void ldm_x4(unsigned& r0, unsigned& r1, unsigned& r2, unsigned& r3,
                                       uint32_t addr) {
    asm volatile("ldmatrix.sync.aligned.m8n8.x4.shared.b16 {%0,%1,%2,%3}, [%4];"
                 : "=r"(r0), "=r"(r1), "=r"(r2), "=r"(r3) : "r"(addr));
}

__device__ __forceinline__ float gelu_f(float v) {
    return 0.5f*v*(1.0f + erff(v*0.70710678118654752f));
}

// ---------------- fp32 -> fp16 weight conversion ----------------
__global__ __launch_bounds__(256) void cvt_kernel(
    const float* __restrict__ src, __half* __restrict__ dst, int n4)
{
    int i = blockIdx.x*256 + threadIdx.x;
    if (i >= n4) return;
    float4 v = ((const float4*)src)[i];
    ((__half2*)dst)[2*i]   = __floats2half2_rn(v.x, v.y);
    ((__half2*)dst)[2*i+1] = __floats2half2_rn(v.z, v.w);
}

// ---------------- combined decomposition kernel build ----------------
__global__ void ckbuild_kernel(
    const float* __restrict__ alpha, const float* __restrict__ w7,
    const float* __restrict__ w25, const float* __restrict__ w49,
    float* __restrict__ ck)
{
    int d = blockIdx.x, j = threadIdx.x;
    if (j >= 49) return;
    float a0 = alpha[0], a1 = alpha[1], a2 = alpha[2];
    float mx = fmaxf(a0, fmaxf(a1, a2));
    float e0 = __expf(a0-mx), e1 = __expf(a1-mx), e2 = __expf(a2-mx);
    float inv = 1.f/(e0+e1+e2);
    float wt0 = e0*inv, wt1 = e1*inv, wt2 = e2*inv;
    float v = wt2 * w49[d*49 + j];
    if (j >= 12 && j < 37) v += wt1 * w25[d*25 + (j-12)];
    if (j >= 21 && j < 28) v += wt0 * w7[d*7 + (j-21)];
    ck[d*49 + j] = v;
}

// ---------------- interior trend ----------------
__global__ __launch_bounds__(256) void trend_kernel(
    const float* __restrict__ x, const float* __restrict__ ck,
    float* __restrict__ Tr, float* __restrict__ S)
{
    __shared__ float xs[64][128];
    int b = blockIdx.y;
    int n0 = 24 + blockIdx.x * 16;
    int d0 = blockIdx.z * 128;
    int tid = threadIdx.x;
    int dl = tid & 127, ng = tid >> 7;

    for (int i = tid; i < 64*32; i += 256) {
        int p = i >> 5, c = i & 31;
        *(float4*)&xs[p][c*4] =
            *(const float4*)&x[((size_t)(b*Nn + n0 - 24 + p))*Dm + d0 + c*4];
    }
    __syncthreads();

    float ckr[49];
    #pragma unroll
    for (int j = 0; j < 49; j++) ckr[j] = __ldg(&ck[(size_t)(d0+dl)*49 + j]);

    float acc[8];
    #pragma unroll
    for (int j = 0; j < 8; j++) acc[j] = 0.f;

    #pragma unroll
    for (int pr = 0; pr < 56; pr++) {
        float xv = xs[ng*8 + pr][dl];
        #pragma unroll
        for (int j = 0; j < 8; j++) {
            int t = pr - j;
            if (t >= 0 && t < 49) acc[j] += ckr[t] * xv;
        }
    }

    #pragma unroll
    for (int j = 0; j < 8; j++) {
        int nl = ng*8 + j;
        size_t idx = ((size_t)(b*Nn + n0 + nl))*Dm + d0 + dl;
        float xval = xs[nl + 24][dl];
        Tr[idx] = acc[j];
        S[idx]  = xval - acc[j];
    }
}

// ---------------- boundary decomposition ----------------
__global__ __launch_bounds__(256) void decomp_edge_kernel(
    const float* __restrict__ x, const float* __restrict__ alpha,
    const float* __restrict__ w7, const float* __restrict__ w25,
    const float* __restrict__ w49, float* __restrict__ Tr, float* __restrict__ S)
{
    int bx = blockIdx.x;
    int n = (bx < 24) ? bx : (Nn - 48 + bx);
    int b = blockIdx.y;
    float a0 = alpha[0], a1 = alpha[1], a2 = alpha[2];
    float mx = fmaxf(a0, fmaxf(a1, a2));
    float e0 = __expf(a0-mx), e1 = __expf(a1-mx), e2 = __expf(a2-mx);
    float inv = 1.f/(e0+e1+e2);
    float wt0 = e0*inv, wt1 = e1*inv, wt2 = e2*inv;

    for (int d = threadIdx.x; d < Dm; d += 256) {
        float t7 = 0.f, t25 = 0.f, t49 = 0.f;
        #pragma unroll
        for (int j = 0; j < 7; j++) {
            int p = n + j - 3; p = p < 0 ? -p : (p >= Nn ? 2*Nn-2-p : p);
            t7 += w7[d*7+j] * x[((size_t)(b*Nn+p))*Dm + d];
        }
        #pragma unroll
        for (int j = 0; j < 25; j++) {
            int p = n + j - 12; p = p < 0 ? -p : (p >= Nn ? 2*Nn-2-p : p);
            t25 += w25[d*25+j] * x[((size_t)(b*Nn+p))*Dm + d];
        }
        #pragma unroll
        for (int j = 0; j < 49; j++) {
            int p = n + j - 24; p = p < 0 ? -p : (p >= Nn ? 2*Nn-2-p : p);
            t49 += w49[d*49+j] * x[((size_t)(b*Nn+p))*Dm + d];
        }
        float tr = wt0*t7 + wt1*t25 + wt2*t49;
        size_t idx = ((size_t)(b*Nn+n))*Dm + d;
        Tr[idx] = tr;
        S[idx]  = x[idx] - tr;
    }
}

// ---------------- one-pass LayerNorm (fp32 in, half out) ----------------
__global__ __launch_bounds__(256) void ln_kernel(
    const float* __restrict__ in, __half* __restrict__ out,
    const float* __restrict__ g, const float* __restrict__ b)
{
    __shared__ float red[8];
    int t = blockIdx.x, tid = threadIdx.x;
    int lane = tid & 31, warp = tid >> 5;
    const float4* row4 = (const float4*)(in + (size_t)t*Dm);
    float4 v = row4[tid];
    float s = v.x + v.y + v.z + v.w;
    #pragma unroll
    for (int o = 16; o; o >>= 1) s += __shfl_xor_sync(0xffffffff, s, o);
    if (lane == 0) red[warp] = s;
    __syncthreads();
    float tot = 0.f;
    #pragma unroll
    for (int i = 0; i < 8; i++) tot += red[i];
    float m = tot * (1.f/Dm);
    float dx = v.x-m, dy = v.y-m, dz = v.z-m, dw = v.w-m;
    float s2 = dx*dx + dy*dy + dz*dz + dw*dw;
    #pragma unroll
    for (int o = 16; o; o >>= 1) s2 += __shfl_xor_sync(0xffffffff, s2, o);
    __syncthreads();
    if (lane == 0) red[warp] = s2;
    __syncthreads();
    float tot2 = 0.f;
    #pragma unroll
    for (int i = 0; i < 8; i++) tot2 += red[i];
    float rinv = rsqrtf(tot2*(1.f/Dm) + 1e-5f);
    float4 gv = ((const float4*)g)[tid];
    float4 bv = ((const float4*)b)[tid];
    __half2* out2 = (__half2*)(out + (size_t)t*Dm);
    out2[2*tid]   = __floats2half2_rn(dx*rinv*gv.x + bv.x, dy*rinv*gv.y + bv.y);
    out2[2*tid+1] = __floats2half2_rn(dz*rinv*gv.z + bv.z, dw*rinv*gv.w + bv.w);
}

// ---------------- fp16 GEMM core: cp.async 3-stage + ldmatrix ----------------
// tiles 128x128, BK=32 halves (64B rows), swizzle: c16 ^= (row>>1)&3
// MODE 0: half C = dot+bias ; MODE 1: float C = +res ; MODE 2: half C = gelu (rows<cN) ;
// MODE 3: float C = w*(dot+bias) (rows<cN)
#define GSTAGES 3
#define GSTAGE_BYTES 16384          // A 8KB + B 8KB

template<int MODE>
__device__ __forceinline__ void gemm_core(
    const __half* __restrict__ A, const __half* __restrict__ W,
    const float* __restrict__ bias, const float* __restrict__ res,
    const float* __restrict__ wvec,
    void* __restrict__ Cv, int K, int O, int t0, int o0, int cN)
{
    __shared__ __align__(16) char sm[GSTAGES*GSTAGE_BYTES];
    int tid = threadIdx.x;
    int lane = tid & 31, warp = tid >> 5;
    int warp_m = warp >> 2, warp_n = warp & 3;   // 2 x 4 warps
    int gid = lane >> 2, tig = lane & 3;

    float acc[4][4][4];
    #pragma unroll
    for (int im = 0; im < 4; im++)
        #pragma unroll
        for (int in = 0; in < 4; in++)
            #pragma unroll
            for (int q = 0; q < 4; q++) acc[im][in][q] = 0.f;

    uint32_t smb = smem_u32(sm);

    // loader: 512 16B chunks per operand tile; thread handles chunks tid, tid+256
    int r0c = tid >> 2, c0c = tid & 3;
    int r1c = (tid + 256) >> 2, c1c = tid & 3;  // (tid+256)&3 == tid&3
    uint32_t dA0 = (uint32_t)(r0c*64 + ((c0c ^ ((r0c>>1)&3))*16));
    uint32_t dA1 = (uint32_t)(r1c*64 + ((c1c ^ ((r1c>>1)&3))*16));
    const __half* Abase = A + (size_t)t0*K;
    const __half* Bbase = W + (size_t)o0*K;
    const __half* srcA0 = Abase + (size_t)r0c*K + c0c*8;
    const __half* srcA1 = Abase + (size_t)r1c*K + c1c*8;
    const __half* srcB0 = Bbase + (size_t)r0c*K + c0c*8;
    const __half* srcB1 = Bbase + (size_t)r1c*K + c1c*8;

    int nt = K >> 5;

    // prologue: stages 0..2
    #pragma unroll
    for (int s = 0; s < GSTAGES; s++) {
        uint32_t ba = smb + s*GSTAGE_BYTES;
        uint32_t bb = ba + 8192;
        int ko = s*32;
        cp16(ba + dA0, srcA0 + ko);
        cp16(ba + dA1, srcA1 + ko);
        cp16(bb + dA0, srcB0 + ko);
        cp16(bb + dA1, srcB1 + ko);
        CP_COMMIT();
    }

    // ldmatrix per-lane address prep
    int rA[4], swA[4];
    #pragma unroll
    for (int im = 0; im < 4; im++) {
        rA[im] = warp_m*64 + im*16 + (lane & 7) + 8*((lane >> 3) & 1);
        swA[im] = (rA[im] >> 1) & 3;
    }
    int kbA = (lane >> 4) & 1;
    int rB[2], swB[2];
    #pragma unroll
    for (int ip = 0; ip < 2; ip++) {
        rB[ip] = warp_n*32 + ip*16 + 8*((lane >> 4) & 1) + (lane & 7);
        swB[ip] = (rB[ip] >> 1) & 3;
    }
    int kbB = (lane >> 3) & 1;

    for (int t = 0; t < nt; t++) {
        int st = t % GSTAGES;
        uint32_t ba = smb + st*GSTAGE_BYTES;
        uint32_t bb = ba + 8192;
        CP_WAIT2();
        __syncthreads();

        #pragma unroll
        for (int s16 = 0; s16 < 2; s16++) {
            unsigned af[4][4], bf[4][2];
            #pragma unroll
            for (int im = 0; im < 4; im++) {
                uint32_t addr = ba + rA[im]*64 + (((2*s16 + kbA) ^ swA[im])*16);
                ldm_x4(af[im][0], af[im][1], af[im][2], af[im][3], addr);
            }
            #pragma unroll
            for (int ip = 0; ip < 2; ip++) {
                uint32_t addr = bb + rB[ip]*64 + (((2*s16 + kbB) ^ swB[ip])*16);
                ldm_x4(bf[2*ip][0], bf[2*ip][1], bf[2*ip+1][0], bf[2*ip+1][1], addr);
            }
            #pragma unroll
            for (int im = 0; im < 4; im++)
                #pragma unroll
                for (int in = 0; in < 4; in++)
                    mma_f16(acc[im][in], af[im], bf[in]);
        }
        __syncthreads();

        int tn = t + GSTAGES;
        if (tn < nt) {
            int ko = tn*32;
            cp16(ba + dA0, srcA0 + ko);
            cp16(ba + dA1, srcA1 + ko);
            cp16(bb + dA0, srcB0 + ko);
            cp16(bb + dA1, srcB1 + ko);
        }
        CP_COMMIT();
    }

    #pragma unroll
    for (int im = 0; im < 4; im++) {
        #pragma unroll
        for (int half = 0; half < 2; half++) {
            int row = t0 + warp_m*64 + im*16 + gid + half*8;
            if ((MODE == 2 || MODE == 3) && row >= cN) continue;
            float w = 0.f;
            if (MODE == 3) w = wvec[row];
            #pragma unroll
            for (int in = 0; in < 4; in++) {
                int col = o0 + warp_n*32 + in*8 + 2*tig;
                float v0 = acc[im][in][half*2+0] + bias[col];
                float v1 = acc[im][in][half*2+1] + bias[col+1];
                size_t idx = (size_t)row*O + col;
                if (MODE == 0) {
                    *(__half2*)&((__half*)Cv)[idx] = __floats2half2_rn(v0, v1);
                } else if (MODE == 1) {
                    float* C = (float*)Cv;
                    C[idx] = v0 + res[idx]; C[idx+1] = v1 + res[idx+1];
                } else if (MODE == 2) {
                    *(__half2*)&((__half*)Cv)[idx] = __floats2half2_rn(gelu_f(v0), gelu_f(v1));
                } else {
                    float* C = (float*)Cv;
                    C[idx] = w*v0; C[idx+1] = w*v1;
                }
            }
        }
    }
}

// ---- wrappers ----
__global__ __launch_bounds__(256, 2) void gemm_qkv(
    const __half* __restrict__ A,
    const __half* __restrict__ w0, const __half* __restrict__ w1, const __half* __restrict__ w2,
    const float* __restrict__ b0, const float* __restrict__ b1, const float* __restrict__ b2,
    __half* __restrict__ c0, __half* __restrict__ c1, __half* __restrict__ c2)
{
    int z = blockIdx.z;
    const __half* W = (z == 0) ? w0 : (z == 1) ? w1 : w2;
    const float* B = (z == 0) ? b0 : (z == 1) ? b1 : b2;
    __half* C = (z == 0) ? c0 : (z == 1) ? c1 : c2;
    gemm_core<0>(A, W, B, nullptr, nullptr, C, Dm, Dm,
                 blockIdx.y*128, blockIdx.x*128, 1 << 30);
}

__global__ __launch_bounds__(256, 2) void gemm_res(
    const __half* __restrict__ A, const __half* __restrict__ W,
    const float* __restrict__ bias, const float* __restrict__ res,
    float* __restrict__ C)
{
    gemm_core<1>(A, W, bias, res, nullptr, C, Dm, Dm,
                 blockIdx.y*128, blockIdx.x*128, 1 << 30);
}

__global__ __launch_bounds__(256, 2) void gemm_moe_up(
    const __half* __restrict__ Xe, const __half* __restrict__ ew1,
    const float* __restrict__ eb1, const int* __restrict__ cnt,
    __half* __restrict__ Hb)
{
    int e = blockIdx.z;
    int cN = cnt[e];
    int t0 = blockIdx.y*128;
    if (t0 >= cN) return;
    gemm_core<2>(Xe + (size_t)e*TT*Dm, ew1 + (size_t)e*MH*Dm, eb1 + (size_t)e*MH,
                 nullptr, nullptr, Hb + (size_t)e*TT*MH, Dm, MH,
                 t0, blockIdx.x*128, cN);
}

__global__ __launch_bounds__(256, 2) void gemm_moe_dn(
    const __half* __restrict__ Hb, const __half* __restrict__ ew2,
    const float* __restrict__ eb2, const int* __restrict__ cnt,
    const float* __restrict__ ewt, float* __restrict__ Oe)
{
    int e = blockIdx.z;
    int cN = cnt[e];
    int t0 = blockIdx.y*128;
    if (t0 >= cN) return;
    gemm_core<3>(Hb + (size_t)e*TT*MH, ew2 + (size_t)e*Dm*MH, eb2 + (size_t)e*Dm,
                 nullptr, ewt + (size_t)e*TT, Oe + (size_t)e*TT*Dm, MH, Dm,
                 t0, blockIdx.x*128, cN);
}

// ---------------- flash attention with fp16 MMA (m16n8k16, half I/O) ----------------
#define ATN_SH_FLOATS (4*2176 + 320)

__global__ __launch_bounds__(256) void attn_mma_kernel(
    const __half* __restrict__ Q, const __half* __restrict__ K,
    const __half* __restrict__ V, __half* __restrict__ Y)
{
    extern __shared__ __align__(16) unsigned ash[];
    unsigned* QsV = ash;
    unsigned* KsV = ash + 2176;
    unsigned* PsV = ash + 2*2176;
    unsigned* VsV = ash + 3*2176;
    float* mrow = (float*)(ash + 4*2176);
    float* lrow = mrow + 64;
    float* rrow = lrow + 64;
    float* cred = rrow + 64;

    int bh = blockIdx.y;
    int b = bh >> 4, h = bh & 15;
    int q0 = blockIdx.x * 64;
    int tid = threadIdx.x;
    int warp = tid >> 5, lane = tid & 31;
    int gid = lane >> 2, tig = lane & 3;
    int warp_m = warp >> 1, warp_n = warp & 1;
    float slope = exp2f(-0.5f * (float)(h+1));

    for (int i = tid; i < 64*32; i += 256) {
        int q = i >> 5, d = (i & 31)*2;
        unsigned u = *(const unsigned*)&Q[((size_t)(b*Nn + q0 + q))*Dm + h*64 + d];
        int b16 = d >> 4, khalf = (d >> 3) & 1, tg = (d >> 1) & 3;
        int grp = ((q >> 4) << 3) + (q & 7), rh = (q >> 3) & 1;
        QsV[((b16*4 + tg)*34 + grp)*4 + rh + 2*khalf] = u;
    }
    if (tid < 64) { mrow[tid] = -1e30f; lrow[tid] = 0.f; }

    float o_acc[4][4];
    #pragma unroll
    for (int in = 0; in < 4; in++)
        #pragma unroll
        for (int q = 0; q < 4; q++) o_acc[in][q] = 0.f;

    int qlo = warp_m*16 + gid, qhi = qlo + 8;
    int qglo = q0 + qlo, qghi = q0 + qhi;
    int grpP = warp_m*8 + gid;

    for (int kt = 0; kt < Nn; kt += 64) {
        __syncthreads();
        for (int i = tid; i < 64*32; i += 256) {
            int j = i >> 5, d = (i & 31)*2;
            unsigned u = *(const unsigned*)&K[((size_t)(b*Nn + kt + j))*Dm + h*64 + d];
            int b16 = d >> 4, khalf = (d >> 3) & 1, tg = (d >> 1) & 3;
            KsV[((b16*4 + tg)*68 + j)*2 + khalf] = u;
        }
        for (int i = tid; i < 64*32; i += 256) {
            int d = i & 63, j = (i >> 6)*2;
            __half v0 = V[((size_t)(b*Nn + kt + j  ))*Dm + h*64 + d];
            __half v1 = V[((size_t)(b*Nn + kt + j+1))*Dm + h*64 + d];
            __half2 h2 = __halves2half2(v0, v1);
            int b16 = j >> 4, khalf = (j >> 3) & 1, tg = (j >> 1) & 3;
            VsV[((b16*4 + tg)*68 + d)*2 + khalf] = *reinterpret_cast<unsigned*>(&h2);
        }
        __syncthreads();

        float acc_s[4][4];
        #pragma unroll
        for (int in = 0; in < 4; in++)
            #pragma unroll
            for (int q = 0; q < 4; q++) acc_s[in][q] = 0.f;

        #pragma unroll
        for (int b16 = 0; b16 < 4; b16++) {
            uint4 afv = *(const uint4*)&QsV[((b16*4 + tig)*34 + grpP)*4];
            unsigned af[4] = {afv.x, afv.y, afv.z, afv.w};
            #pragma unroll
            for (int in = 0; in < 4; in++) {
                uint2 bfv = *(const uint2*)&KsV[((b16*4 + tig)*68 + warp_n*32 + in*8 + gid)*2];
                unsigned bf[2] = {bfv.x, bfv.y};
                mma_f16(acc_s[in], af, bf);
            }
        }

        float rmax0 = -1e30f, rmax1 = -1e30f;
        #pragma unroll
        for (int in = 0; in < 4; in++) {
            #pragma unroll
            for (int c2 = 0; c2 < 2; c2++) {
                int kg = kt + warp_n*32 + in*8 + 2*tig + c2;
                float d0 = (kg > qglo) ? (float)(kg - qglo) : 0.f;
                float d1 = (kg > qghi) ? (float)(kg - qghi) : 0.f;
                acc_s[in][c2]   = acc_s[in][c2]  *0.125f - slope*d0;
                acc_s[in][c2+2] = acc_s[in][c2+2]*0.125f - slope*d1;
                rmax0 = fmaxf(rmax0, acc_s[in][c2]);
                rmax1 = fmaxf(rmax1, acc_s[in][c2+2]);
            }
        }
        rmax0 = fmaxf(rmax0, __shfl_xor_sync(0xffffffff, rmax0, 1));
        rmax0 = fmaxf(rmax0, __shfl_xor_sync(0xffffffff, rmax0, 2));
        rmax1 = fmaxf(rmax1, __shfl_xor_sync(0xffffffff, rmax1, 1));
        rmax1 = fmaxf(rmax1, __shfl_xor_sync(0xffffffff, rmax1, 2));
        if (tig == 0) {
            cred[warp_n*64 + qlo] = rmax0;
            cred[warp_n*64 + qhi] = rmax1;
        }
        __syncthreads();
        if (tid < 64) {
            float mo = mrow[tid];
            float mn = fmaxf(mo, fmaxf(cred[tid], cred[64+tid]));
            mrow[tid] = mn;
            rrow[tid] = __expf(mo - mn);
        }
        __syncthreads();

        float mn0 = mrow[qlo], mn1 = mrow[qhi];
        float r0 = rrow[qlo], r1 = rrow[qhi];
        float rs0 = 0.f, rs1 = 0.f;
        #pragma unroll
        for (int in = 0; in < 4; in++) {
            float p00 = __expf(acc_s[in][0] - mn0);
            float p01 = __expf(acc_s[in][1] - mn0);
            float p10 = __expf(acc_s[in][2] - mn1);
            float p11 = __expf(acc_s[in][3] - mn1);
            rs0 += p00 + p01; rs1 += p10 + p11;
            int b16k = warp_n*2 + (in >> 1);
            int khalf = in & 1;
            PsV[((b16k*4 + tig)*34 + grpP)*4 + 0 + 2*khalf] = pack_h2(p00, p01);
            PsV[((b16k*4 + tig)*34 + grpP)*4 + 1 + 2*khalf] = pack_h2(p10, p11);
        }
        rs0 += __shfl_xor_sync(0xffffffff, rs0, 1);
        rs0 += __shfl_xor_sync(0xffffffff, rs0, 2);
        rs1 += __shfl_xor_sync(0xffffffff, rs1, 1);
        rs1 += __shfl_xor_sync(0xffffffff, rs1, 2);
        if (tig == 0) {
            cred[warp_n*64 + qlo] = rs0;
            cred[warp_n*64 + qhi] = rs1;
        }
        #pragma unroll
        for (int in = 0; in < 4; in++) {
            o_acc[in][0] *= r0; o_acc[in][1] *= r0;
            o_acc[in][2] *= r1; o_acc[in][3] *= r1;
        }
        __syncthreads();
        if (tid < 64) lrow[tid] = lrow[tid]*rrow[tid] + cred[tid] + cred[64+tid];

        #pragma unroll
        for (int b16 = 0; b16 < 4; b16++) {
            uint4 afv = *(const uint4*)&PsV[((b16*4 + tig)*34 + grpP)*4];
            unsigned af[4] = {afv.x, afv.y, afv.z, afv.w};
            #pragma unroll
            for (int in = 0; in < 4; in++) {
                uint2 bfv = *(const uint2*)&VsV[((b16*4 + tig)*68 + warp_n*32 + in*8 + gid)*2];
                unsigned bf[2] = {bfv.x, bfv.y};
                mma_f16(o_acc[in], af, bf);
            }
        }
    }
    __syncthreads();

    float inv0 = 1.f / lrow[qlo];
    float inv1 = 1.f / lrow[qhi];
    #pragma unroll
    for (int in = 0; in < 4; in++) {
        int col = h*64 + warp_n*32 + in*8 + 2*tig;
        *(__half2*)&Y[((size_t)(b*Nn + qglo))*Dm + col] =
            __floats2half2_rn(o_acc[in][0]*inv0, o_acc[in][1]*inv0);
        *(__half2*)&Y[((size_t)(b*Nn + qghi))*Dm + col] =
            __floats2half2_rn(o_acc[in][2]*inv1, o_acc[in][3]*inv1);
    }
}

// ---------------- router (half activations) ----------------
__global__ __launch_bounds__(128) void router_kernel(
    const __half* __restrict__ xf, const float* __restrict__ rw,
    float* __restrict__ Wout, float* __restrict__ Aux)
{
    int t = blockIdx.x;
    int warp = threadIdx.x >> 5, lane = threadIdx.x & 31;
    __shared__ float sg[NE];
    const __half* xrow = xf + (size_t)t*Dm;
    float s = 0.f;
    for (int i = lane; i < Dm; i += 32) s += __half2float(xrow[i])*rw[(size_t)warp*Dm + i];
    #pragma unroll
    for (int o = 16; o; o >>= 1) s += __shfl_xor_sync(0xffffffff, s, o);
    if (lane == 0) sg[warp] = s;
    __syncthreads();
    if (threadIdx.x == 0) {
        float m = fmaxf(fmaxf(sg[0],sg[1]), fmaxf(sg[2],sg[3]));
        float e[NE], sum = 0.f;
        #pragma unroll
        for (int i = 0; i < NE; i++) { e[i] = __expf(sg[i]-m); sum += e[i]; }
        float gate[NE];
        #pragma unroll
        for (int i = 0; i < NE; i++) gate[i] = e[i]/sum;
        int i0 = 0;
        #pragma unroll
        for (int i = 1; i < NE; i++) if (gate[i] > gate[i0]) i0 = i;
        int i1 = -1;
        #pragma unroll
        for (int i = 0; i < NE; i++) if (i != i0 && (i1 < 0 || gate[i] > gate[i1])) i1 = i;
        float s2 = fmaxf(gate[i0] + gate[i1], 1e-9f);
        #pragma unroll
        for (int i = 0; i < NE; i++) Wout[(size_t)t*NE + i] = 0.f;
        Wout[(size_t)t*NE + i0] = gate[i0]/s2;
        Wout[(size_t)t*NE + i1] = gate[i1]/s2;
        #pragma unroll
        for (int i = 0; i < NE; i++) atomicAdd(&Aux[i], gate[i]);
        atomicAdd(&Aux[NE + i0], 1.f);
        atomicAdd(&Aux[NE + i1], 1.f);
    }
}

// ---------------- MoE assignment / gather ----------------
__global__ __launch_bounds__(256) void assign_kernel(
    const float* __restrict__ Wt, int* __restrict__ cnt,
    int* __restrict__ eidx, float* __restrict__ ewt, int* __restrict__ tinv)
{
    int t = blockIdx.x*256 + threadIdx.x;
    if (t >= TT) return;
    int s = 0;
    #pragma unroll
    for (int e = 0; e < NE; e++) {
        float w = Wt[(size_t)t*NE + e];
        if (w != 0.f) {
            int pos = atomicAdd(&cnt[e], 1);
            eidx[e*TT + pos] = t;
            ewt [e*TT + pos] = w;
            tinv[t*2 + s] = e*TT + pos;
            s++;
        }
    }
}

__global__ __launch_bounds__(256) void gather_kernel(
    const __half* __restrict__ xf, const int* __restrict__ cnt,
    const int* __restrict__ eidx, __half* __restrict__ Xe)
{
    int e = blockIdx.y, row = blockIdx.x;
    int c = cnt[e];
    if (row >= c) return;
    uint2* dst = (uint2*)(Xe + ((size_t)e*TT + row)*Dm);
    const uint2* src = (const uint2*)(xf + (size_t)eidx[e*TT + row]*Dm);
    dst[threadIdx.x] = src[threadIdx.x];
}

// ---------------- final (fused MoE combine + trend conv + residual) ----------------
__global__ __launch_bounds__(256) void final_kernel(
    const float* __restrict__ tw, const float* __restrict__ tb,
    const float* __restrict__ Tr, const float* __restrict__ XS,
    const int* __restrict__ tinv, const float* __restrict__ Oe,
    float* __restrict__ out)
{
    int n = blockIdx.x, b = blockIdx.y;
    int t = b*Nn + n;
    int i0 = tinv[t*2], i1 = tinv[t*2+1];
    const float* oe0 = Oe + (size_t)i0*Dm;
    const float* oe1 = Oe + (size_t)i1*Dm;
    for (int d = threadIdx.x; d < Dm; d += 256) {
        float acc = tb[d];
        #pragma unroll
        for (int j = 0; j < 5; j++) {
            int p = n + j - 2;
            if (p >= 0 && p < Nn) acc += tw[d*5+j] * Tr[((size_t)(b*Nn+p))*Dm + d];
        }
        size_t idx = (size_t)t*Dm + d;
        out[idx] = XS[idx] + oe0[d] + oe1[d] + acc;
    }
}

__global__ void zero_aux_kernel(float* Aux, int* cnt) {
    if (threadIdx.x < 2*NE) Aux[threadIdx.x] = 0.f;
    if (threadIdx.x < NE) cnt[threadIdx.x] = 0;
}

__global__ void aux_write_kernel(const float* Aux, float* out, int out_size) {
    if (out_size > TT*Dm) {
        float a = 0.f;
        #pragma unroll
        for (int e = 0; e < NE; e++)
            a += (Aux[e]/(float)TT) * (Aux[NE+e]/(float)TT);
        out[TT*Dm] = (float)NE * a;
    }
}

// ---------------- launcher ----------------
extern "C" void kernel_launch(void* const* d_in, const int* in_sizes, int n_in,
                              void* d_out, int out_size)
{
    const float* x    = (const float*)d_in[0];
    const float* qw   = (const float*)d_in[1];
    const float* qb   = (const float*)d_in[2];
    const float* kw   = (const float*)d_in[3];
    const float* kb   = (const float*)d_in[4];
    const float* vw   = (const float*)d_in[5];
    const float* vb   = (const float*)d_in[6];
    const float* ow   = (const float*)d_in[7];
    const float* ob   = (const float*)d_in[8];
    const float* n1g  = (const float*)d_in[9];
    const float* n1b  = (const float*)d_in[10];
    const float* n2g  = (const float*)d_in[11];
    const float* n2b  = (const float*)d_in[12];
    const float* alpha= (const float*)d_in[13];
    const float* dw7  = (const float*)d_in[14];
    const float* dw25 = (const float*)d_in[15];
    const float* dw49 = (const float*)d_in[16];
    const float* rw   = (const float*)d_in[17];
    const float* ew1  = (const float*)d_in[18];
    const float* eb1  = (const float*)d_in[19];
    const float* ew2  = (const float*)d_in[20];
    const float* eb2  = (const float*)d_in[21];
    const float* tw   = (const float*)d_in[22];
    const float* tb   = (const float*)d_in[23];
    float* out = (float*)d_out;

    float *Tr,*S,*XS,*Oe,*Wt,*Ewt,*Aux,*Ck;
    __half *hSn,*hQ,*hK,*hV,*hY,*hH,*hXe,*hQw,*hKw,*hVw,*hOw,*hE1,*hE2;
    int *Eidx,*Cnt,*Tinv;
    cudaGetSymbolAddress((void**)&Tr,  g_Tr);
    cudaGetSymbolAddress((void**)&S,   g_S);
    cudaGetSymbolAddress((void**)&XS,  g_XS);
    cudaGetSymbolAddress((void**)&Oe,  g_Oe);
    cudaGetSymbolAddress((void**)&Wt,  g_W);
    cudaGetSymbolAddress((void**)&Ewt, g_Ewt);
    cudaGetSymbolAddress((void**)&Aux, g_Aux);
    cudaGetSymbolAddress((void**)&Ck,  g_Ck);
    cudaGetSymbolAddress((void**)&hSn, g_hSn);
    cudaGetSymbolAddress((void**)&hQ,  g_hQ);
    cudaGetSymbolAddress((void**)&hK,  g_hK);
    cudaGetSymbolAddress((void**)&hV,  g_hV);
    cudaGetSymbolAddress((void**)&hY,  g_hY);
    cudaGetSymbolAddress((void**)&hH,  g_hH);
    cudaGetSymbolAddress((void**)&hXe, g_hXe);
    cudaGetSymbolAddress((void**)&hQw, g_hQw);
    cudaGetSymbolAddress((void**)&hKw, g_hKw);
    cudaGetSymbolAddress((void**)&hVw, g_hVw);
    cudaGetSymbolAddress((void**)&hOw, g_hOw);
    cudaGetSymbolAddress((void**)&hE1, g_hE1);
    cudaGetSymbolAddress((void**)&hE2, g_hE2);
    cudaGetSymbolAddress((void**)&Eidx,g_Eidx);
    cudaGetSymbolAddress((void**)&Cnt, g_Cnt);
    cudaGetSymbolAddress((void**)&Tinv,g_Tinv);

    const int ATN_SH_BYTES = ATN_SH_FLOATS * 4;
    cudaFuncSetAttribute(attn_mma_kernel, cudaFuncAttributeMaxDynamicSharedMemorySize, ATN_SH_BYTES);

    zero_aux_kernel<<<1, 32>>>(Aux, Cnt);
    const int NW4 = (Dm*Dm)/4, NE14 = (NE*MH*Dm)/4;
    cvt_kernel<<<(NW4+255)/256, 256>>>(qw, hQw, NW4);
    cvt_kernel<<<(NW4+255)/256, 256>>>(kw, hKw, NW4);
    cvt_kernel<<<(NW4+255)/256, 256>>>(vw, hVw, NW4);
    cvt_kernel<<<(NW4+255)/256, 256>>>(ow, hOw, NW4);
    cvt_kernel<<<(NE14+255)/256, 256>>>(ew1, hE1, NE14);
    cvt_kernel<<<(NE14+255)/256, 256>>>(ew2, hE2, NE14);

    ckbuild_kernel<<<Dm, 64>>>(alpha, dw7, dw25, dw49, Ck);
    trend_kernel<<<dim3(61, Bz, Dm/128), 256>>>(x, Ck, Tr, S);
    decomp_edge_kernel<<<dim3(48, Bz), 256>>>(x, alpha, dw7, dw25, dw49, Tr, S);
    ln_kernel<<<TT, 256>>>(S, hSn, n1g, n1b);

    gemm_qkv<<<dim3(Dm/128, TT/128, 3), 256>>>(hSn, hQw, hKw, hVw, qb, kb, vb, hQ, hK, hV);

    attn_mma_kernel<<<dim3(Nn/64, Bz*Hh), 256, ATN_SH_BYTES>>>(hQ, hK, hV, hY);

    gemm_res<<<dim3(Dm/128, TT/128), 256>>>(hY, hOw, ob, S, XS);
    ln_kernel<<<TT, 256>>>(XS, hSn, n2g, n2b);
    router_kernel<<<TT, 128>>>(hSn, rw, Wt, Aux);
    assign_kernel<<<TT/256, 256>>>(Wt, Cnt, Eidx, Ewt, Tinv);
    gather_kernel<<<dim3(TT, NE), 256>>>(hSn, Cnt, Eidx, hXe);

    gemm_moe_up<<<dim3(MH/128, TT/128, NE), 256>>>(hXe, hE1, eb1, Cnt, hH);
    gemm_moe_dn<<<dim3(Dm/128, TT/128, NE), 256>>>(hH, hE2, eb2, Cnt, Ewt, Oe);

    final_kernel<<<dim3(Nn, Bz), 256>>>(tw, tb, Tr, XS, Tinv, Oe, out);
    aux_write_kernel<<<1, 1>>>(Aux, out, out_size);
}

// round 14
// speedup vs baseline: 12.3635x; 1.0837x over previous
#include <cuda_runtime.h>
#include <cuda_fp16.h>
#include <math.h>
#include <stdint.h>

#define Bz 8
#define Nn 1024
#define Dm 1024
#define Hh 16
#define HD 64
#define TT (Bz*Nn)       // 8192 tokens
#define MH 2048
#define NE 4

// ---------------- static device scratch (no allocation allowed) ----------------
__device__ float  g_Tr[(size_t)TT*Dm];
__device__ float  g_S [(size_t)TT*Dm];
__device__ float  g_XS[(size_t)TT*Dm];
__device__ float  g_Oe[(size_t)NE*TT*Dm];
__device__ float  g_W [(size_t)TT*NE];
__device__ float  g_Ck[(size_t)Dm*49];
__device__ __align__(16) __half g_hSn[(size_t)TT*Dm];
__device__ __align__(16) __half g_hQ [(size_t)TT*Dm];
__device__ __align__(16) __half g_hK [(size_t)TT*Dm];
__device__ __align__(16) __half g_hV [(size_t)TT*Dm];
__device__ __align__(16) __half g_hY [(size_t)TT*Dm];
__device__ __align__(16) __half g_hH [(size_t)NE*TT*MH];
__device__ __align__(16) __half g_hXe[(size_t)NE*TT*Dm];
__device__ __align__(16) __half g_hQw[(size_t)Dm*Dm];
__device__ __align__(16) __half g_hKw[(size_t)Dm*Dm];
__device__ __align__(16) __half g_hVw[(size_t)Dm*Dm];
__device__ __align__(16) __half g_hOw[(size_t)Dm*Dm];
__device__ __align__(16) __half g_hE1[(size_t)NE*MH*Dm];
__device__ __align__(16) __half g_hE2[(size_t)NE*Dm*MH];
__device__ int    g_Eidx[NE*TT];
__device__ float  g_Ewt [NE*TT];
__device__ int    g_Tinv[TT*2];
__device__ int    g_Cnt[NE];
__device__ float  g_Aux[2*NE];

// ---------------- ptx helpers ----------------
__device__ __forceinline__ uint32_t smem_u32(const void* p) {
    uint32_t a;
    asm("{ .reg .u64 t; cvta.to.shared.u64 t, %1; cvt.u32.u64 %0, t; }" : "=r"(a) : "l"(p));
    return a;
}
__device__ __forceinline__ unsigned pack_h2(float lo, float hi) {
    __half2 h = __floats2half2_rn(lo, hi);
    return *reinterpret_cast<unsigned*>(&h);
}
__device__ __forceinline__ void mma_f16(float* c, const unsigned* a, const unsigned* b) {
    asm volatile(
        "mma.sync.aligned.m16n8k16.row.col.f32.f16.f16.f32 "
        "{%0,%1,%2,%3}, {%4,%5,%6,%7}, {%8,%9}, {%0,%1,%2,%3};\n"
        : "+f"(c[0]), "+f"(c[1]), "+f"(c[2]), "+f"(c[3])
        : "r"(a[0]), "r"(a[1]), "r"(a[2]), "r"(a[3]), "r"(b[0]), "r"(b[1]));
}
__device__ __forceinline__ void cp16(uint32_t dst, const void* src) {
    asm volatile("cp.async.cg.shared.global [%0], [%1], 16;\n" :: "r"(dst), "l"(src));
}
#define CP_COMMIT() asm volatile("cp.async.commit_group;\n" ::: "memory")
#define CP_WAIT0()  asm volatile("cp.async.wait_group 0;\n" ::: "memory")
#define CP_WAIT2()  asm volatile("cp.async.wait_group 2;\n" ::: "memory")
__device__ __forceinline__ void ldm_x4(unsigned& r0, unsigned& r1, unsigned& r2, unsigned& r3,
                                       uint32_t addr) {
    asm volatile("ldmatrix.sync.aligned.m8n8.x4.shared.b16 {%0,%1,%2,%3}, [%4];"
                 : "=r"(r0), "=r"(r1), "=r"(r2), "=r"(r3) : "r"(addr));
}
__device__ __forceinline__ void ldm_x4t(unsigned& r0, unsigned& r1, unsigned& r2, unsigned& r3,
                                        uint32_t addr) {
    asm volatile("ldmatrix.sync.aligned.m8n8.x4.trans.shared.b16 {%0,%1,%2,%3}, [%4];"
                 : "=r"(r0), "=r"(r1), "=r"(r2), "=r"(r3) : "r"(addr));
}

__device__ __forceinline__ float gelu_f(float v) {
    return 0.5f*v*(1.0f + erff(v*0.70710678118654752f));
}

// ---------------- fp32 -> fp16 weight conversion ----------------
__global__ __launch_bounds__(256) void cvt_kernel(
    const float* __restrict__ src, __half* __restrict__ dst, int n4)
{
    int i = blockIdx.x*256 + threadIdx.x;
    if (i >= n4) return;
    float4 v = ((const float4*)src)[i];
    ((__half2*)dst)[2*i]   = __floats2half2_rn(v.x, v.y);
    ((__half2*)dst)[2*i+1] = __floats2half2_rn(v.z, v.w);
}

// ---------------- combined decomposition kernel build ----------------
__global__ void ckbuild_kernel(
    const float* __restrict__ alpha, const float* __restrict__ w7,
    const float* __restrict__ w25, const float* __restrict__ w49,
    float* __restrict__ ck)
{
    int d = blockIdx.x, j = threadIdx.x;
    if (j >= 49) return;
    float a0 = alpha[0], a1 = alpha[1], a2 = alpha[2];
    float mx = fmaxf(a0, fmaxf(a1, a2));
    float e0 = __expf(a0-mx), e1 = __expf(a1-mx), e2 = __expf(a2-mx);
    float inv = 1.f/(e0+e1+e2);
    float wt0 = e0*inv, wt1 = e1*inv, wt2 = e2*inv;
    float v = wt2 * w49[d*49 + j];
    if (j >= 12 && j < 37) v += wt1 * w25[d*25 + (j-12)];
    if (j >= 21 && j < 28) v += wt0 * w7[d*7 + (j-21)];
    ck[d*49 + j] = v;
}

// ---------------- interior trend ----------------
__global__ __launch_bounds__(256) void trend_kernel(
    const float* __restrict__ x, const float* __restrict__ ck,
    float* __restrict__ Tr, float* __restrict__ S)
{
    __shared__ float xs[64][128];
    int b = blockIdx.y;
    int n0 = 24 + blockIdx.x * 16;
    int d0 = blockIdx.z * 128;
    int tid = threadIdx.x;
    int dl = tid & 127, ng = tid >> 7;

    for (int i = tid; i < 64*32; i += 256) {
        int p = i >> 5, c = i & 31;
        *(float4*)&xs[p][c*4] =
            *(const float4*)&x[((size_t)(b*Nn + n0 - 24 + p))*Dm + d0 + c*4];
    }
    __syncthreads();

    float ckr[49];
    #pragma unroll
    for (int j = 0; j < 49; j++) ckr[j] = __ldg(&ck[(size_t)(d0+dl)*49 + j]);

    float acc[8];
    #pragma unroll
    for (int j = 0; j < 8; j++) acc[j] = 0.f;

    #pragma unroll
    for (int pr = 0; pr < 56; pr++) {
        float xv = xs[ng*8 + pr][dl];
        #pragma unroll
        for (int j = 0; j < 8; j++) {
            int t = pr - j;
            if (t >= 0 && t < 49) acc[j] += ckr[t] * xv;
        }
    }

    #pragma unroll
    for (int j = 0; j < 8; j++) {
        int nl = ng*8 + j;
        size_t idx = ((size_t)(b*Nn + n0 + nl))*Dm + d0 + dl;
        float xval = xs[nl + 24][dl];
        Tr[idx] = acc[j];
        S[idx]  = xval - acc[j];
    }
}

// ---------------- boundary decomposition ----------------
__global__ __launch_bounds__(256) void decomp_edge_kernel(
    const float* __restrict__ x, const float* __restrict__ alpha,
    const float* __restrict__ w7, const float* __restrict__ w25,
    const float* __restrict__ w49, float* __restrict__ Tr, float* __restrict__ S)
{
    int bx = blockIdx.x;
    int n = (bx < 24) ? bx : (Nn - 48 + bx);
    int b = blockIdx.y;
    float a0 = alpha[0], a1 = alpha[1], a2 = alpha[2];
    float mx = fmaxf(a0, fmaxf(a1, a2));
    float e0 = __expf(a0-mx), e1 = __expf(a1-mx), e2 = __expf(a2-mx);
    float inv = 1.f/(e0+e1+e2);
    float wt0 = e0*inv, wt1 = e1*inv, wt2 = e2*inv;

    for (int d = threadIdx.x; d < Dm; d += 256) {
        float t7 = 0.f, t25 = 0.f, t49 = 0.f;
        #pragma unroll
        for (int j = 0; j < 7; j++) {
            int p = n + j - 3; p = p < 0 ? -p : (p >= Nn ? 2*Nn-2-p : p);
            t7 += w7[d*7+j] * x[((size_t)(b*Nn+p))*Dm + d];
        }
        #pragma unroll
        for (int j = 0; j < 25; j++) {
            int p = n + j - 12; p = p < 0 ? -p : (p >= Nn ? 2*Nn-2-p : p);
            t25 += w25[d*25+j] * x[((size_t)(b*Nn+p))*Dm + d];
        }
        #pragma unroll
        for (int j = 0; j < 49; j++) {
            int p = n + j - 24; p = p < 0 ? -p : (p >= Nn ? 2*Nn-2-p : p);
            t49 += w49[d*49+j] * x[((size_t)(b*Nn+p))*Dm + d];
        }
        float tr = wt0*t7 + wt1*t25 + wt2*t49;
        size_t idx = ((size_t)(b*Nn+n))*Dm + d;
        Tr[idx] = tr;
        S[idx]  = x[idx] - tr;
    }
}

// ---------------- one-pass LayerNorm (fp32 in, half out) ----------------
__global__ __launch_bounds__(256) void ln_kernel(
    const float* __restrict__ in, __half* __restrict__ out,
    const float* __restrict__ g, const float* __restrict__ b)
{
    __shared__ float red[8];
    int t = blockIdx.x, tid = threadIdx.x;
    int lane = tid & 31, warp = tid >> 5;
    const float4* row4 = (const float4*)(in + (size_t)t*Dm);
    float4 v = row4[tid];
    float s = v.x + v.y + v.z + v.w;
    #pragma unroll
    for (int o = 16; o; o >>= 1) s += __shfl_xor_sync(0xffffffff, s, o);
    if (lane == 0) red[warp] = s;
    __syncthreads();
    float tot = 0.f;
    #pragma unroll
    for (int i = 0; i < 8; i++) tot += red[i];
    float m = tot * (1.f/Dm);
    float dx = v.x-m, dy = v.y-m, dz = v.z-m, dw = v.w-m;
    float s2 = dx*dx + dy*dy + dz*dz + dw*dw;
    #pragma unroll
    for (int o = 16; o; o >>= 1) s2 += __shfl_xor_sync(0xffffffff, s2, o);
    __syncthreads();
    if (lane == 0) red[warp] = s2;
    __syncthreads();
    float tot2 = 0.f;
    #pragma unroll
    for (int i = 0; i < 8; i++) tot2 += red[i];
    float rinv = rsqrtf(tot2*(1.f/Dm) + 1e-5f);
    float4 gv = ((const float4*)g)[tid];
    float4 bv = ((const float4*)b)[tid];
    __half2* out2 = (__half2*)(out + (size_t)t*Dm);
    out2[2*tid]   = __floats2half2_rn(dx*rinv*gv.x + bv.x, dy*rinv*gv.y + bv.y);
    out2[2*tid+1] = __floats2half2_rn(dz*rinv*gv.z + bv.z, dw*rinv*gv.w + bv.w);
}

// ---------------- fp16 GEMM core: cp.async 3-stage + ldmatrix (R11, unchanged) ----------------
#define GSTAGES 3
#define GSTAGE_BYTES 16384

template<int MODE>
__device__ __forceinline__ void gemm_core(
    const __half* __restrict__ A, const __half* __restrict__ W,
    const float* __restrict__ bias, const float* __restrict__ res,
    const float* __restrict__ wvec,
    void* __restrict__ Cv, int K, int O, int t0, int o0, int cN)
{
    __shared__ __align__(16) char sm[GSTAGES*GSTAGE_BYTES];
    int tid = threadIdx.x;
    int lane = tid & 31, warp = tid >> 5;
    int warp_m = warp >> 2, warp_n = warp & 3;
    int gid = lane >> 2, tig = lane & 3;

    float acc[4][4][4];
    #pragma unroll
    for (int im = 0; im < 4; im++)
        #pragma unroll
        for (int in = 0; in < 4; in++)
            #pragma unroll
            for (int q = 0; q < 4; q++) acc[im][in][q] = 0.f;

    uint32_t smb = smem_u32(sm);

    int r0c = tid >> 2, c0c = tid & 3;
    int r1c = (tid + 256) >> 2, c1c = tid & 3;
    uint32_t dA0 = (uint32_t)(r0c*64 + ((c0c ^ ((r0c>>1)&3))*16));
    uint32_t dA1 = (uint32_t)(r1c*64 + ((c1c ^ ((r1c>>1)&3))*16));
    const __half* Abase = A + (size_t)t0*K;
    const __half* Bbase = W + (size_t)o0*K;
    const __half* srcA0 = Abase + (size_t)r0c*K + c0c*8;
    const __half* srcA1 = Abase + (size_t)r1c*K + c1c*8;
    const __half* srcB0 = Bbase + (size_t)r0c*K + c0c*8;
    const __half* srcB1 = Bbase + (size_t)r1c*K + c1c*8;

    int nt = K >> 5;

    #pragma unroll
    for (int s = 0; s < GSTAGES; s++) {
        uint32_t ba = smb + s*GSTAGE_BYTES;
        uint32_t bb = ba + 8192;
        int ko = s*32;
        cp16(ba + dA0, srcA0 + ko);
        cp16(ba + dA1, srcA1 + ko);
        cp16(bb + dA0, srcB0 + ko);
        cp16(bb + dA1, srcB1 + ko);
        CP_COMMIT();
    }

    int rA[4], swA[4];
    #pragma unroll
    for (int im = 0; im < 4; im++) {
        rA[im] = warp_m*64 + im*16 + (lane & 7) + 8*((lane >> 3) & 1);
        swA[im] = (rA[im] >> 1) & 3;
    }
    int kbA = (lane >> 4) & 1;
    int rB[2], swB[2];
    #pragma unroll
    for (int ip = 0; ip < 2; ip++) {
        rB[ip] = warp_n*32 + ip*16 + 8*((lane >> 4) & 1) + (lane & 7);
        swB[ip] = (rB[ip] >> 1) & 3;
    }
    int kbB = (lane >> 3) & 1;

    for (int t = 0; t < nt; t++) {
        int st = t % GSTAGES;
        uint32_t ba = smb + st*GSTAGE_BYTES;
        uint32_t bb = ba + 8192;
        CP_WAIT2();
        __syncthreads();

        #pragma unroll
        for (int s16 = 0; s16 < 2; s16++) {
            unsigned af[4][4], bf[4][2];
            #pragma unroll
            for (int im = 0; im < 4; im++) {
                uint32_t addr = ba + rA[im]*64 + (((2*s16 + kbA) ^ swA[im])*16);
                ldm_x4(af[im][0], af[im][1], af[im][2], af[im][3], addr);
            }
            #pragma unroll
            for (int ip = 0; ip < 2; ip++) {
                uint32_t addr = bb + rB[ip]*64 + (((2*s16 + kbB) ^ swB[ip])*16);
                ldm_x4(bf[2*ip][0], bf[2*ip][1], bf[2*ip+1][0], bf[2*ip+1][1], addr);
            }
            #pragma unroll
            for (int im = 0; im < 4; im++)
                #pragma unroll
                for (int in = 0; in < 4; in++)
                    mma_f16(acc[im][in], af[im], bf[in]);
        }
        __syncthreads();

        int tn = t + GSTAGES;
        if (tn < nt) {
            int ko = tn*32;
            cp16(ba + dA0, srcA0 + ko);
            cp16(ba + dA1, srcA1 + ko);
            cp16(bb + dA0, srcB0 + ko);
            cp16(bb + dA1, srcB1 + ko);
        }
        CP_COMMIT();
    }

    #pragma unroll
    for (int im = 0; im < 4; im++) {
        #pragma unroll
        for (int half = 0; half < 2; half++) {
            int row = t0 + warp_m*64 + im*16 + gid + half*8;
            if ((MODE == 2 || MODE == 3) && row >= cN) continue;
            float w = 0.f;
            if (MODE == 3) w = wvec[row];
            #pragma unroll
            for (int in = 0; in < 4; in++) {
                int col = o0 + warp_n*32 + in*8 + 2*tig;
                float v0 = acc[im][in][half*2+0] + bias[col];
                float v1 = acc[im][in][half*2+1] + bias[col+1];
                size_t idx = (size_t)row*O + col;
                if (MODE == 0) {
                    *(__half2*)&((__half*)Cv)[idx] = __floats2half2_rn(v0, v1);
                } else if (MODE == 1) {
                    float* C = (float*)Cv;
                    C[idx] = v0 + res[idx]; C[idx+1] = v1 + res[idx+1];
                } else if (MODE == 2) {
                    *(__half2*)&((__half*)Cv)[idx] = __floats2half2_rn(gelu_f(v0), gelu_f(v1));
                } else {
                    float* C = (float*)Cv;
                    C[idx] = w*v0; C[idx+1] = w*v1;
                }
            }
        }
    }
}

// ---- wrappers ----
__global__ __launch_bounds__(256, 2) void gemm_qkv(
    const __half* __restrict__ A,
    const __half* __restrict__ w0, const __half* __restrict__ w1, const __half* __restrict__ w2,
    const float* __restrict__ b0, const float* __restrict__ b1, const float* __restrict__ b2,
    __half* __restrict__ c0, __half* __restrict__ c1, __half* __restrict__ c2)
{
    int z = blockIdx.z;
    const __half* W = (z == 0) ? w0 : (z == 1) ? w1 : w2;
    const float* B = (z == 0) ? b0 : (z == 1) ? b1 : b2;
    __half* C = (z == 0) ? c0 : (z == 1) ? c1 : c2;
    gemm_core<0>(A, W, B, nullptr, nullptr, C, Dm, Dm,
                 blockIdx.y*128, blockIdx.x*128, 1 << 30);
}

__global__ __launch_bounds__(256, 2) void gemm_res(
    const __half* __restrict__ A, const __half* __restrict__ W,
    const float* __restrict__ bias, const float* __restrict__ res,
    float* __restrict__ C)
{
    gemm_core<1>(A, W, bias, res, nullptr, C, Dm, Dm,
                 blockIdx.y*128, blockIdx.x*128, 1 << 30);
}

__global__ __launch_bounds__(256, 2) void gemm_moe_up(
    const __half* __restrict__ Xe, const __half* __restrict__ ew1,
    const float* __restrict__ eb1, const int* __restrict__ cnt,
    __half* __restrict__ Hb)
{
    int e = blockIdx.z;
    int cN = cnt[e];
    int t0 = blockIdx.y*128;
    if (t0 >= cN) return;
    gemm_core<2>(Xe + (size_t)e*TT*Dm, ew1 + (size_t)e*MH*Dm, eb1 + (size_t)e*MH,
                 nullptr, nullptr, Hb + (size_t)e*TT*MH, Dm, MH,
                 t0, blockIdx.x*128, cN);
}

__global__ __launch_bounds__(256, 2) void gemm_moe_dn(
    const __half* __restrict__ Hb, const __half* __restrict__ ew2,
    const float* __restrict__ eb2, const int* __restrict__ cnt,
    const float* __restrict__ ewt, float* __restrict__ Oe)
{
    int e = blockIdx.z;
    int cN = cnt[e];
    int t0 = blockIdx.y*128;
    if (t0 >= cN) return;
    gemm_core<3>(Hb + (size_t)e*TT*MH, ew2 + (size_t)e*Dm*MH, eb2 + (size_t)e*Dm,
                 nullptr, ewt + (size_t)e*TT, Oe + (size_t)e*TT*Dm, MH, Dm,
                 t0, blockIdx.x*128, cN);
}

// ---------------- flash attention v2: per-warp softmax, register P, cp.async KV ----------------
// block 256 thr = 8 warps: warp_m = warp>>1 (16 q rows), warp_n = warp&1 (32-key slice)
// smem: 3 stages x (K 8KB + V 8KB) + merge O (4*16*64 fp32) + merge ml (4*16*2 fp32)
#define AT_STAGE 16384
#define AT_OM    (3*AT_STAGE)
#define AT_ML    (AT_OM + 4*16*64*4)
#define AT_DSM   (AT_ML + 4*16*2*4)

__global__ __launch_bounds__(256) void attn2_kernel(
    const __half* __restrict__ Q, const __half* __restrict__ K,
    const __half* __restrict__ V, __half* __restrict__ Y)
{
    extern __shared__ __align__(16) char asmem[];
    uint32_t sb = smem_u32(asmem);
    float* Om = (float*)(asmem + AT_OM);
    float* Ml = (float*)(asmem + AT_ML);

    int bh = blockIdx.y;
    int b = bh >> 4, h = bh & 15;
    int q0 = blockIdx.x * 64;
    int tid = threadIdx.x;
    int warp = tid >> 5, lane = tid & 31;
    int gid = lane >> 2, tig = lane & 3;
    int warp_m = warp >> 1, warp_n = warp & 1;
    float slope = exp2f(-0.5f * (float)(h+1));

    // tile loader indices: 512 chunks of 16B per 64x64-half tile; thread does chunk tid, tid+256
    int rw0 = tid >> 3, cc0 = tid & 7;
    int rw1 = (tid + 256) >> 3, cc1 = tid & 7;
    uint32_t d0 = (uint32_t)(rw0*128 + ((cc0 ^ (rw0 & 7))*16));
    uint32_t d1 = (uint32_t)(rw1*128 + ((cc1 ^ (rw1 & 7))*16));

    // ---- stage Q into buffer 0, ldmatrix into registers ----
    {
        const __half* qsrc = Q + ((size_t)(b*Nn + q0))*Dm + h*64;
        cp16(sb + d0, qsrc + (size_t)rw0*Dm + cc0*8);
        cp16(sb + d1, qsrc + (size_t)rw1*Dm + cc1*8);
        CP_COMMIT();
        CP_WAIT0();
        __syncthreads();
    }
    unsigned aQ[4][4];
    {
        int rq = warp_m*16 + (lane & 15);
        int kb = (lane >> 4) & 1;
        #pragma unroll
        for (int b16 = 0; b16 < 4; b16++) {
            uint32_t addr = sb + rq*128 + (((b16*2 + kb) ^ (rq & 7))*16);
            ldm_x4(aQ[b16][0], aQ[b16][1], aQ[b16][2], aQ[b16][3], addr);
        }
    }
    __syncthreads();   // Q consumed; stage 0 reusable

    // ---- prologue: load chunks 0..2 ----
    const int NT = Nn/64;
    #pragma unroll
    for (int s = 0; s < 3; s++) {
        uint32_t kb = sb + s*AT_STAGE;
        uint32_t vb = kb + 8192;
        const __half* ks = K + ((size_t)(b*Nn + s*64))*Dm + h*64;
        const __half* vs = V + ((size_t)(b*Nn + s*64))*Dm + h*64;
        cp16(kb + d0, ks + (size_t)rw0*Dm + cc0*8);
        cp16(kb + d1, ks + (size_t)rw1*Dm + cc1*8);
        cp16(vb + d0, vs + (size_t)rw0*Dm + cc0*8);
        cp16(vb + d1, vs + (size_t)rw1*Dm + cc1*8);
        CP_COMMIT();
    }

    // ldmatrix lane addressing (K: non-trans B operand; V: trans B operand)
    int rK = warp_n*32 + 8*((lane >> 4) & 1) + (lane & 7);   // + ip*16
    int kbK = (lane >> 3) & 1;
    int jV = warp_n*32 + (lane & 7) + 8*((lane >> 3) & 1);   // + c*16
    int cV = (lane >> 4) & 1;                                 // + dt*2

    float m_lo = -1e30f, m_hi = -1e30f, l_lo = 0.f, l_hi = 0.f;
    float o_acc[8][4];
    #pragma unroll
    for (int nt8 = 0; nt8 < 8; nt8++)
        #pragma unroll
        for (int q = 0; q < 4; q++) o_acc[nt8][q] = 0.f;

    int qglo = q0 + warp_m*16 + gid, qghi = qglo + 8;

    for (int t = 0; t < NT; t++) {
        uint32_t kb = sb + (t % 3)*AT_STAGE;
        uint32_t vb = kb + 8192;
        CP_WAIT2();
        __syncthreads();

        // ---- S = Q K^T over this warp's 32-key slice ----
        float acc_s[4][4];
        #pragma unroll
        for (int in = 0; in < 4; in++)
            #pragma unroll
            for (int q = 0; q < 4; q++) acc_s[in][q] = 0.f;

        #pragma unroll
        for (int b16 = 0; b16 < 4; b16++) {
            unsigned bf[4][2];
            #pragma unroll
            for (int ip = 0; ip < 2; ip++) {
                int row = rK + ip*16;
                uint32_t addr = kb + row*128 + (((b16*2 + kbK) ^ (row & 7))*16);
                ldm_x4(bf[2*ip][0], bf[2*ip][1], bf[2*ip+1][0], bf[2*ip+1][1], addr);
            }
            #pragma unroll
            for (int in = 0; in < 4; in++)
                mma_f16(acc_s[in], aQ[b16], bf[in]);
        }

        // ---- alibi + per-warp online softmax (no smem, no barrier) ----
        int kgbase = t*64 + warp_n*32;
        float rmax0 = -1e30f, rmax1 = -1e30f;
        #pragma unroll
        for (int in = 0; in < 4; in++) {
            #pragma unroll
            for (int c2 = 0; c2 < 2; c2++) {
                int kg = kgbase + in*8 + 2*tig + c2;
                float dd0 = (kg > qglo) ? (float)(kg - qglo) : 0.f;
                float dd1 = (kg > qghi) ? (float)(kg - qghi) : 0.f;
                acc_s[in][c2]   = acc_s[in][c2]  *0.125f - slope*dd0;
                acc_s[in][c2+2] = acc_s[in][c2+2]*0.125f - slope*dd1;
                rmax0 = fmaxf(rmax0, acc_s[in][c2]);
                rmax1 = fmaxf(rmax1, acc_s[in][c2+2]);
            }
        }
        rmax0 = fmaxf(rmax0, __shfl_xor_sync(0xffffffff, rmax0, 1));
        rmax0 = fmaxf(rmax0, __shfl_xor_sync(0xffffffff, rmax0, 2));
        rmax1 = fmaxf(rmax1, __shfl_xor_sync(0xffffffff, rmax1, 1));
        rmax1 = fmaxf(rmax1, __shfl_xor_sync(0xffffffff, rmax1, 2));

        float mn0 = fmaxf(m_lo, rmax0), mn1 = fmaxf(m_hi, rmax1);
        float r0 = __expf(m_lo - mn0), r1 = __expf(m_hi - mn1);
        m_lo = mn0; m_hi = mn1;

        float p[4][4];
        float rs0 = 0.f, rs1 = 0.f;
        #pragma unroll
        for (int in = 0; in < 4; in++) {
            p[in][0] = __expf(acc_s[in][0] - mn0);
            p[in][1] = __expf(acc_s[in][1] - mn0);
            p[in][2] = __expf(acc_s[in][2] - mn1);
            p[in][3] = __expf(acc_s[in][3] - mn1);
            rs0 += p[in][0] + p[in][1];
            rs1 += p[in][2] + p[in][3];
        }
        rs0 += __shfl_xor_sync(0xffffffff, rs0, 1);
        rs0 += __shfl_xor_sync(0xffffffff, rs0, 2);
        rs1 += __shfl_xor_sync(0xffffffff, rs1, 1);
        rs1 += __shfl_xor_sync(0xffffffff, rs1, 2);
        l_lo = l_lo*r0 + rs0;
        l_hi = l_hi*r1 + rs1;

        #pragma unroll
        for (int nt8 = 0; nt8 < 8; nt8++) {
            o_acc[nt8][0] *= r0; o_acc[nt8][1] *= r0;
            o_acc[nt8][2] *= r1; o_acc[nt8][3] *= r1;
        }

        // ---- O += P V : P fragments straight from registers ----
        #pragma unroll
        for (int c = 0; c < 2; c++) {
            unsigned aP[4];
            aP[0] = pack_h2(p[2*c][0],   p[2*c][1]);
            aP[1] = pack_h2(p[2*c][2],   p[2*c][3]);
            aP[2] = pack_h2(p[2*c+1][0], p[2*c+1][1]);
            aP[3] = pack_h2(p[2*c+1][2], p[2*c+1][3]);
            #pragma unroll
            for (int dt = 0; dt < 4; dt++) {
                int row = jV + c*16;
                uint32_t addr = vb + row*128 + (((dt*2 + cV) ^ (row & 7))*16);
                unsigned bv0, bv1, bv2, bv3;
                ldm_x4t(bv0, bv1, bv2, bv3, addr);
                unsigned bfa[2] = {bv0, bv1};
                unsigned bfb[2] = {bv2, bv3};
                mma_f16(o_acc[2*dt],   aP, bfa);
                mma_f16(o_acc[2*dt+1], aP, bfb);
            }
        }
        __syncthreads();

        int tn = t + 3;
        if (tn < NT) {
            const __half* ks = K + ((size_t)(b*Nn + tn*64))*Dm + h*64;
            const __half* vs = V + ((size_t)(b*Nn + tn*64))*Dm + h*64;
            cp16(kb + d0, ks + (size_t)rw0*Dm + cc0*8);
            cp16(kb + d1, ks + (size_t)rw1*Dm + cc1*8);
            cp16(vb + d0, vs + (size_t)rw0*Dm + cc0*8);
            cp16(vb + d1, vs + (size_t)rw1*Dm + cc1*8);
        }
        CP_COMMIT();
    }

    // ---- merge the two key-half warps ----
    if (warp_n == 1) {
        #pragma unroll
        for (int nt8 = 0; nt8 < 8; nt8++) {
            #pragma unroll
            for (int q = 0; q < 4; q++) {
                int row = warp_m*16 + gid + ((q >= 2) ? 8 : 0);
                int col = nt8*8 + 2*tig + (q & 1);
                Om[row*64 + col] = o_acc[nt8][q];
            }
        }
        if (tig == 0) {
            Ml[(warp_m*16 + gid)*2 + 0]     = m_lo;
            Ml[(warp_m*16 + gid)*2 + 1]     = l_lo;
            Ml[(warp_m*16 + gid + 8)*2 + 0] = m_hi;
            Ml[(warp_m*16 + gid + 8)*2 + 1] = l_hi;
        }
    }
    __syncthreads();
    if (warp_n == 0) {
        int rlo = warp_m*16 + gid, rhi = rlo + 8;
        float m1lo = Ml[rlo*2], l1lo = Ml[rlo*2+1];
        float m1hi = Ml[rhi*2], l1hi = Ml[rhi*2+1];
        float mlo = fmaxf(m_lo, m1lo), mhi = fmaxf(m_hi, m1hi);
        float s0lo = __expf(m_lo - mlo), s1lo = __expf(m1lo - mlo);
        float s0hi = __expf(m_hi - mhi), s1hi = __expf(m1hi - mhi);
        float invlo = 1.f / (l_lo*s0lo + l1lo*s1lo);
        float invhi = 1.f / (l_hi*s0hi + l1hi*s1hi);
        #pragma unroll
        for (int nt8 = 0; nt8 < 8; nt8++) {
            int col = nt8*8 + 2*tig;
            float vlo0 = (o_acc[nt8][0]*s0lo + Om[rlo*64 + col  ]*s1lo)*invlo;
            float vlo1 = (o_acc[nt8][1]*s0lo + Om[rlo*64 + col+1]*s1lo)*invlo;
            float vhi0 = (o_acc[nt8][2]*s0hi + Om[rhi*64 + col  ]*s1hi)*invhi;
            float vhi1 = (o_acc[nt8][3]*s0hi + Om[rhi*64 + col+1]*s1hi)*invhi;
            *(__half2*)&Y[((size_t)(b*Nn + q0 + rlo))*Dm + h*64 + col] =
                __floats2half2_rn(vlo0, vlo1);
            *(__half2*)&Y[((size_t)(b*Nn + q0 + rhi))*Dm + h*64 + col] =
                __floats2half2_rn(vhi0, vhi1);
        }
    }
}

// ---------------- router (half activations) ----------------
__global__ __launch_bounds__(128) void router_kernel(
    const __half* __restrict__ xf, const float* __restrict__ rw,
    float* __restrict__ Wout, float* __restrict__ Aux)
{
    int t = blockIdx.x;
    int warp = threadIdx.x >> 5, lane = threadIdx.x & 31;
    __shared__ float sg[NE];
    const __half* xrow = xf + (size_t)t*Dm;
    float s = 0.f;
    for (int i = lane; i < Dm; i += 32) s += __half2float(xrow[i])*rw[(size_t)warp*Dm + i];
    #pragma unroll
    for (int o = 16; o; o >>= 1) s += __shfl_xor_sync(0xffffffff, s, o);
    if (lane == 0) sg[warp] = s;
    __syncthreads();
    if (threadIdx.x == 0) {
        float m = fmaxf(fmaxf(sg[0],sg[1]), fmaxf(sg[2],sg[3]));
        float e[NE], sum = 0.f;
        #pragma unroll
        for (int i = 0; i < NE; i++) { e[i] = __expf(sg[i]-m); sum += e[i]; }
        float gate[NE];
        #pragma unroll
        for (int i = 0; i < NE; i++) gate[i] = e[i]/sum;
        int i0 = 0;
        #pragma unroll
        for (int i = 1; i < NE; i++) if (gate[i] > gate[i0]) i0 = i;
        int i1 = -1;
        #pragma unroll
        for (int i = 0; i < NE; i++) if (i != i0 && (i1 < 0 || gate[i] > gate[i1])) i1 = i;
        float s2 = fmaxf(gate[i0] + gate[i1], 1e-9f);
        #pragma unroll
        for (int i = 0; i < NE; i++) Wout[(size_t)t*NE + i] = 0.f;
        Wout[(size_t)t*NE + i0] = gate[i0]/s2;
        Wout[(size_t)t*NE + i1] = gate[i1]/s2;
        #pragma unroll
        for (int i = 0; i < NE; i++) atomicAdd(&Aux[i], gate[i]);
        atomicAdd(&Aux[NE + i0], 1.f);
        atomicAdd(&Aux[NE + i1], 1.f);
    }
}

// ---------------- MoE assignment / gather ----------------
__global__ __launch_bounds__(256) void assign_kernel(
    const float* __restrict__ Wt, int* __restrict__ cnt,
    int* __restrict__ eidx, float* __restrict__ ewt, int* __restrict__ tinv)
{
    int t = blockIdx.x*256 + threadIdx.x;
    if (t >= TT) return;
    int s = 0;
    #pragma unroll
    for (int e = 0; e < NE; e++) {
        float w = Wt[(size_t)t*NE + e];
        if (w != 0.f) {
            int pos = atomicAdd(&cnt[e], 1);
            eidx[e*TT + pos] = t;
            ewt [e*TT + pos] = w;
            tinv[t*2 + s] = e*TT + pos;
            s++;
        }
    }
}

__global__ __launch_bounds__(256) void gather_kernel(
    const __half* __restrict__ xf, const int* __restrict__ cnt,
    const int* __restrict__ eidx, __half* __restrict__ Xe)
{
    int e = blockIdx.y, row = blockIdx.x;
    int c = cnt[e];
    if (row >= c) return;
    uint2* dst = (uint2*)(Xe + ((size_t)e*TT + row)*Dm);
    const uint2* src = (const uint2*)(xf + (size_t)eidx[e*TT + row]*Dm);
    dst[threadIdx.x] = src[threadIdx.x];
}

// ---------------- final (fused MoE combine + trend conv + residual) ----------------
__global__ __launch_bounds__(256) void final_kernel(
    const float* __restrict__ tw, const float* __restrict__ tb,
    const float* __restrict__ Tr, const float* __restrict__ XS,
    const int* __restrict__ tinv, const float* __restrict__ Oe,
    float* __restrict__ out)
{
    int n = blockIdx.x, b = blockIdx.y;
    int t = b*Nn + n;
    int i0 = tinv[t*2], i1 = tinv[t*2+1];
    const float* oe0 = Oe + (size_t)i0*Dm;
    const float* oe1 = Oe + (size_t)i1*Dm;
    for (int d = threadIdx.x; d < Dm; d += 256) {
        float acc = tb[d];
        #pragma unroll
        for (int j = 0; j < 5; j++) {
            int p = n + j - 2;
            if (p >= 0 && p < Nn) acc += tw[d*5+j] * Tr[((size_t)(b*Nn+p))*Dm + d];
        }
        size_t idx = (size_t)t*Dm + d;
        out[idx] = XS[idx] + oe0[d] + oe1[d] + acc;
    }
}

__global__ void zero_aux_kernel(float* Aux, int* cnt) {
    if (threadIdx.x < 2*NE) Aux[threadIdx.x] = 0.f;
    if (threadIdx.x < NE) cnt[threadIdx.x] = 0;
}

__global__ void aux_write_kernel(const float* Aux, float* out, int out_size) {
    if (out_size > TT*Dm) {
        float a = 0.f;
        #pragma unroll
        for (int e = 0; e < NE; e++)
            a += (Aux[e]/(float)TT) * (Aux[NE+e]/(float)TT);
        out[TT*Dm] = (float)NE * a;
    }
}

// ---------------- launcher ----------------
extern "C" void kernel_launch(void* const* d_in, const int* in_sizes, int n_in,
                              void* d_out, int out_size)
{
    const float* x    = (const float*)d_in[0];
    const float* qw   = (const float*)d_in[1];
    const float* qb   = (const float*)d_in[2];
    const float* kw   = (const float*)d_in[3];
    const float* kb   = (const float*)d_in[4];
    const float* vw   = (const float*)d_in[5];
    const float* vb   = (const float*)d_in[6];
    const float* ow   = (const float*)d_in[7];
    const float* ob   = (const float*)d_in[8];
    const float* n1g  = (const float*)d_in[9];
    const float* n1b  = (const float*)d_in[10];
    const float* n2g  = (const float*)d_in[11];
    const float* n2b  = (const float*)d_in[12];
    const float* alpha= (const float*)d_in[13];
    const float* dw7  = (const float*)d_in[14];
    const float* dw25 = (const float*)d_in[15];
    const float* dw49 = (const float*)d_in[16];
    const float* rw   = (const float*)d_in[17];
    const float* ew1  = (const float*)d_in[18];
    const float* eb1  = (const float*)d_in[19];
    const float* ew2  = (const float*)d_in[20];
    const float* eb2  = (const float*)d_in[21];
    const float* tw   = (const float*)d_in[22];
    const float* tb   = (const float*)d_in[23];
    float* out = (float*)d_out;

    float *Tr,*S,*XS,*Oe,*Wt,*Ewt,*Aux,*Ck;
    __half *hSn,*hQ,*hK,*hV,*hY,*hH,*hXe,*hQw,*hKw,*hVw,*hOw,*hE1,*hE2;
    int *Eidx,*Cnt,*Tinv;
    cudaGetSymbolAddress((void**)&Tr,  g_Tr);
    cudaGetSymbolAddress((void**)&S,   g_S);
    cudaGetSymbolAddress((void**)&XS,  g_XS);
    cudaGetSymbolAddress((void**)&Oe,  g_Oe);
    cudaGetSymbolAddress((void**)&Wt,  g_W);
    cudaGetSymbolAddress((void**)&Ewt, g_Ewt);
    cudaGetSymbolAddress((void**)&Aux, g_Aux);
    cudaGetSymbolAddress((void**)&Ck,  g_Ck);
    cudaGetSymbolAddress((void**)&hSn, g_hSn);
    cudaGetSymbolAddress((void**)&hQ,  g_hQ);
    cudaGetSymbolAddress((void**)&hK,  g_hK);
    cudaGetSymbolAddress((void**)&hV,  g_hV);
    cudaGetSymbolAddress((void**)&hY,  g_hY);
    cudaGetSymbolAddress((void**)&hH,  g_hH);
    cudaGetSymbolAddress((void**)&hXe, g_hXe);
    cudaGetSymbolAddress((void**)&hQw, g_hQw);
    cudaGetSymbolAddress((void**)&hKw, g_hKw);
    cudaGetSymbolAddress((void**)&hVw, g_hVw);
    cudaGetSymbolAddress((void**)&hOw, g_hOw);
    cudaGetSymbolAddress((void**)&hE1, g_hE1);
    cudaGetSymbolAddress((void**)&hE2, g_hE2);
    cudaGetSymbolAddress((void**)&Eidx,g_Eidx);
    cudaGetSymbolAddress((void**)&Cnt, g_Cnt);
    cudaGetSymbolAddress((void**)&Tinv,g_Tinv);

    cudaFuncSetAttribute(attn2_kernel, cudaFuncAttributeMaxDynamicSharedMemorySize, AT_DSM);

    zero_aux_kernel<<<1, 32>>>(Aux, Cnt);
    const int NW4 = (Dm*Dm)/4, NE14 = (NE*MH*Dm)/4;
    cvt_kernel<<<(NW4+255)/256, 256>>>(qw, hQw, NW4);
    cvt_kernel<<<(NW4+255)/256, 256>>>(kw, hKw, NW4);
    cvt_kernel<<<(NW4+255)/256, 256>>>(vw, hVw, NW4);
    cvt_kernel<<<(NW4+255)/256, 256>>>(ow, hOw, NW4);
    cvt_kernel<<<(NE14+255)/256, 256>>>(ew1, hE1, NE14);
    cvt_kernel<<<(NE14+255)/256, 256>>>(ew2, hE2, NE14);

    ckbuild_kernel<<<Dm, 64>>>(alpha, dw7, dw25, dw49, Ck);
    trend_kernel<<<dim3(61, Bz, Dm/128), 256>>>(x, Ck, Tr, S);
    decomp_edge_kernel<<<dim3(48, Bz), 256>>>(x, alpha, dw7, dw25, dw49, Tr, S);
    ln_kernel<<<TT, 256>>>(S, hSn, n1g, n1b);

    gemm_qkv<<<dim3(Dm/128, TT/128, 3), 256>>>(hSn, hQw, hKw, hVw, qb, kb, vb, hQ, hK, hV);

    attn2_kernel<<<dim3(Nn/64, Bz*Hh), 256, AT_DSM>>>(hQ, hK, hV, hY);

    gemm_res<<<dim3(Dm/128, TT/128), 256>>>(hY, hOw, ob, S, XS);
    ln_kernel<<<TT, 256>>>(XS, hSn, n2g, n2b);
    router_kernel<<<TT, 128>>>(hSn, rw, Wt, Aux);
    assign_kernel<<<TT/256, 256>>>(Wt, Cnt, Eidx, Ewt, Tinv);
    gather_kernel<<<dim3(TT, NE), 256>>>(hSn, Cnt, Eidx, hXe);

    gemm_moe_up<<<dim3(MH/128, TT/128, NE), 256>>>(hXe, hE1, eb1, Cnt, hH);
    gemm_moe_dn<<<dim3(Dm/128, TT/128, NE), 256>>>(hH, hE2, eb2, Cnt, Ewt, Oe);

    final_kernel<<<dim3(Nn, Bz), 256>>>(tw, tb, Tr, XS, Tinv, Oe, out);
    aux_write_kernel<<<1, 1>>>(Aux, out, out_size);
}